// round 1
// baseline (speedup 1.0000x reference)
#include <cuda_runtime.h>
#include <math.h>

#define S_LEN   2048
#define D_MODEL 4096
#define NQH     32
#define NKVH    8
#define HD      128
#define KV_DIM  1024
#define SCALE_F 0.08838834764831845f   // 128^-0.5

// Scratch (allocation-free rule: __device__ globals)
__device__ float g_q[S_LEN * D_MODEL];     // [s, h*128+d] after proj+norm+rope
__device__ float g_k[S_LEN * KV_DIM];
__device__ float g_v[S_LEN * KV_DIM];
__device__ float g_attn[S_LEN * D_MODEL];  // attention output, [s, h*128+d]

// ---------------------------------------------------------------------------
// SGEMM NT: C[M,N] = A[M,K] @ B[N,K]^T   (both row-major, K contiguous)
// 128x128 block tile, BK=16, 256 threads, 8x8 micro-tile per thread.
// ---------------------------------------------------------------------------
__global__ __launch_bounds__(256)
void sgemm_nt(const float* __restrict__ A, const float* __restrict__ B,
              float* __restrict__ C, int M, int N, int K)
{
    __shared__ float As[16][128];
    __shared__ float Bs[16][128];

    const int tid = threadIdx.x;
    const int tx  = tid & 15;        // 0..15 -> N micro
    const int ty  = tid >> 4;        // 0..15 -> M micro
    const int lr  = tid >> 2;        // 0..63 loader row
    const int lc  = (tid & 3) << 2;  // 0,4,8,12 loader col (float4)

    const float* Ab = A + (size_t)blockIdx.y * 128 * K;
    const float* Bb = B + (size_t)blockIdx.x * 128 * K;

    float acc[8][8];
#pragma unroll
    for (int i = 0; i < 8; i++)
#pragma unroll
        for (int j = 0; j < 8; j++) acc[i][j] = 0.0f;

    for (int k0 = 0; k0 < K; k0 += 16) {
        float4 a0 = *(const float4*)(Ab + (size_t)lr * K + k0 + lc);
        float4 a1 = *(const float4*)(Ab + (size_t)(lr + 64) * K + k0 + lc);
        float4 b0 = *(const float4*)(Bb + (size_t)lr * K + k0 + lc);
        float4 b1 = *(const float4*)(Bb + (size_t)(lr + 64) * K + k0 + lc);

        As[lc + 0][lr] = a0.x; As[lc + 1][lr] = a0.y;
        As[lc + 2][lr] = a0.z; As[lc + 3][lr] = a0.w;
        As[lc + 0][lr + 64] = a1.x; As[lc + 1][lr + 64] = a1.y;
        As[lc + 2][lr + 64] = a1.z; As[lc + 3][lr + 64] = a1.w;
        Bs[lc + 0][lr] = b0.x; Bs[lc + 1][lr] = b0.y;
        Bs[lc + 2][lr] = b0.z; Bs[lc + 3][lr] = b0.w;
        Bs[lc + 0][lr + 64] = b1.x; Bs[lc + 1][lr + 64] = b1.y;
        Bs[lc + 2][lr + 64] = b1.z; Bs[lc + 3][lr + 64] = b1.w;

        __syncthreads();

#pragma unroll
        for (int kk = 0; kk < 16; kk++) {
            float ar[8], br[8];
            *(float4*)(ar)     = *(const float4*)&As[kk][ty * 8];
            *(float4*)(ar + 4) = *(const float4*)&As[kk][ty * 8 + 4];
            *(float4*)(br)     = *(const float4*)&Bs[kk][tx * 8];
            *(float4*)(br + 4) = *(const float4*)&Bs[kk][tx * 8 + 4];
#pragma unroll
            for (int i = 0; i < 8; i++)
#pragma unroll
                for (int j = 0; j < 8; j++)
                    acc[i][j] = fmaf(ar[i], br[j], acc[i][j]);
        }
        __syncthreads();
    }

    float* Cb = C + (size_t)(blockIdx.y * 128 + ty * 8) * N + blockIdx.x * 128 + tx * 8;
#pragma unroll
    for (int i = 0; i < 8; i++) {
        *(float4*)(Cb + (size_t)i * N)     = make_float4(acc[i][0], acc[i][1], acc[i][2], acc[i][3]);
        *(float4*)(Cb + (size_t)i * N + 4) = make_float4(acc[i][4], acc[i][5], acc[i][6], acc[i][7]);
    }
}

// ---------------------------------------------------------------------------
// Fused per-head RMSNorm (fp32, eps=1e-6) + RoPE, in place on g_q / g_k.
// One warp per (seq, head) row of 128 elems. Lane handles elems
// {lane, lane+32, lane+64, lane+96}; RoPE pairs (j, j+64).
// ---------------------------------------------------------------------------
__global__ __launch_bounds__(256)
void rmsnorm_rope(const float* __restrict__ cosb, const float* __restrict__ sinb,
                  const float* __restrict__ qw, const float* __restrict__ kw)
{
    const int warp = blockIdx.x * 8 + (threadIdx.x >> 5);
    const int lane = threadIdx.x & 31;

    float* base;
    const float* w;
    int s;
    if (warp < S_LEN * NQH) {
        s = warp / NQH;
        int h = warp - s * NQH;
        base = g_q + (size_t)s * D_MODEL + h * HD;
        w = qw;
    } else {
        int wv = warp - S_LEN * NQH;
        s = wv / NKVH;
        int h = wv - s * NKVH;
        base = g_k + (size_t)s * KV_DIM + h * HD;
        w = kw;
    }

    float x0 = base[lane];
    float x1 = base[lane + 32];
    float x2 = base[lane + 64];
    float x3 = base[lane + 96];

    float ss = x0 * x0 + x1 * x1 + x2 * x2 + x3 * x3;
#pragma unroll
    for (int o = 16; o; o >>= 1) ss += __shfl_xor_sync(0xffffffffu, ss, o);
    float inv = rsqrtf(ss * (1.0f / 128.0f) + 1e-6f);

    float n0 = w[lane]      * x0 * inv;
    float n1 = w[lane + 32] * x1 * inv;
    float n2 = w[lane + 64] * x2 * inv;
    float n3 = w[lane + 96] * x3 * inv;

    const float c0 = cosb[s * 64 + lane];
    const float c1 = cosb[s * 64 + lane + 32];
    const float s0 = sinb[s * 64 + lane];
    const float s1 = sinb[s * 64 + lane + 32];

    base[lane]      = n0 * c0 - n2 * s0;
    base[lane + 32] = n1 * c1 - n3 * s1;
    base[lane + 64] = n2 * c0 + n0 * s0;
    base[lane + 96] = n3 * c1 + n1 * s1;
}

// ---------------------------------------------------------------------------
// Flash attention, fp32, causal, GQA (kv head = h/4).
// Block = (q-tile 64 rows, head). 256 threads: (ty,tx) 16x16.
// S micro-tile 4x4 per thread; O micro-tile 4 rows x 8 dims per thread.
// Padded smem stride 132 to kill K^T column bank conflicts.
// ---------------------------------------------------------------------------
#define LDQ 132

__global__ __launch_bounds__(256)
void flash_attn()
{
    extern __shared__ float sm[];
    float* Qs = sm;                   // 64 x LDQ
    float* Ks = Qs + 64 * LDQ;        // 64 x LDQ
    float* Vs = Ks + 64 * LDQ;        // 64 x LDQ
    float* Ss = Vs + 64 * LDQ;        // 64 x 64

    const int qt  = blockIdx.x;       // query tile (0..31)
    const int h   = blockIdx.y;       // head (0..31)
    const int q0  = qt * 64;
    const int kvh = h >> 2;
    const int tid = threadIdx.x;
    const int tx  = tid & 15;
    const int ty  = tid >> 4;

    // load Q tile
    for (int i = tid; i < 64 * 32; i += 256) {
        int r = i >> 5, c = (i & 31) << 2;
        *(float4*)&Qs[r * LDQ + c] =
            *(const float4*)&g_q[(size_t)(q0 + r) * D_MODEL + h * HD + c];
    }

    float o[4][8];
    float m[4], l[4];
#pragma unroll
    for (int i = 0; i < 4; i++) {
        m[i] = -1e30f; l[i] = 0.0f;
#pragma unroll
        for (int j = 0; j < 8; j++) o[i][j] = 0.0f;
    }

    const int nkt = qt + 1;
    for (int kt = 0; kt < nkt; kt++) {
        const int k0 = kt * 64;
        __syncthreads();  // protect Ks/Vs reuse (also orders Qs on iter 0)
        for (int i = tid; i < 64 * 32; i += 256) {
            int r = i >> 5, c = (i & 31) << 2;
            *(float4*)&Ks[r * LDQ + c] =
                *(const float4*)&g_k[(size_t)(k0 + r) * KV_DIM + kvh * HD + c];
            *(float4*)&Vs[r * LDQ + c] =
                *(const float4*)&g_v[(size_t)(k0 + r) * KV_DIM + kvh * HD + c];
        }
        __syncthreads();

        // S = Q @ K^T
        float s[4][4];
#pragma unroll
        for (int i = 0; i < 4; i++)
#pragma unroll
            for (int j = 0; j < 4; j++) s[i][j] = 0.0f;

        for (int d = 0; d < 128; d += 4) {
            float4 qv[4], kv[4];
#pragma unroll
            for (int i = 0; i < 4; i++) qv[i] = *(const float4*)&Qs[(ty * 4 + i) * LDQ + d];
#pragma unroll
            for (int j = 0; j < 4; j++) kv[j] = *(const float4*)&Ks[(tx * 4 + j) * LDQ + d];
#pragma unroll
            for (int i = 0; i < 4; i++)
#pragma unroll
                for (int j = 0; j < 4; j++) {
                    s[i][j] = fmaf(qv[i].x, kv[j].x, s[i][j]);
                    s[i][j] = fmaf(qv[i].y, kv[j].y, s[i][j]);
                    s[i][j] = fmaf(qv[i].z, kv[j].z, s[i][j]);
                    s[i][j] = fmaf(qv[i].w, kv[j].w, s[i][j]);
                }
        }

        // scale + causal mask (diagonal tile only)
        if (kt == nkt - 1) {
#pragma unroll
            for (int i = 0; i < 4; i++)
#pragma unroll
                for (int j = 0; j < 4; j++)
                    s[i][j] = (tx * 4 + j > ty * 4 + i) ? -1e30f : s[i][j] * SCALE_F;
        } else {
#pragma unroll
            for (int i = 0; i < 4; i++)
#pragma unroll
                for (int j = 0; j < 4; j++) s[i][j] *= SCALE_F;
        }

        // online softmax: row max over 16 lanes sharing ty
        float mn[4];
#pragma unroll
        for (int i = 0; i < 4; i++) {
            float v = fmaxf(fmaxf(s[i][0], s[i][1]), fmaxf(s[i][2], s[i][3]));
#pragma unroll
            for (int off = 8; off; off >>= 1)
                v = fmaxf(v, __shfl_xor_sync(0xffffffffu, v, off));
            mn[i] = fmaxf(v, m[i]);
        }

        float rs[4];
#pragma unroll
        for (int i = 0; i < 4; i++) {
            float alpha = __expf(m[i] - mn[i]);
            m[i] = mn[i];
            l[i] *= alpha;
#pragma unroll
            for (int j = 0; j < 8; j++) o[i][j] *= alpha;
            float r = 0.0f;
#pragma unroll
            for (int j = 0; j < 4; j++) {
                float p = __expf(s[i][j] - m[i]);
                s[i][j] = p;
                r += p;
            }
            rs[i] = r;
        }
#pragma unroll
        for (int i = 0; i < 4; i++) {
#pragma unroll
            for (int off = 8; off; off >>= 1)
                rs[i] += __shfl_xor_sync(0xffffffffu, rs[i], off);
            l[i] += rs[i];
        }

        // store P, then O += P @ V
#pragma unroll
        for (int i = 0; i < 4; i++)
            *(float4*)&Ss[(ty * 4 + i) * 64 + tx * 4] =
                make_float4(s[i][0], s[i][1], s[i][2], s[i][3]);
        __syncthreads();

        for (int c = 0; c < 64; c += 4) {
            float4 pv[4];
#pragma unroll
            for (int i = 0; i < 4; i++) pv[i] = *(const float4*)&Ss[(ty * 4 + i) * 64 + c];
#pragma unroll
            for (int cc = 0; cc < 4; cc++) {
                float4 v0 = *(const float4*)&Vs[(c + cc) * LDQ + tx * 8];
                float4 v1 = *(const float4*)&Vs[(c + cc) * LDQ + tx * 8 + 4];
                float pcol[4] = { (&pv[0].x)[cc], (&pv[1].x)[cc], (&pv[2].x)[cc], (&pv[3].x)[cc] };
#pragma unroll
                for (int i = 0; i < 4; i++) {
                    o[i][0] = fmaf(pcol[i], v0.x, o[i][0]);
                    o[i][1] = fmaf(pcol[i], v0.y, o[i][1]);
                    o[i][2] = fmaf(pcol[i], v0.z, o[i][2]);
                    o[i][3] = fmaf(pcol[i], v0.w, o[i][3]);
                    o[i][4] = fmaf(pcol[i], v1.x, o[i][4]);
                    o[i][5] = fmaf(pcol[i], v1.y, o[i][5]);
                    o[i][6] = fmaf(pcol[i], v1.z, o[i][6]);
                    o[i][7] = fmaf(pcol[i], v1.w, o[i][7]);
                }
            }
        }
    }

    // normalize + write out
#pragma unroll
    for (int i = 0; i < 4; i++) {
        float invl = 1.0f / l[i];
        float* dst = &g_attn[(size_t)(q0 + ty * 4 + i) * D_MODEL + h * HD + tx * 8];
        *(float4*)dst       = make_float4(o[i][0] * invl, o[i][1] * invl, o[i][2] * invl, o[i][3] * invl);
        *(float4*)(dst + 4) = make_float4(o[i][4] * invl, o[i][5] * invl, o[i][6] * invl, o[i][7] * invl);
    }
}

#define FLASH_SMEM ((3 * 64 * LDQ + 64 * 64) * (int)sizeof(float))

// ---------------------------------------------------------------------------
extern "C" void kernel_launch(void* const* d_in, const int* in_sizes, int n_in,
                              void* d_out, int out_size)
{
    const float* hidden = (const float*)d_in[0];
    const float* cosb   = (const float*)d_in[1];
    const float* sinb   = (const float*)d_in[2];
    // d_in[3] attention_mask: exactly causal -> handled analytically
    const float* Wq = (const float*)d_in[4];
    const float* Wk = (const float*)d_in[5];
    const float* Wv = (const float*)d_in[6];
    const float* Wo = (const float*)d_in[7];
    const float* qw = (const float*)d_in[8];
    const float* kw = (const float*)d_in[9];
    float* out = (float*)d_out;

    float *qp, *kp, *vp, *ap;
    cudaGetSymbolAddress((void**)&qp, g_q);
    cudaGetSymbolAddress((void**)&kp, g_k);
    cudaGetSymbolAddress((void**)&vp, g_v);
    cudaGetSymbolAddress((void**)&ap, g_attn);

    cudaFuncSetAttribute(flash_attn, cudaFuncAttributeMaxDynamicSharedMemorySize, FLASH_SMEM);

    // QKV projections
    sgemm_nt<<<dim3(32, 16), 256>>>(hidden, Wq, qp, 2048, 4096, 4096);
    sgemm_nt<<<dim3(8, 16),  256>>>(hidden, Wk, kp, 2048, 1024, 4096);
    sgemm_nt<<<dim3(8, 16),  256>>>(hidden, Wv, vp, 2048, 1024, 4096);

    // RMSNorm + RoPE on q and k (in place): 2048*(32+8) = 81920 warps
    rmsnorm_rope<<<10240, 256>>>(cosb, sinb, qw, kw);

    // causal flash attention
    flash_attn<<<dim3(32, 32), 256, FLASH_SMEM>>>();

    // output projection
    sgemm_nt<<<dim3(32, 16), 256>>>(ap, Wo, out, 2048, 4096, 4096);
}

// round 2
// speedup vs baseline: 1.4846x; 1.4846x over previous
#include <cuda_runtime.h>
#include <math.h>
#include <stdint.h>

#define S_LEN   2048
#define D_MODEL 4096
#define NQH     32
#define NKVH    8
#define HD      128
#define KV_DIM  1024
#define SCALE_F 0.08838834764831845f   // 128^-0.5

// Scratch (allocation-free rule: __device__ globals)
__device__ float g_q[S_LEN * D_MODEL];     // [s, h*128+d] after proj+norm+rope
__device__ float g_k[S_LEN * KV_DIM];
__device__ float g_v[S_LEN * KV_DIM];
__device__ float g_attn[S_LEN * D_MODEL];  // attention output, [s, h*128+d]

// ---------------------------------------------------------------------------
// TF32 tensor-core GEMM NT: C[M,N] = A[M,K] @ B[N,K]^T (row-major, K contig).
// Block 128x128, BK=32, 256 threads (8 warps, 4m x 2n), warp tile 32x64.
// SPLIT=true: 3xTF32 fp32-emulation (hi/lo split) for fp32-grade accuracy.
// SPLIT=false: single-pass tf32.
// ---------------------------------------------------------------------------
#define BK      32
#define LDT     36              // smem k-stride (conflict-free: bank = 4g+t)
#define TSTAGE  (128 * LDT)     // floats per matrix per stage

__device__ __forceinline__ uint32_t f2tf32(float x) {
    uint32_t r;
    asm("cvt.rna.tf32.f32 %0, %1;" : "=r"(r) : "f"(x));
    return r;
}

__device__ __forceinline__ void mma_tf32(float (&d)[4], const uint32_t (&a)[4],
                                         const uint32_t (&b)[2]) {
    asm volatile(
        "mma.sync.aligned.m16n8k8.row.col.f32.tf32.tf32.f32 "
        "{%0,%1,%2,%3}, {%4,%5,%6,%7}, {%8,%9}, {%0,%1,%2,%3};\n"
        : "+f"(d[0]), "+f"(d[1]), "+f"(d[2]), "+f"(d[3])
        : "r"(a[0]), "r"(a[1]), "r"(a[2]), "r"(a[3]), "r"(b[0]), "r"(b[1]));
}

template <bool SPLIT>
__global__ __launch_bounds__(256)
void tgemm_nt(const float* __restrict__ A, const float* __restrict__ B,
              float* __restrict__ C, int M, int N, int K)
{
    extern __shared__ float sm[];
    float* As = sm;                // [2][TSTAGE]
    float* Bs = sm + 2 * TSTAGE;   // [2][TSTAGE]

    const int tid  = threadIdx.x;
    const int warp = tid >> 5;
    const int lane = tid & 31;
    const int g    = lane >> 2;    // 0..7
    const int t    = lane & 3;     // 0..3
    const int wm   = (warp & 3) * 32;
    const int wn   = (warp >> 2) * 64;

    const float* Ab = A + (size_t)blockIdx.y * 128 * K;
    const float* Bb = B + (size_t)blockIdx.x * 128 * K;

    const int lrow = tid >> 3;          // 0..31
    const int lcol = (tid & 7) * 4;     // 0..28

    float4 ra[4], rb[4];
    float acc[2][8][4];
#pragma unroll
    for (int i = 0; i < 2; i++)
#pragma unroll
        for (int j = 0; j < 8; j++)
#pragma unroll
            for (int c = 0; c < 4; c++) acc[i][j][c] = 0.0f;

    const int nk = K / BK;

#define LOADG(KT)                                                              \
    {                                                                          \
        const float* ap_ = Ab + (size_t)lrow * K + (KT) * BK + lcol;           \
        const float* bp_ = Bb + (size_t)lrow * K + (KT) * BK + lcol;           \
        ra[0] = *(const float4*)(ap_);                                         \
        ra[1] = *(const float4*)(ap_ + (size_t)32 * K);                        \
        ra[2] = *(const float4*)(ap_ + (size_t)64 * K);                        \
        ra[3] = *(const float4*)(ap_ + (size_t)96 * K);                        \
        rb[0] = *(const float4*)(bp_);                                         \
        rb[1] = *(const float4*)(bp_ + (size_t)32 * K);                        \
        rb[2] = *(const float4*)(bp_ + (size_t)64 * K);                        \
        rb[3] = *(const float4*)(bp_ + (size_t)96 * K);                        \
    }

#define STS(ST)                                                                \
    {                                                                          \
        float* as_ = As + (ST) * TSTAGE + lrow * LDT + lcol;                   \
        float* bs_ = Bs + (ST) * TSTAGE + lrow * LDT + lcol;                   \
        *(float4*)(as_)            = ra[0];                                    \
        *(float4*)(as_ + 32 * LDT) = ra[1];                                    \
        *(float4*)(as_ + 64 * LDT) = ra[2];                                    \
        *(float4*)(as_ + 96 * LDT) = ra[3];                                    \
        *(float4*)(bs_)            = rb[0];                                    \
        *(float4*)(bs_ + 32 * LDT) = rb[1];                                    \
        *(float4*)(bs_ + 64 * LDT) = rb[2];                                    \
        *(float4*)(bs_ + 96 * LDT) = rb[3];                                    \
    }

    // prologue
    LOADG(0);
    STS(0);
    if (nk > 1) LOADG(1);
    __syncthreads();

    for (int kt = 0; kt < nk; kt++) {
        const float* as = As + (kt & 1) * TSTAGE;
        const float* bs = Bs + (kt & 1) * TSTAGE;

#pragma unroll
        for (int k8 = 0; k8 < BK / 8; k8++) {
            uint32_t ahi[2][4], alo[2][4], bhi[8][2], blo[8][2];
#pragma unroll
            for (int mt = 0; mt < 2; mt++) {
                const float* p = as + (wm + mt * 16 + g) * LDT + k8 * 8 + t;
                float x0 = p[0];
                float x1 = p[8 * LDT];
                float x2 = p[4];
                float x3 = p[8 * LDT + 4];
                ahi[mt][0] = f2tf32(x0);
                ahi[mt][1] = f2tf32(x1);
                ahi[mt][2] = f2tf32(x2);
                ahi[mt][3] = f2tf32(x3);
                if (SPLIT) {
                    alo[mt][0] = f2tf32(x0 - __uint_as_float(ahi[mt][0]));
                    alo[mt][1] = f2tf32(x1 - __uint_as_float(ahi[mt][1]));
                    alo[mt][2] = f2tf32(x2 - __uint_as_float(ahi[mt][2]));
                    alo[mt][3] = f2tf32(x3 - __uint_as_float(ahi[mt][3]));
                }
            }
#pragma unroll
            for (int nt = 0; nt < 8; nt++) {
                const float* p = bs + (wn + nt * 8 + g) * LDT + k8 * 8 + t;
                float y0 = p[0];
                float y1 = p[4];
                bhi[nt][0] = f2tf32(y0);
                bhi[nt][1] = f2tf32(y1);
                if (SPLIT) {
                    blo[nt][0] = f2tf32(y0 - __uint_as_float(bhi[nt][0]));
                    blo[nt][1] = f2tf32(y1 - __uint_as_float(bhi[nt][1]));
                }
            }
#pragma unroll
            for (int mt = 0; mt < 2; mt++)
#pragma unroll
                for (int nt = 0; nt < 8; nt++) {
                    if (SPLIT) {
                        mma_tf32(acc[mt][nt], ahi[mt], blo[nt]);
                        mma_tf32(acc[mt][nt], alo[mt], bhi[nt]);
                    }
                    mma_tf32(acc[mt][nt], ahi[mt], bhi[nt]);
                }
        }

        if (kt + 1 < nk) {
            STS((kt + 1) & 1);
            __syncthreads();
            if (kt + 2 < nk) LOADG(kt + 2);
        }
    }

    // epilogue: fragment c layout (g, 2t), (g, 2t+1), (g+8, 2t), (g+8, 2t+1)
#pragma unroll
    for (int mt = 0; mt < 2; mt++) {
        int r0 = blockIdx.y * 128 + wm + mt * 16 + g;
#pragma unroll
        for (int nt = 0; nt < 8; nt++) {
            int c0 = blockIdx.x * 128 + wn + nt * 8 + 2 * t;
            *(float2*)&C[(size_t)r0 * N + c0] =
                make_float2(acc[mt][nt][0], acc[mt][nt][1]);
            *(float2*)&C[(size_t)(r0 + 8) * N + c0] =
                make_float2(acc[mt][nt][2], acc[mt][nt][3]);
        }
    }
#undef LOADG
#undef STS
}

#define TGEMM_SMEM (4 * TSTAGE * (int)sizeof(float))

// ---------------------------------------------------------------------------
// Fused per-head RMSNorm (fp32, eps=1e-6) + RoPE, in place on g_q / g_k.
// ---------------------------------------------------------------------------
__global__ __launch_bounds__(256)
void rmsnorm_rope(const float* __restrict__ cosb, const float* __restrict__ sinb,
                  const float* __restrict__ qw, const float* __restrict__ kw)
{
    const int warp = blockIdx.x * 8 + (threadIdx.x >> 5);
    const int lane = threadIdx.x & 31;

    float* base;
    const float* w;
    int s;
    if (warp < S_LEN * NQH) {
        s = warp / NQH;
        int h = warp - s * NQH;
        base = g_q + (size_t)s * D_MODEL + h * HD;
        w = qw;
    } else {
        int wv = warp - S_LEN * NQH;
        s = wv / NKVH;
        int h = wv - s * NKVH;
        base = g_k + (size_t)s * KV_DIM + h * HD;
        w = kw;
    }

    float x0 = base[lane];
    float x1 = base[lane + 32];
    float x2 = base[lane + 64];
    float x3 = base[lane + 96];

    float ss = x0 * x0 + x1 * x1 + x2 * x2 + x3 * x3;
#pragma unroll
    for (int o = 16; o; o >>= 1) ss += __shfl_xor_sync(0xffffffffu, ss, o);
    float inv = rsqrtf(ss * (1.0f / 128.0f) + 1e-6f);

    float n0 = w[lane]      * x0 * inv;
    float n1 = w[lane + 32] * x1 * inv;
    float n2 = w[lane + 64] * x2 * inv;
    float n3 = w[lane + 96] * x3 * inv;

    const float c0 = cosb[s * 64 + lane];
    const float c1 = cosb[s * 64 + lane + 32];
    const float s0 = sinb[s * 64 + lane];
    const float s1 = sinb[s * 64 + lane + 32];

    base[lane]      = n0 * c0 - n2 * s0;
    base[lane + 32] = n1 * c1 - n3 * s1;
    base[lane + 64] = n2 * c0 + n0 * s0;
    base[lane + 96] = n3 * c1 + n1 * s1;
}

// ---------------------------------------------------------------------------
// Flash attention, fp32, causal, GQA (kv head = h/4). (unchanged from R1)
// ---------------------------------------------------------------------------
#define LDQ 132

__global__ __launch_bounds__(256)
void flash_attn()
{
    extern __shared__ float smf[];
    float* Qs = smf;
    float* Ks = Qs + 64 * LDQ;
    float* Vs = Ks + 64 * LDQ;
    float* Ss = Vs + 64 * LDQ;

    const int qt  = blockIdx.x;
    const int h   = blockIdx.y;
    const int q0  = qt * 64;
    const int kvh = h >> 2;
    const int tid = threadIdx.x;
    const int tx  = tid & 15;
    const int ty  = tid >> 4;

    for (int i = tid; i < 64 * 32; i += 256) {
        int r = i >> 5, c = (i & 31) << 2;
        *(float4*)&Qs[r * LDQ + c] =
            *(const float4*)&g_q[(size_t)(q0 + r) * D_MODEL + h * HD + c];
    }

    float o[4][8];
    float m[4], l[4];
#pragma unroll
    for (int i = 0; i < 4; i++) {
        m[i] = -1e30f; l[i] = 0.0f;
#pragma unroll
        for (int j = 0; j < 8; j++) o[i][j] = 0.0f;
    }

    const int nkt = qt + 1;
    for (int kt = 0; kt < nkt; kt++) {
        const int k0 = kt * 64;
        __syncthreads();
        for (int i = tid; i < 64 * 32; i += 256) {
            int r = i >> 5, c = (i & 31) << 2;
            *(float4*)&Ks[r * LDQ + c] =
                *(const float4*)&g_k[(size_t)(k0 + r) * KV_DIM + kvh * HD + c];
            *(float4*)&Vs[r * LDQ + c] =
                *(const float4*)&g_v[(size_t)(k0 + r) * KV_DIM + kvh * HD + c];
        }
        __syncthreads();

        float s[4][4];
#pragma unroll
        for (int i = 0; i < 4; i++)
#pragma unroll
            for (int j = 0; j < 4; j++) s[i][j] = 0.0f;

        for (int d = 0; d < 128; d += 4) {
            float4 qv[4], kv[4];
#pragma unroll
            for (int i = 0; i < 4; i++) qv[i] = *(const float4*)&Qs[(ty * 4 + i) * LDQ + d];
#pragma unroll
            for (int j = 0; j < 4; j++) kv[j] = *(const float4*)&Ks[(tx * 4 + j) * LDQ + d];
#pragma unroll
            for (int i = 0; i < 4; i++)
#pragma unroll
                for (int j = 0; j < 4; j++) {
                    s[i][j] = fmaf(qv[i].x, kv[j].x, s[i][j]);
                    s[i][j] = fmaf(qv[i].y, kv[j].y, s[i][j]);
                    s[i][j] = fmaf(qv[i].z, kv[j].z, s[i][j]);
                    s[i][j] = fmaf(qv[i].w, kv[j].w, s[i][j]);
                }
        }

        if (kt == nkt - 1) {
#pragma unroll
            for (int i = 0; i < 4; i++)
#pragma unroll
                for (int j = 0; j < 4; j++)
                    s[i][j] = (tx * 4 + j > ty * 4 + i) ? -1e30f : s[i][j] * SCALE_F;
        } else {
#pragma unroll
            for (int i = 0; i < 4; i++)
#pragma unroll
                for (int j = 0; j < 4; j++) s[i][j] *= SCALE_F;
        }

        float mn[4];
#pragma unroll
        for (int i = 0; i < 4; i++) {
            float v = fmaxf(fmaxf(s[i][0], s[i][1]), fmaxf(s[i][2], s[i][3]));
#pragma unroll
            for (int off = 8; off; off >>= 1)
                v = fmaxf(v, __shfl_xor_sync(0xffffffffu, v, off));
            mn[i] = fmaxf(v, m[i]);
        }

        float rs[4];
#pragma unroll
        for (int i = 0; i < 4; i++) {
            float alpha = __expf(m[i] - mn[i]);
            m[i] = mn[i];
            l[i] *= alpha;
#pragma unroll
            for (int j = 0; j < 8; j++) o[i][j] *= alpha;
            float r = 0.0f;
#pragma unroll
            for (int j = 0; j < 4; j++) {
                float p = __expf(s[i][j] - m[i]);
                s[i][j] = p;
                r += p;
            }
            rs[i] = r;
        }
#pragma unroll
        for (int i = 0; i < 4; i++) {
#pragma unroll
            for (int off = 8; off; off >>= 1)
                rs[i] += __shfl_xor_sync(0xffffffffu, rs[i], off);
            l[i] += rs[i];
        }

#pragma unroll
        for (int i = 0; i < 4; i++)
            *(float4*)&Ss[(ty * 4 + i) * 64 + tx * 4] =
                make_float4(s[i][0], s[i][1], s[i][2], s[i][3]);
        __syncthreads();

        for (int c = 0; c < 64; c += 4) {
            float4 pv[4];
#pragma unroll
            for (int i = 0; i < 4; i++) pv[i] = *(const float4*)&Ss[(ty * 4 + i) * 64 + c];
#pragma unroll
            for (int cc = 0; cc < 4; cc++) {
                float4 v0 = *(const float4*)&Vs[(c + cc) * LDQ + tx * 8];
                float4 v1 = *(const float4*)&Vs[(c + cc) * LDQ + tx * 8 + 4];
                float pcol[4] = { (&pv[0].x)[cc], (&pv[1].x)[cc], (&pv[2].x)[cc], (&pv[3].x)[cc] };
#pragma unroll
                for (int i = 0; i < 4; i++) {
                    o[i][0] = fmaf(pcol[i], v0.x, o[i][0]);
                    o[i][1] = fmaf(pcol[i], v0.y, o[i][1]);
                    o[i][2] = fmaf(pcol[i], v0.z, o[i][2]);
                    o[i][3] = fmaf(pcol[i], v0.w, o[i][3]);
                    o[i][4] = fmaf(pcol[i], v1.x, o[i][4]);
                    o[i][5] = fmaf(pcol[i], v1.y, o[i][5]);
                    o[i][6] = fmaf(pcol[i], v1.z, o[i][6]);
                    o[i][7] = fmaf(pcol[i], v1.w, o[i][7]);
                }
            }
        }
    }

#pragma unroll
    for (int i = 0; i < 4; i++) {
        float invl = 1.0f / l[i];
        float* dst = &g_attn[(size_t)(q0 + ty * 4 + i) * D_MODEL + h * HD + tx * 8];
        *(float4*)dst       = make_float4(o[i][0] * invl, o[i][1] * invl, o[i][2] * invl, o[i][3] * invl);
        *(float4*)(dst + 4) = make_float4(o[i][4] * invl, o[i][5] * invl, o[i][6] * invl, o[i][7] * invl);
    }
}

#define FLASH_SMEM ((3 * 64 * LDQ + 64 * 64) * (int)sizeof(float))

// ---------------------------------------------------------------------------
extern "C" void kernel_launch(void* const* d_in, const int* in_sizes, int n_in,
                              void* d_out, int out_size)
{
    const float* hidden = (const float*)d_in[0];
    const float* cosb   = (const float*)d_in[1];
    const float* sinb   = (const float*)d_in[2];
    // d_in[3] attention_mask: exactly causal -> handled analytically
    const float* Wq = (const float*)d_in[4];
    const float* Wk = (const float*)d_in[5];
    const float* Wv = (const float*)d_in[6];
    const float* Wo = (const float*)d_in[7];
    const float* qw = (const float*)d_in[8];
    const float* kw = (const float*)d_in[9];
    float* out = (float*)d_out;

    float *qp, *kp, *vp, *ap;
    cudaGetSymbolAddress((void**)&qp, g_q);
    cudaGetSymbolAddress((void**)&kp, g_k);
    cudaGetSymbolAddress((void**)&vp, g_v);
    cudaGetSymbolAddress((void**)&ap, g_attn);

    cudaFuncSetAttribute(tgemm_nt<true>,  cudaFuncAttributeMaxDynamicSharedMemorySize, TGEMM_SMEM);
    cudaFuncSetAttribute(tgemm_nt<false>, cudaFuncAttributeMaxDynamicSharedMemorySize, TGEMM_SMEM);
    cudaFuncSetAttribute(flash_attn, cudaFuncAttributeMaxDynamicSharedMemorySize, FLASH_SMEM);

    // QKV projections (3xTF32 split: fp32-grade accuracy)
    tgemm_nt<true><<<dim3(32, 16), 256, TGEMM_SMEM>>>(hidden, Wq, qp, 2048, 4096, 4096);
    tgemm_nt<true><<<dim3(8, 16),  256, TGEMM_SMEM>>>(hidden, Wk, kp, 2048, 1024, 4096);
    tgemm_nt<true><<<dim3(8, 16),  256, TGEMM_SMEM>>>(hidden, Wv, vp, 2048, 1024, 4096);

    // RMSNorm + RoPE on q and k (in place)
    rmsnorm_rope<<<10240, 256>>>(cosb, sinb, qw, kw);

    // causal flash attention (fp32)
    flash_attn<<<dim3(32, 32), 256, FLASH_SMEM>>>();

    // output projection (single-pass TF32: linear error path, ~2.5e-4)
    tgemm_nt<false><<<dim3(32, 16), 256, TGEMM_SMEM>>>(ap, Wo, out, 2048, 4096, 4096);
}

// round 3
// speedup vs baseline: 2.2306x; 1.5025x over previous
#include <cuda_runtime.h>
#include <cuda_bf16.h>
#include <math.h>
#include <stdint.h>

#define S_LEN   2048
#define D_MODEL 4096
#define NQH     32
#define NKVH    8
#define HD      128
#define KV_DIM  1024
#define SCALE_F 0.08838834764831845f   // 128^-0.5

__device__ float g_q[S_LEN * D_MODEL];
__device__ float g_k[S_LEN * KV_DIM];
__device__ float g_v[S_LEN * KV_DIM];
__device__ float g_attn[S_LEN * D_MODEL];

// ---------------------------------------------------------------------------
// TF32 tensor-core GEMM NT (unchanged from R2)
// ---------------------------------------------------------------------------
#define BK      32
#define LDT     36
#define TSTAGE  (128 * LDT)

__device__ __forceinline__ uint32_t f2tf32(float x) {
    uint32_t r;
    asm("cvt.rna.tf32.f32 %0, %1;" : "=r"(r) : "f"(x));
    return r;
}

__device__ __forceinline__ void mma_tf32(float (&d)[4], const uint32_t (&a)[4],
                                         const uint32_t (&b)[2]) {
    asm volatile(
        "mma.sync.aligned.m16n8k8.row.col.f32.tf32.tf32.f32 "
        "{%0,%1,%2,%3}, {%4,%5,%6,%7}, {%8,%9}, {%0,%1,%2,%3};\n"
        : "+f"(d[0]), "+f"(d[1]), "+f"(d[2]), "+f"(d[3])
        : "r"(a[0]), "r"(a[1]), "r"(a[2]), "r"(a[3]), "r"(b[0]), "r"(b[1]));
}

template <bool SPLIT>
__global__ __launch_bounds__(256)
void tgemm_nt(const float* __restrict__ A, const float* __restrict__ B,
              float* __restrict__ C, int M, int N, int K)
{
    extern __shared__ float sm[];
    float* As = sm;
    float* Bs = sm + 2 * TSTAGE;

    const int tid  = threadIdx.x;
    const int warp = tid >> 5;
    const int lane = tid & 31;
    const int g    = lane >> 2;
    const int t    = lane & 3;
    const int wm   = (warp & 3) * 32;
    const int wn   = (warp >> 2) * 64;

    const float* Ab = A + (size_t)blockIdx.y * 128 * K;
    const float* Bb = B + (size_t)blockIdx.x * 128 * K;

    const int lrow = tid >> 3;
    const int lcol = (tid & 7) * 4;

    float4 ra[4], rb[4];
    float acc[2][8][4];
#pragma unroll
    for (int i = 0; i < 2; i++)
#pragma unroll
        for (int j = 0; j < 8; j++)
#pragma unroll
            for (int c = 0; c < 4; c++) acc[i][j][c] = 0.0f;

    const int nk = K / BK;

#define LOADG(KT)                                                              \
    {                                                                          \
        const float* ap_ = Ab + (size_t)lrow * K + (KT) * BK + lcol;           \
        const float* bp_ = Bb + (size_t)lrow * K + (KT) * BK + lcol;           \
        ra[0] = *(const float4*)(ap_);                                         \
        ra[1] = *(const float4*)(ap_ + (size_t)32 * K);                        \
        ra[2] = *(const float4*)(ap_ + (size_t)64 * K);                        \
        ra[3] = *(const float4*)(ap_ + (size_t)96 * K);                        \
        rb[0] = *(const float4*)(bp_);                                         \
        rb[1] = *(const float4*)(bp_ + (size_t)32 * K);                        \
        rb[2] = *(const float4*)(bp_ + (size_t)64 * K);                        \
        rb[3] = *(const float4*)(bp_ + (size_t)96 * K);                        \
    }

#define STS(ST)                                                                \
    {                                                                          \
        float* as_ = As + (ST) * TSTAGE + lrow * LDT + lcol;                   \
        float* bs_ = Bs + (ST) * TSTAGE + lrow * LDT + lcol;                   \
        *(float4*)(as_)            = ra[0];                                    \
        *(float4*)(as_ + 32 * LDT) = ra[1];                                    \
        *(float4*)(as_ + 64 * LDT) = ra[2];                                    \
        *(float4*)(as_ + 96 * LDT) = ra[3];                                    \
        *(float4*)(bs_)            = rb[0];                                    \
        *(float4*)(bs_ + 32 * LDT) = rb[1];                                    \
        *(float4*)(bs_ + 64 * LDT) = rb[2];                                    \
        *(float4*)(bs_ + 96 * LDT) = rb[3];                                    \
    }

    LOADG(0);
    STS(0);
    if (nk > 1) LOADG(1);
    __syncthreads();

    for (int kt = 0; kt < nk; kt++) {
        const float* as = As + (kt & 1) * TSTAGE;
        const float* bs = Bs + (kt & 1) * TSTAGE;

#pragma unroll
        for (int k8 = 0; k8 < BK / 8; k8++) {
            uint32_t ahi[2][4], alo[2][4], bhi[8][2], blo[8][2];
#pragma unroll
            for (int mt = 0; mt < 2; mt++) {
                const float* p = as + (wm + mt * 16 + g) * LDT + k8 * 8 + t;
                float x0 = p[0];
                float x1 = p[8 * LDT];
                float x2 = p[4];
                float x3 = p[8 * LDT + 4];
                ahi[mt][0] = f2tf32(x0);
                ahi[mt][1] = f2tf32(x1);
                ahi[mt][2] = f2tf32(x2);
                ahi[mt][3] = f2tf32(x3);
                if (SPLIT) {
                    alo[mt][0] = f2tf32(x0 - __uint_as_float(ahi[mt][0]));
                    alo[mt][1] = f2tf32(x1 - __uint_as_float(ahi[mt][1]));
                    alo[mt][2] = f2tf32(x2 - __uint_as_float(ahi[mt][2]));
                    alo[mt][3] = f2tf32(x3 - __uint_as_float(ahi[mt][3]));
                }
            }
#pragma unroll
            for (int nt = 0; nt < 8; nt++) {
                const float* p = bs + (wn + nt * 8 + g) * LDT + k8 * 8 + t;
                float y0 = p[0];
                float y1 = p[4];
                bhi[nt][0] = f2tf32(y0);
                bhi[nt][1] = f2tf32(y1);
                if (SPLIT) {
                    blo[nt][0] = f2tf32(y0 - __uint_as_float(bhi[nt][0]));
                    blo[nt][1] = f2tf32(y1 - __uint_as_float(bhi[nt][1]));
                }
            }
#pragma unroll
            for (int mt = 0; mt < 2; mt++)
#pragma unroll
                for (int nt = 0; nt < 8; nt++) {
                    if (SPLIT) {
                        mma_tf32(acc[mt][nt], ahi[mt], blo[nt]);
                        mma_tf32(acc[mt][nt], alo[mt], bhi[nt]);
                    }
                    mma_tf32(acc[mt][nt], ahi[mt], bhi[nt]);
                }
        }

        if (kt + 1 < nk) {
            STS((kt + 1) & 1);
            __syncthreads();
            if (kt + 2 < nk) LOADG(kt + 2);
        }
    }

#pragma unroll
    for (int mt = 0; mt < 2; mt++) {
        int r0 = blockIdx.y * 128 + wm + mt * 16 + g;
#pragma unroll
        for (int nt = 0; nt < 8; nt++) {
            int c0 = blockIdx.x * 128 + wn + nt * 8 + 2 * t;
            *(float2*)&C[(size_t)r0 * N + c0] =
                make_float2(acc[mt][nt][0], acc[mt][nt][1]);
            *(float2*)&C[(size_t)(r0 + 8) * N + c0] =
                make_float2(acc[mt][nt][2], acc[mt][nt][3]);
        }
    }
#undef LOADG
#undef STS
}

#define TGEMM_SMEM (4 * TSTAGE * (int)sizeof(float))

// ---------------------------------------------------------------------------
// Fused per-head RMSNorm + RoPE (unchanged)
// ---------------------------------------------------------------------------
__global__ __launch_bounds__(256)
void rmsnorm_rope(const float* __restrict__ cosb, const float* __restrict__ sinb,
                  const float* __restrict__ qw, const float* __restrict__ kw)
{
    const int warp = blockIdx.x * 8 + (threadIdx.x >> 5);
    const int lane = threadIdx.x & 31;

    float* base;
    const float* w;
    int s;
    if (warp < S_LEN * NQH) {
        s = warp / NQH;
        int h = warp - s * NQH;
        base = g_q + (size_t)s * D_MODEL + h * HD;
        w = qw;
    } else {
        int wv = warp - S_LEN * NQH;
        s = wv / NKVH;
        int h = wv - s * NKVH;
        base = g_k + (size_t)s * KV_DIM + h * HD;
        w = kw;
    }

    float x0 = base[lane];
    float x1 = base[lane + 32];
    float x2 = base[lane + 64];
    float x3 = base[lane + 96];

    float ss = x0 * x0 + x1 * x1 + x2 * x2 + x3 * x3;
#pragma unroll
    for (int o = 16; o; o >>= 1) ss += __shfl_xor_sync(0xffffffffu, ss, o);
    float inv = rsqrtf(ss * (1.0f / 128.0f) + 1e-6f);

    float n0 = w[lane]      * x0 * inv;
    float n1 = w[lane + 32] * x1 * inv;
    float n2 = w[lane + 64] * x2 * inv;
    float n3 = w[lane + 96] * x3 * inv;

    const float c0 = cosb[s * 64 + lane];
    const float c1 = cosb[s * 64 + lane + 32];
    const float s0 = sinb[s * 64 + lane];
    const float s1 = sinb[s * 64 + lane + 32];

    base[lane]      = n0 * c0 - n2 * s0;
    base[lane + 32] = n1 * c1 - n3 * s1;
    base[lane + 64] = n2 * c0 + n0 * s0;
    base[lane + 96] = n3 * c1 + n1 * s1;
}

// ---------------------------------------------------------------------------
// Tensor-core flash attention: bf16 hi/lo 3-term split, causal, GQA.
// Block = (128 q-rows, head), 8 warps of 16 q-rows. KV tile 64.
// Q/K planes stride 136 bf16; Vt/P staging stride 72 (all lane-bank 4g+t).
// ---------------------------------------------------------------------------
#define OFF_QHI  0
#define OFF_QLO  17408
#define OFF_KHI  34816
#define OFF_KLO  43520
#define OFF_VTH  52224
#define OFF_VTL  61440
#define OFF_PSH  70656
#define OFF_PSL  79872
#define FLASH_SMEM_TC (89088 * 2)

__device__ __forceinline__ void mma_bf16(float (&d)[4],
    uint32_t a0, uint32_t a1, uint32_t a2, uint32_t a3,
    uint32_t b0, uint32_t b1) {
    asm volatile(
        "mma.sync.aligned.m16n8k16.row.col.f32.bf16.bf16.f32 "
        "{%0,%1,%2,%3}, {%4,%5,%6,%7}, {%8,%9}, {%0,%1,%2,%3};\n"
        : "+f"(d[0]), "+f"(d[1]), "+f"(d[2]), "+f"(d[3])
        : "r"(a0), "r"(a1), "r"(a2), "r"(a3), "r"(b0), "r"(b1));
}

__device__ __forceinline__ void split2(float x0, float x1,
                                       __nv_bfloat162& hi, __nv_bfloat162& lo) {
    hi = __floats2bfloat162_rn(x0, x1);
    float2 hf = __bfloat1622float2(hi);
    lo = __floats2bfloat162_rn(x0 - hf.x, x1 - hf.y);
}

__global__ __launch_bounds__(256, 1)
void flash_attn_tc()
{
    extern __shared__ __nv_bfloat16 smb[];
    __nv_bfloat16* Qhi = smb + OFF_QHI;
    __nv_bfloat16* Qlo = smb + OFF_QLO;
    __nv_bfloat16* Khi = smb + OFF_KHI;
    __nv_bfloat16* Klo = smb + OFF_KLO;
    __nv_bfloat16* Vth = smb + OFF_VTH;
    __nv_bfloat16* Vtl = smb + OFF_VTL;
    __nv_bfloat16* Psh = smb + OFF_PSH;
    __nv_bfloat16* Psl = smb + OFF_PSL;

    const int qt  = 15 - blockIdx.x;   // heavy tiles first
    const int h   = blockIdx.y;
    const int q0  = qt * 128;
    const int kvh = h >> 2;
    const int tid  = threadIdx.x;
    const int warp = tid >> 5;
    const int lane = tid & 31;
    const int g = lane >> 2;
    const int t = lane & 3;

    // Q tile load + bf16 split
    for (int i = tid; i < 128 * 32; i += 256) {
        int r = i >> 5, c = (i & 31) << 2;
        float4 v = *(const float4*)&g_q[(size_t)(q0 + r) * D_MODEL + h * HD + c];
        __nv_bfloat162 h01, l01, h23, l23;
        split2(v.x, v.y, h01, l01);
        split2(v.z, v.w, h23, l23);
        *(__nv_bfloat162*)(Qhi + r * 136 + c)     = h01;
        *(__nv_bfloat162*)(Qhi + r * 136 + c + 2) = h23;
        *(__nv_bfloat162*)(Qlo + r * 136 + c)     = l01;
        *(__nv_bfloat162*)(Qlo + r * 136 + c + 2) = l23;
    }

    float o[16][4];
#pragma unroll
    for (int nt = 0; nt < 16; nt++)
#pragma unroll
        for (int j = 0; j < 4; j++) o[nt][j] = 0.0f;
    float m0 = -1e30f, m1 = -1e30f, l0 = 0.0f, l1 = 0.0f;

    const int wrow = q0 + warp * 16;
    const int nkt  = 2 * qt + 2;

    for (int kt = 0; kt < nkt; kt++) {
        const int k0 = kt * 64;
        __syncthreads();
        // K tile: coalesced rows, split into Khi/Klo
        for (int i = tid; i < 64 * 32; i += 256) {
            int r = i >> 5, c = (i & 31) << 2;
            float4 v = *(const float4*)&g_k[(size_t)(k0 + r) * KV_DIM + kvh * HD + c];
            __nv_bfloat162 h01, l01, h23, l23;
            split2(v.x, v.y, h01, l01);
            split2(v.z, v.w, h23, l23);
            *(__nv_bfloat162*)(Khi + r * 136 + c)     = h01;
            *(__nv_bfloat162*)(Khi + r * 136 + c + 2) = h23;
            *(__nv_bfloat162*)(Klo + r * 136 + c)     = l01;
            *(__nv_bfloat162*)(Klo + r * 136 + c + 2) = l23;
        }
        // V tile: transpose into Vt (hd-major), split
        for (int i = tid; i < 64 * 32; i += 256) {
            int r = i & 63, c = (i >> 6) << 2;
            float4 v = *(const float4*)&g_v[(size_t)(k0 + r) * KV_DIM + kvh * HD + c];
            float x[4] = {v.x, v.y, v.z, v.w};
#pragma unroll
            for (int j = 0; j < 4; j++) {
                __nv_bfloat16 hb = __float2bfloat16(x[j]);
                Vth[(c + j) * 72 + r] = hb;
                Vtl[(c + j) * 72 + r] = __float2bfloat16(x[j] - __bfloat162float(hb));
            }
        }
        __syncthreads();

        if (k0 > wrow + 15) continue;   // tile entirely above diagonal for this warp

        // ---- S = Q K^T (3-term bf16 split) ----
        float s[8][4];
#pragma unroll
        for (int nt = 0; nt < 8; nt++)
#pragma unroll
            for (int j = 0; j < 4; j++) s[nt][j] = 0.0f;

        const __nv_bfloat16* qrh = Qhi + (warp * 16 + g) * 136 + 2 * t;
        const __nv_bfloat16* qrl = Qlo + (warp * 16 + g) * 136 + 2 * t;
#pragma unroll
        for (int c = 0; c < 8; c++) {
            uint32_t ah0 = *(const uint32_t*)(qrh + c * 16);
            uint32_t ah1 = *(const uint32_t*)(qrh + 8 * 136 + c * 16);
            uint32_t ah2 = *(const uint32_t*)(qrh + c * 16 + 8);
            uint32_t ah3 = *(const uint32_t*)(qrh + 8 * 136 + c * 16 + 8);
            uint32_t al0 = *(const uint32_t*)(qrl + c * 16);
            uint32_t al1 = *(const uint32_t*)(qrl + 8 * 136 + c * 16);
            uint32_t al2 = *(const uint32_t*)(qrl + c * 16 + 8);
            uint32_t al3 = *(const uint32_t*)(qrl + 8 * 136 + c * 16 + 8);
#pragma unroll
            for (int nt = 0; nt < 8; nt++) {
                const __nv_bfloat16* kp  = Khi + (nt * 8 + g) * 136 + c * 16 + 2 * t;
                const __nv_bfloat16* kpl = Klo + (nt * 8 + g) * 136 + c * 16 + 2 * t;
                uint32_t bh0 = *(const uint32_t*)(kp);
                uint32_t bh1 = *(const uint32_t*)(kp + 8);
                uint32_t bl0 = *(const uint32_t*)(kpl);
                uint32_t bl1 = *(const uint32_t*)(kpl + 8);
                mma_bf16(s[nt], ah0, ah1, ah2, ah3, bh0, bh1);
                mma_bf16(s[nt], ah0, ah1, ah2, ah3, bl0, bl1);
                mma_bf16(s[nt], al0, al1, al2, al3, bh0, bh1);
            }
        }

        // ---- scale + causal mask ----
        if (k0 + 63 > wrow) {
            int r0 = wrow + g, r1 = r0 + 8;
#pragma unroll
            for (int nt = 0; nt < 8; nt++) {
                int c0 = k0 + nt * 8 + 2 * t;
                s[nt][0] = (c0     > r0) ? -1e30f : s[nt][0] * SCALE_F;
                s[nt][1] = (c0 + 1 > r0) ? -1e30f : s[nt][1] * SCALE_F;
                s[nt][2] = (c0     > r1) ? -1e30f : s[nt][2] * SCALE_F;
                s[nt][3] = (c0 + 1 > r1) ? -1e30f : s[nt][3] * SCALE_F;
            }
        } else {
#pragma unroll
            for (int nt = 0; nt < 8; nt++)
#pragma unroll
                for (int j = 0; j < 4; j++) s[nt][j] *= SCALE_F;
        }

        // ---- online softmax (rows g and g+8; quad reduce over t) ----
        float mx0 = -1e30f, mx1 = -1e30f;
#pragma unroll
        for (int nt = 0; nt < 8; nt++) {
            mx0 = fmaxf(mx0, fmaxf(s[nt][0], s[nt][1]));
            mx1 = fmaxf(mx1, fmaxf(s[nt][2], s[nt][3]));
        }
        mx0 = fmaxf(mx0, __shfl_xor_sync(0xffffffffu, mx0, 1));
        mx0 = fmaxf(mx0, __shfl_xor_sync(0xffffffffu, mx0, 2));
        mx1 = fmaxf(mx1, __shfl_xor_sync(0xffffffffu, mx1, 1));
        mx1 = fmaxf(mx1, __shfl_xor_sync(0xffffffffu, mx1, 2));

        float mn0 = fmaxf(m0, mx0), mn1 = fmaxf(m1, mx1);
        float a0 = __expf(m0 - mn0), a1 = __expf(m1 - mn1);
        m0 = mn0; m1 = mn1;

        float sum0 = 0.0f, sum1 = 0.0f;
#pragma unroll
        for (int nt = 0; nt < 8; nt++) {
            s[nt][0] = __expf(s[nt][0] - m0);
            s[nt][1] = __expf(s[nt][1] - m0);
            s[nt][2] = __expf(s[nt][2] - m1);
            s[nt][3] = __expf(s[nt][3] - m1);
            sum0 += s[nt][0] + s[nt][1];
            sum1 += s[nt][2] + s[nt][3];
        }
        sum0 += __shfl_xor_sync(0xffffffffu, sum0, 1);
        sum0 += __shfl_xor_sync(0xffffffffu, sum0, 2);
        sum1 += __shfl_xor_sync(0xffffffffu, sum1, 1);
        sum1 += __shfl_xor_sync(0xffffffffu, sum1, 2);
        l0 = l0 * a0 + sum0;
        l1 = l1 * a1 + sum1;

#pragma unroll
        for (int nt = 0; nt < 16; nt++) {
            o[nt][0] *= a0; o[nt][1] *= a0;
            o[nt][2] *= a1; o[nt][3] *= a1;
        }

        // ---- stage P (hi/lo) to per-warp smem ----
        __nv_bfloat16* ph = Psh + (warp * 16 + g) * 72 + 2 * t;
        __nv_bfloat16* pl = Psl + (warp * 16 + g) * 72 + 2 * t;
#pragma unroll
        for (int nt = 0; nt < 8; nt++) {
            __nv_bfloat162 hp, lp;
            split2(s[nt][0], s[nt][1], hp, lp);
            *(__nv_bfloat162*)(ph + nt * 8) = hp;
            *(__nv_bfloat162*)(pl + nt * 8) = lp;
            split2(s[nt][2], s[nt][3], hp, lp);
            *(__nv_bfloat162*)(ph + 8 * 72 + nt * 8) = hp;
            *(__nv_bfloat162*)(pl + 8 * 72 + nt * 8) = lp;
        }
        __syncwarp();

        // ---- O += P V (3-term bf16 split) ----
#pragma unroll
        for (int c = 0; c < 4; c++) {
            uint32_t ah0 = *(const uint32_t*)(ph + c * 16);
            uint32_t ah1 = *(const uint32_t*)(ph + 8 * 72 + c * 16);
            uint32_t ah2 = *(const uint32_t*)(ph + c * 16 + 8);
            uint32_t ah3 = *(const uint32_t*)(ph + 8 * 72 + c * 16 + 8);
            uint32_t al0 = *(const uint32_t*)(pl + c * 16);
            uint32_t al1 = *(const uint32_t*)(pl + 8 * 72 + c * 16);
            uint32_t al2 = *(const uint32_t*)(pl + c * 16 + 8);
            uint32_t al3 = *(const uint32_t*)(pl + 8 * 72 + c * 16 + 8);
#pragma unroll
            for (int nt = 0; nt < 16; nt++) {
                const __nv_bfloat16* vp  = Vth + (nt * 8 + g) * 72 + c * 16 + 2 * t;
                const __nv_bfloat16* vpl = Vtl + (nt * 8 + g) * 72 + c * 16 + 2 * t;
                uint32_t bh0 = *(const uint32_t*)(vp);
                uint32_t bh1 = *(const uint32_t*)(vp + 8);
                uint32_t bl0 = *(const uint32_t*)(vpl);
                uint32_t bl1 = *(const uint32_t*)(vpl + 8);
                mma_bf16(o[nt], ah0, ah1, ah2, ah3, bh0, bh1);
                mma_bf16(o[nt], ah0, ah1, ah2, ah3, bl0, bl1);
                mma_bf16(o[nt], al0, al1, al2, al3, bh0, bh1);
            }
        }
    }

    // ---- normalize + writeback ----
    float inv0 = 1.0f / l0, inv1 = 1.0f / l1;
    int row0 = q0 + warp * 16 + g;
#pragma unroll
    for (int nt = 0; nt < 16; nt++) {
        int col = h * HD + nt * 8 + 2 * t;
        *(float2*)&g_attn[(size_t)row0 * D_MODEL + col] =
            make_float2(o[nt][0] * inv0, o[nt][1] * inv0);
        *(float2*)&g_attn[(size_t)(row0 + 8) * D_MODEL + col] =
            make_float2(o[nt][2] * inv1, o[nt][3] * inv1);
    }
}

// ---------------------------------------------------------------------------
extern "C" void kernel_launch(void* const* d_in, const int* in_sizes, int n_in,
                              void* d_out, int out_size)
{
    const float* hidden = (const float*)d_in[0];
    const float* cosb   = (const float*)d_in[1];
    const float* sinb   = (const float*)d_in[2];
    const float* Wq = (const float*)d_in[4];
    const float* Wk = (const float*)d_in[5];
    const float* Wv = (const float*)d_in[6];
    const float* Wo = (const float*)d_in[7];
    const float* qw = (const float*)d_in[8];
    const float* kw = (const float*)d_in[9];
    float* out = (float*)d_out;

    float *qp, *kp, *vp, *ap;
    cudaGetSymbolAddress((void**)&qp, g_q);
    cudaGetSymbolAddress((void**)&kp, g_k);
    cudaGetSymbolAddress((void**)&vp, g_v);
    cudaGetSymbolAddress((void**)&ap, g_attn);

    cudaFuncSetAttribute(tgemm_nt<true>,  cudaFuncAttributeMaxDynamicSharedMemorySize, TGEMM_SMEM);
    cudaFuncSetAttribute(tgemm_nt<false>, cudaFuncAttributeMaxDynamicSharedMemorySize, TGEMM_SMEM);
    cudaFuncSetAttribute(flash_attn_tc, cudaFuncAttributeMaxDynamicSharedMemorySize, FLASH_SMEM_TC);

    tgemm_nt<true><<<dim3(32, 16), 256, TGEMM_SMEM>>>(hidden, Wq, qp, 2048, 4096, 4096);
    tgemm_nt<true><<<dim3(8, 16),  256, TGEMM_SMEM>>>(hidden, Wk, kp, 2048, 1024, 4096);
    tgemm_nt<true><<<dim3(8, 16),  256, TGEMM_SMEM>>>(hidden, Wv, vp, 2048, 1024, 4096);

    rmsnorm_rope<<<10240, 256>>>(cosb, sinb, qw, kw);

    flash_attn_tc<<<dim3(16, 32), 256, FLASH_SMEM_TC>>>();

    tgemm_nt<false><<<dim3(32, 16), 256, TGEMM_SMEM>>>(ap, Wo, out, 2048, 4096, 4096);
}

// round 4
// speedup vs baseline: 2.9709x; 1.3319x over previous
#include <cuda_runtime.h>
#include <cuda_bf16.h>
#include <math.h>
#include <stdint.h>

#define S_LEN   2048
#define D_MODEL 4096
#define NQH     32
#define NKVH    8
#define HD      128
#define KV_DIM  1024
#define SCALE_F 0.08838834764831845f   // 128^-0.5

__device__ float g_q[S_LEN * D_MODEL];
__device__ float g_k[S_LEN * KV_DIM];
__device__ float g_v[S_LEN * KV_DIM];
__device__ float g_attn[S_LEN * D_MODEL];

// ---------------------------------------------------------------------------
// bf16 hi/lo-split tensor-core GEMM NT: C[M,N] = A[M,K] @ B[N,K]^T, fp32 I/O.
// 3-term split (hi*hi + hi*lo + lo*hi) done PRODUCER-side during STS.
// Block 128x128, BK=32, 256 threads (8 warps, 4m x 2n), warp tile 32x64.
// smem row stride 40 bf16 -> fragment LDS banks (20g+t)%32 all distinct.
// ---------------------------------------------------------------------------
#define LDB   40
#define BSTG  (128 * LDB)          // bf16 per plane
#define STG4  (4 * BSTG)           // bf16 per stage (Ah,Al,Bh,Bl)
#define BGEMM_SMEM (2 * STG4 * (int)sizeof(__nv_bfloat16))   // 81920 B

__device__ __forceinline__ void mma_bf16(float (&d)[4],
    uint32_t a0, uint32_t a1, uint32_t a2, uint32_t a3,
    uint32_t b0, uint32_t b1) {
    asm volatile(
        "mma.sync.aligned.m16n8k16.row.col.f32.bf16.bf16.f32 "
        "{%0,%1,%2,%3}, {%4,%5,%6,%7}, {%8,%9}, {%0,%1,%2,%3};\n"
        : "+f"(d[0]), "+f"(d[1]), "+f"(d[2]), "+f"(d[3])
        : "r"(a0), "r"(a1), "r"(a2), "r"(a3), "r"(b0), "r"(b1));
}

__device__ __forceinline__ void split_sts(float4 v, __nv_bfloat16* hi, __nv_bfloat16* lo) {
    __nv_bfloat162 h01 = __floats2bfloat162_rn(v.x, v.y);
    __nv_bfloat162 h23 = __floats2bfloat162_rn(v.z, v.w);
    float2 f01 = __bfloat1622float2(h01);
    float2 f23 = __bfloat1622float2(h23);
    __nv_bfloat162 l01 = __floats2bfloat162_rn(v.x - f01.x, v.y - f01.y);
    __nv_bfloat162 l23 = __floats2bfloat162_rn(v.z - f23.x, v.w - f23.y);
    *(__nv_bfloat162*)(hi)     = h01;
    *(__nv_bfloat162*)(hi + 2) = h23;
    *(__nv_bfloat162*)(lo)     = l01;
    *(__nv_bfloat162*)(lo + 2) = l23;
}

__device__ __forceinline__ void bgemm_body(const float* __restrict__ A,
                                           const float* __restrict__ B,
                                           float* __restrict__ C,
                                           int N, int K)
{
    extern __shared__ __nv_bfloat16 smb[];

    const int tid  = threadIdx.x;
    const int warp = tid >> 5;
    const int lane = tid & 31;
    const int g    = lane >> 2;
    const int t    = lane & 3;
    const int wm   = (warp & 3) * 32;
    const int wn   = (warp >> 2) * 64;

    const float* Ab = A + (size_t)blockIdx.y * 128 * K;
    const float* Bb = B + (size_t)blockIdx.x * 128 * K;

    const int lrow = tid >> 3;          // 0..31
    const int lcol = (tid & 7) * 4;     // 0..28

    float4 ra[4], rb[4];
    float acc[2][8][4];
#pragma unroll
    for (int i = 0; i < 2; i++)
#pragma unroll
        for (int j = 0; j < 8; j++)
#pragma unroll
            for (int c = 0; c < 4; c++) acc[i][j][c] = 0.0f;

    const int nk = K / 32;

#define LOADG(KT)                                                              \
    {                                                                          \
        const float* ap_ = Ab + (size_t)lrow * K + (KT) * 32 + lcol;           \
        const float* bp_ = Bb + (size_t)lrow * K + (KT) * 32 + lcol;           \
        ra[0] = *(const float4*)(ap_);                                         \
        ra[1] = *(const float4*)(ap_ + (size_t)32 * K);                        \
        ra[2] = *(const float4*)(ap_ + (size_t)64 * K);                        \
        ra[3] = *(const float4*)(ap_ + (size_t)96 * K);                        \
        rb[0] = *(const float4*)(bp_);                                         \
        rb[1] = *(const float4*)(bp_ + (size_t)32 * K);                        \
        rb[2] = *(const float4*)(bp_ + (size_t)64 * K);                        \
        rb[3] = *(const float4*)(bp_ + (size_t)96 * K);                        \
    }

#define STS(ST)                                                                \
    {                                                                          \
        __nv_bfloat16* sb_ = smb + (ST) * STG4;                                \
        int off_ = lrow * LDB + lcol;                                          \
        split_sts(ra[0], sb_ + off_,            sb_ + BSTG + off_);            \
        split_sts(ra[1], sb_ + off_ + 32 * LDB, sb_ + BSTG + off_ + 32 * LDB); \
        split_sts(ra[2], sb_ + off_ + 64 * LDB, sb_ + BSTG + off_ + 64 * LDB); \
        split_sts(ra[3], sb_ + off_ + 96 * LDB, sb_ + BSTG + off_ + 96 * LDB); \
        __nv_bfloat16* bh_ = sb_ + 2 * BSTG;                                   \
        split_sts(rb[0], bh_ + off_,            bh_ + BSTG + off_);            \
        split_sts(rb[1], bh_ + off_ + 32 * LDB, bh_ + BSTG + off_ + 32 * LDB); \
        split_sts(rb[2], bh_ + off_ + 64 * LDB, bh_ + BSTG + off_ + 64 * LDB); \
        split_sts(rb[3], bh_ + off_ + 96 * LDB, bh_ + BSTG + off_ + 96 * LDB); \
    }

    LOADG(0);
    STS(0);
    if (nk > 1) LOADG(1);
    __syncthreads();

    for (int kt = 0; kt < nk; kt++) {
        const __nv_bfloat16* Ah = smb + (kt & 1) * STG4;
        const __nv_bfloat16* Al = Ah + BSTG;
        const __nv_bfloat16* Bh = Ah + 2 * BSTG;
        const __nv_bfloat16* Bl = Ah + 3 * BSTG;

#pragma unroll
        for (int k16 = 0; k16 < 2; k16++) {
            uint32_t ah[2][4], al[2][4];
#pragma unroll
            for (int mt = 0; mt < 2; mt++) {
                const __nv_bfloat16* p  = Ah + (wm + mt * 16 + g) * LDB + k16 * 16 + 2 * t;
                const __nv_bfloat16* pl = Al + (wm + mt * 16 + g) * LDB + k16 * 16 + 2 * t;
                ah[mt][0] = *(const uint32_t*)(p);
                ah[mt][1] = *(const uint32_t*)(p + 8 * LDB);
                ah[mt][2] = *(const uint32_t*)(p + 8);
                ah[mt][3] = *(const uint32_t*)(p + 8 * LDB + 8);
                al[mt][0] = *(const uint32_t*)(pl);
                al[mt][1] = *(const uint32_t*)(pl + 8 * LDB);
                al[mt][2] = *(const uint32_t*)(pl + 8);
                al[mt][3] = *(const uint32_t*)(pl + 8 * LDB + 8);
            }
#pragma unroll
            for (int nh = 0; nh < 2; nh++) {
                uint32_t bh[4][2], bl[4][2];
#pragma unroll
                for (int j = 0; j < 4; j++) {
                    int nt = nh * 4 + j;
                    const __nv_bfloat16* p  = Bh + (wn + nt * 8 + g) * LDB + k16 * 16 + 2 * t;
                    const __nv_bfloat16* pl = Bl + (wn + nt * 8 + g) * LDB + k16 * 16 + 2 * t;
                    bh[j][0] = *(const uint32_t*)(p);
                    bh[j][1] = *(const uint32_t*)(p + 8);
                    bl[j][0] = *(const uint32_t*)(pl);
                    bl[j][1] = *(const uint32_t*)(pl + 8);
                }
#pragma unroll
                for (int mt = 0; mt < 2; mt++)
#pragma unroll
                    for (int j = 0; j < 4; j++) {
                        float (&d)[4] = acc[mt][nh * 4 + j];
                        mma_bf16(d, ah[mt][0], ah[mt][1], ah[mt][2], ah[mt][3],
                                 bl[j][0], bl[j][1]);
                        mma_bf16(d, al[mt][0], al[mt][1], al[mt][2], al[mt][3],
                                 bh[j][0], bh[j][1]);
                        mma_bf16(d, ah[mt][0], ah[mt][1], ah[mt][2], ah[mt][3],
                                 bh[j][0], bh[j][1]);
                    }
            }
        }

        if (kt + 1 < nk) {
            STS((kt + 1) & 1);
            __syncthreads();
            if (kt + 2 < nk) LOADG(kt + 2);
        }
    }

#pragma unroll
    for (int mt = 0; mt < 2; mt++) {
        int r0 = blockIdx.y * 128 + wm + mt * 16 + g;
#pragma unroll
        for (int nt = 0; nt < 8; nt++) {
            int c0 = blockIdx.x * 128 + wn + nt * 8 + 2 * t;
            *(float2*)&C[(size_t)r0 * N + c0] =
                make_float2(acc[mt][nt][0], acc[mt][nt][1]);
            *(float2*)&C[(size_t)(r0 + 8) * N + c0] =
                make_float2(acc[mt][nt][2], acc[mt][nt][3]);
        }
    }
#undef LOADG
#undef STS
}

__global__ __launch_bounds__(256, 2)
void bgemm_nt(const float* __restrict__ A, const float* __restrict__ B,
              float* __restrict__ C, int N, int K)
{
    bgemm_body(A, B, C, N, K);
}

// K and V projections fused into one launch (grid.z selects) to fill the wave.
__global__ __launch_bounds__(256, 2)
void bgemm_kv(const float* __restrict__ A,
              const float* __restrict__ B0, const float* __restrict__ B1,
              float* __restrict__ C0, float* __restrict__ C1, int N, int K)
{
    bgemm_body(A, blockIdx.z ? B1 : B0, blockIdx.z ? C1 : C0, N, K);
}

// ---------------------------------------------------------------------------
// Fused per-head RMSNorm + RoPE (unchanged)
// ---------------------------------------------------------------------------
__global__ __launch_bounds__(256)
void rmsnorm_rope(const float* __restrict__ cosb, const float* __restrict__ sinb,
                  const float* __restrict__ qw, const float* __restrict__ kw)
{
    const int warp = blockIdx.x * 8 + (threadIdx.x >> 5);
    const int lane = threadIdx.x & 31;

    float* base;
    const float* w;
    int s;
    if (warp < S_LEN * NQH) {
        s = warp / NQH;
        int h = warp - s * NQH;
        base = g_q + (size_t)s * D_MODEL + h * HD;
        w = qw;
    } else {
        int wv = warp - S_LEN * NQH;
        s = wv / NKVH;
        int h = wv - s * NKVH;
        base = g_k + (size_t)s * KV_DIM + h * HD;
        w = kw;
    }

    float x0 = base[lane];
    float x1 = base[lane + 32];
    float x2 = base[lane + 64];
    float x3 = base[lane + 96];

    float ss = x0 * x0 + x1 * x1 + x2 * x2 + x3 * x3;
#pragma unroll
    for (int o = 16; o; o >>= 1) ss += __shfl_xor_sync(0xffffffffu, ss, o);
    float inv = rsqrtf(ss * (1.0f / 128.0f) + 1e-6f);

    float n0 = w[lane]      * x0 * inv;
    float n1 = w[lane + 32] * x1 * inv;
    float n2 = w[lane + 64] * x2 * inv;
    float n3 = w[lane + 96] * x3 * inv;

    const float c0 = cosb[s * 64 + lane];
    const float c1 = cosb[s * 64 + lane + 32];
    const float s0 = sinb[s * 64 + lane];
    const float s1 = sinb[s * 64 + lane + 32];

    base[lane]      = n0 * c0 - n2 * s0;
    base[lane + 32] = n1 * c1 - n3 * s1;
    base[lane + 64] = n2 * c0 + n0 * s0;
    base[lane + 96] = n3 * c1 + n1 * s1;
}

// ---------------------------------------------------------------------------
// Tensor-core flash attention (unchanged from R3)
// ---------------------------------------------------------------------------
#define OFF_QHI  0
#define OFF_QLO  17408
#define OFF_KHI  34816
#define OFF_KLO  43520
#define OFF_VTH  52224
#define OFF_VTL  61440
#define OFF_PSH  70656
#define OFF_PSL  79872
#define FLASH_SMEM_TC (89088 * 2)

__device__ __forceinline__ void split2(float x0, float x1,
                                       __nv_bfloat162& hi, __nv_bfloat162& lo) {
    hi = __floats2bfloat162_rn(x0, x1);
    float2 hf = __bfloat1622float2(hi);
    lo = __floats2bfloat162_rn(x0 - hf.x, x1 - hf.y);
}

__global__ __launch_bounds__(256, 1)
void flash_attn_tc()
{
    extern __shared__ __nv_bfloat16 smb[];
    __nv_bfloat16* Qhi = smb + OFF_QHI;
    __nv_bfloat16* Qlo = smb + OFF_QLO;
    __nv_bfloat16* Khi = smb + OFF_KHI;
    __nv_bfloat16* Klo = smb + OFF_KLO;
    __nv_bfloat16* Vth = smb + OFF_VTH;
    __nv_bfloat16* Vtl = smb + OFF_VTL;
    __nv_bfloat16* Psh = smb + OFF_PSH;
    __nv_bfloat16* Psl = smb + OFF_PSL;

    const int qt  = 15 - blockIdx.x;
    const int h   = blockIdx.y;
    const int q0  = qt * 128;
    const int kvh = h >> 2;
    const int tid  = threadIdx.x;
    const int warp = tid >> 5;
    const int lane = tid & 31;
    const int g = lane >> 2;
    const int t = lane & 3;

    for (int i = tid; i < 128 * 32; i += 256) {
        int r = i >> 5, c = (i & 31) << 2;
        float4 v = *(const float4*)&g_q[(size_t)(q0 + r) * D_MODEL + h * HD + c];
        __nv_bfloat162 h01, l01, h23, l23;
        split2(v.x, v.y, h01, l01);
        split2(v.z, v.w, h23, l23);
        *(__nv_bfloat162*)(Qhi + r * 136 + c)     = h01;
        *(__nv_bfloat162*)(Qhi + r * 136 + c + 2) = h23;
        *(__nv_bfloat162*)(Qlo + r * 136 + c)     = l01;
        *(__nv_bfloat162*)(Qlo + r * 136 + c + 2) = l23;
    }

    float o[16][4];
#pragma unroll
    for (int nt = 0; nt < 16; nt++)
#pragma unroll
        for (int j = 0; j < 4; j++) o[nt][j] = 0.0f;
    float m0 = -1e30f, m1 = -1e30f, l0 = 0.0f, l1 = 0.0f;

    const int wrow = q0 + warp * 16;
    const int nkt  = 2 * qt + 2;

    for (int kt = 0; kt < nkt; kt++) {
        const int k0 = kt * 64;
        __syncthreads();
        for (int i = tid; i < 64 * 32; i += 256) {
            int r = i >> 5, c = (i & 31) << 2;
            float4 v = *(const float4*)&g_k[(size_t)(k0 + r) * KV_DIM + kvh * HD + c];
            __nv_bfloat162 h01, l01, h23, l23;
            split2(v.x, v.y, h01, l01);
            split2(v.z, v.w, h23, l23);
            *(__nv_bfloat162*)(Khi + r * 136 + c)     = h01;
            *(__nv_bfloat162*)(Khi + r * 136 + c + 2) = h23;
            *(__nv_bfloat162*)(Klo + r * 136 + c)     = l01;
            *(__nv_bfloat162*)(Klo + r * 136 + c + 2) = l23;
        }
        for (int i = tid; i < 64 * 32; i += 256) {
            int r = i & 63, c = (i >> 6) << 2;
            float4 v = *(const float4*)&g_v[(size_t)(k0 + r) * KV_DIM + kvh * HD + c];
            float x[4] = {v.x, v.y, v.z, v.w};
#pragma unroll
            for (int j = 0; j < 4; j++) {
                __nv_bfloat16 hb = __float2bfloat16(x[j]);
                Vth[(c + j) * 72 + r] = hb;
                Vtl[(c + j) * 72 + r] = __float2bfloat16(x[j] - __bfloat162float(hb));
            }
        }
        __syncthreads();

        if (k0 > wrow + 15) continue;

        float s[8][4];
#pragma unroll
        for (int nt = 0; nt < 8; nt++)
#pragma unroll
            for (int j = 0; j < 4; j++) s[nt][j] = 0.0f;

        const __nv_bfloat16* qrh = Qhi + (warp * 16 + g) * 136 + 2 * t;
        const __nv_bfloat16* qrl = Qlo + (warp * 16 + g) * 136 + 2 * t;
#pragma unroll
        for (int c = 0; c < 8; c++) {
            uint32_t ah0 = *(const uint32_t*)(qrh + c * 16);
            uint32_t ah1 = *(const uint32_t*)(qrh + 8 * 136 + c * 16);
            uint32_t ah2 = *(const uint32_t*)(qrh + c * 16 + 8);
            uint32_t ah3 = *(const uint32_t*)(qrh + 8 * 136 + c * 16 + 8);
            uint32_t al0 = *(const uint32_t*)(qrl + c * 16);
            uint32_t al1 = *(const uint32_t*)(qrl + 8 * 136 + c * 16);
            uint32_t al2 = *(const uint32_t*)(qrl + c * 16 + 8);
            uint32_t al3 = *(const uint32_t*)(qrl + 8 * 136 + c * 16 + 8);
#pragma unroll
            for (int nt = 0; nt < 8; nt++) {
                const __nv_bfloat16* kp  = Khi + (nt * 8 + g) * 136 + c * 16 + 2 * t;
                const __nv_bfloat16* kpl = Klo + (nt * 8 + g) * 136 + c * 16 + 2 * t;
                uint32_t bh0 = *(const uint32_t*)(kp);
                uint32_t bh1 = *(const uint32_t*)(kp + 8);
                uint32_t bl0 = *(const uint32_t*)(kpl);
                uint32_t bl1 = *(const uint32_t*)(kpl + 8);
                mma_bf16(s[nt], ah0, ah1, ah2, ah3, bh0, bh1);
                mma_bf16(s[nt], ah0, ah1, ah2, ah3, bl0, bl1);
                mma_bf16(s[nt], al0, al1, al2, al3, bh0, bh1);
            }
        }

        if (k0 + 63 > wrow) {
            int r0 = wrow + g, r1 = r0 + 8;
#pragma unroll
            for (int nt = 0; nt < 8; nt++) {
                int c0 = k0 + nt * 8 + 2 * t;
                s[nt][0] = (c0     > r0) ? -1e30f : s[nt][0] * SCALE_F;
                s[nt][1] = (c0 + 1 > r0) ? -1e30f : s[nt][1] * SCALE_F;
                s[nt][2] = (c0     > r1) ? -1e30f : s[nt][2] * SCALE_F;
                s[nt][3] = (c0 + 1 > r1) ? -1e30f : s[nt][3] * SCALE_F;
            }
        } else {
#pragma unroll
            for (int nt = 0; nt < 8; nt++)
#pragma unroll
                for (int j = 0; j < 4; j++) s[nt][j] *= SCALE_F;
        }

        float mx0 = -1e30f, mx1 = -1e30f;
#pragma unroll
        for (int nt = 0; nt < 8; nt++) {
            mx0 = fmaxf(mx0, fmaxf(s[nt][0], s[nt][1]));
            mx1 = fmaxf(mx1, fmaxf(s[nt][2], s[nt][3]));
        }
        mx0 = fmaxf(mx0, __shfl_xor_sync(0xffffffffu, mx0, 1));
        mx0 = fmaxf(mx0, __shfl_xor_sync(0xffffffffu, mx0, 2));
        mx1 = fmaxf(mx1, __shfl_xor_sync(0xffffffffu, mx1, 1));
        mx1 = fmaxf(mx1, __shfl_xor_sync(0xffffffffu, mx1, 2));

        float mn0 = fmaxf(m0, mx0), mn1 = fmaxf(m1, mx1);
        float a0 = __expf(m0 - mn0), a1 = __expf(m1 - mn1);
        m0 = mn0; m1 = mn1;

        float sum0 = 0.0f, sum1 = 0.0f;
#pragma unroll
        for (int nt = 0; nt < 8; nt++) {
            s[nt][0] = __expf(s[nt][0] - m0);
            s[nt][1] = __expf(s[nt][1] - m0);
            s[nt][2] = __expf(s[nt][2] - m1);
            s[nt][3] = __expf(s[nt][3] - m1);
            sum0 += s[nt][0] + s[nt][1];
            sum1 += s[nt][2] + s[nt][3];
        }
        sum0 += __shfl_xor_sync(0xffffffffu, sum0, 1);
        sum0 += __shfl_xor_sync(0xffffffffu, sum0, 2);
        sum1 += __shfl_xor_sync(0xffffffffu, sum1, 1);
        sum1 += __shfl_xor_sync(0xffffffffu, sum1, 2);
        l0 = l0 * a0 + sum0;
        l1 = l1 * a1 + sum1;

#pragma unroll
        for (int nt = 0; nt < 16; nt++) {
            o[nt][0] *= a0; o[nt][1] *= a0;
            o[nt][2] *= a1; o[nt][3] *= a1;
        }

        __nv_bfloat16* ph = Psh + (warp * 16 + g) * 72 + 2 * t;
        __nv_bfloat16* pl = Psl + (warp * 16 + g) * 72 + 2 * t;
#pragma unroll
        for (int nt = 0; nt < 8; nt++) {
            __nv_bfloat162 hp, lp;
            split2(s[nt][0], s[nt][1], hp, lp);
            *(__nv_bfloat162*)(ph + nt * 8) = hp;
            *(__nv_bfloat162*)(pl + nt * 8) = lp;
            split2(s[nt][2], s[nt][3], hp, lp);
            *(__nv_bfloat162*)(ph + 8 * 72 + nt * 8) = hp;
            *(__nv_bfloat162*)(pl + 8 * 72 + nt * 8) = lp;
        }
        __syncwarp();

#pragma unroll
        for (int c = 0; c < 4; c++) {
            uint32_t ah0 = *(const uint32_t*)(ph + c * 16);
            uint32_t ah1 = *(const uint32_t*)(ph + 8 * 72 + c * 16);
            uint32_t ah2 = *(const uint32_t*)(ph + c * 16 + 8);
            uint32_t ah3 = *(const uint32_t*)(ph + 8 * 72 + c * 16 + 8);
            uint32_t al0 = *(const uint32_t*)(pl + c * 16);
            uint32_t al1 = *(const uint32_t*)(pl + 8 * 72 + c * 16);
            uint32_t al2 = *(const uint32_t*)(pl + c * 16 + 8);
            uint32_t al3 = *(const uint32_t*)(pl + 8 * 72 + c * 16 + 8);
#pragma unroll
            for (int nt = 0; nt < 16; nt++) {
                const __nv_bfloat16* vp  = Vth + (nt * 8 + g) * 72 + c * 16 + 2 * t;
                const __nv_bfloat16* vpl = Vtl + (nt * 8 + g) * 72 + c * 16 + 2 * t;
                uint32_t bh0 = *(const uint32_t*)(vp);
                uint32_t bh1 = *(const uint32_t*)(vp + 8);
                uint32_t bl0 = *(const uint32_t*)(vpl);
                uint32_t bl1 = *(const uint32_t*)(vpl + 8);
                mma_bf16(o[nt], ah0, ah1, ah2, ah3, bh0, bh1);
                mma_bf16(o[nt], ah0, ah1, ah2, ah3, bl0, bl1);
                mma_bf16(o[nt], al0, al1, al2, al3, bh0, bh1);
            }
        }
    }

    float inv0 = 1.0f / l0, inv1 = 1.0f / l1;
    int row0 = q0 + warp * 16 + g;
#pragma unroll
    for (int nt = 0; nt < 16; nt++) {
        int col = h * HD + nt * 8 + 2 * t;
        *(float2*)&g_attn[(size_t)row0 * D_MODEL + col] =
            make_float2(o[nt][0] * inv0, o[nt][1] * inv0);
        *(float2*)&g_attn[(size_t)(row0 + 8) * D_MODEL + col] =
            make_float2(o[nt][2] * inv1, o[nt][3] * inv1);
    }
}

// ---------------------------------------------------------------------------
extern "C" void kernel_launch(void* const* d_in, const int* in_sizes, int n_in,
                              void* d_out, int out_size)
{
    const float* hidden = (const float*)d_in[0];
    const float* cosb   = (const float*)d_in[1];
    const float* sinb   = (const float*)d_in[2];
    const float* Wq = (const float*)d_in[4];
    const float* Wk = (const float*)d_in[5];
    const float* Wv = (const float*)d_in[6];
    const float* Wo = (const float*)d_in[7];
    const float* qw = (const float*)d_in[8];
    const float* kw = (const float*)d_in[9];
    float* out = (float*)d_out;

    float *qp, *kp, *vp, *ap;
    cudaGetSymbolAddress((void**)&qp, g_q);
    cudaGetSymbolAddress((void**)&kp, g_k);
    cudaGetSymbolAddress((void**)&vp, g_v);
    cudaGetSymbolAddress((void**)&ap, g_attn);

    cudaFuncSetAttribute(bgemm_nt, cudaFuncAttributeMaxDynamicSharedMemorySize, BGEMM_SMEM);
    cudaFuncSetAttribute(bgemm_kv, cudaFuncAttributeMaxDynamicSharedMemorySize, BGEMM_SMEM);
    cudaFuncSetAttribute(flash_attn_tc, cudaFuncAttributeMaxDynamicSharedMemorySize, FLASH_SMEM_TC);

    // Q projection + fused K/V projections (all bf16 3-term split)
    bgemm_nt<<<dim3(32, 16), 256, BGEMM_SMEM>>>(hidden, Wq, qp, 4096, 4096);
    bgemm_kv<<<dim3(8, 16, 2), 256, BGEMM_SMEM>>>(hidden, Wk, Wv, kp, vp, 1024, 4096);

    rmsnorm_rope<<<10240, 256>>>(cosb, sinb, qw, kw);

    flash_attn_tc<<<dim3(16, 32), 256, FLASH_SMEM_TC>>>();

    // O projection (now also split -> accuracy improves)
    bgemm_nt<<<dim3(32, 16), 256, BGEMM_SMEM>>>(ap, Wo, out, 4096, 4096);
}

// round 5
// speedup vs baseline: 3.1287x; 1.0531x over previous
#include <cuda_runtime.h>
#include <cuda_bf16.h>
#include <math.h>
#include <stdint.h>

#define S_LEN   2048
#define D_MODEL 4096
#define NQH     32
#define NKVH    8
#define HD      128
#define KV_DIM  1024
#define SCALE_F 0.08838834764831845f   // 128^-0.5

__device__ float g_q[S_LEN * D_MODEL];
__device__ float g_k[S_LEN * KV_DIM];
__device__ float g_v[S_LEN * KV_DIM];
__device__ float g_attn[S_LEN * D_MODEL];

// ---------------------------------------------------------------------------
// common mma / split helpers
// ---------------------------------------------------------------------------
__device__ __forceinline__ void mma_bf16(float (&d)[4],
    uint32_t a0, uint32_t a1, uint32_t a2, uint32_t a3,
    uint32_t b0, uint32_t b1) {
    asm volatile(
        "mma.sync.aligned.m16n8k16.row.col.f32.bf16.bf16.f32 "
        "{%0,%1,%2,%3}, {%4,%5,%6,%7}, {%8,%9}, {%0,%1,%2,%3};\n"
        : "+f"(d[0]), "+f"(d[1]), "+f"(d[2]), "+f"(d[3])
        : "r"(a0), "r"(a1), "r"(a2), "r"(a3), "r"(b0), "r"(b1));
}

__device__ __forceinline__ void ldsm4(uint32_t (&r)[4], uint32_t addr) {
    asm volatile("ldmatrix.sync.aligned.m8n8.x4.shared.b16 {%0,%1,%2,%3}, [%4];"
        : "=r"(r[0]), "=r"(r[1]), "=r"(r[2]), "=r"(r[3]) : "r"(addr));
}

__device__ __forceinline__ void split2(float x0, float x1,
                                       __nv_bfloat162& hi, __nv_bfloat162& lo) {
    hi = __floats2bfloat162_rn(x0, x1);
    float2 hf = __bfloat1622float2(hi);
    lo = __floats2bfloat162_rn(x0 - hf.x, x1 - hf.y);
}

__device__ __forceinline__ uint32_t b2u(__nv_bfloat162 v) {
    return *reinterpret_cast<uint32_t*>(&v);
}

// ---------------------------------------------------------------------------
// bf16 hi/lo-split tensor-core GEMM NT, producer-side split, ldmatrix frags.
// Block 128x128, BK=32, 256 threads (8 warps, 4m x 2n), warp tile 32x64.
// ---------------------------------------------------------------------------
#define LDB   40
#define BSTG  (128 * LDB)
#define STG4  (4 * BSTG)
#define BGEMM_SMEM (2 * STG4 * (int)sizeof(__nv_bfloat16))   // 81920 B

__device__ __forceinline__ void split_sts(float4 v, __nv_bfloat16* hi, __nv_bfloat16* lo) {
    __nv_bfloat162 h01, l01, h23, l23;
    split2(v.x, v.y, h01, l01);
    split2(v.z, v.w, h23, l23);
    *(__nv_bfloat162*)(hi)     = h01;
    *(__nv_bfloat162*)(hi + 2) = h23;
    *(__nv_bfloat162*)(lo)     = l01;
    *(__nv_bfloat162*)(lo + 2) = l23;
}

__device__ __forceinline__ void bgemm_body(const float* __restrict__ A,
                                           const float* __restrict__ B,
                                           float* __restrict__ C,
                                           int N, int K, int bx, int by)
{
    extern __shared__ __nv_bfloat16 smb[];

    const int tid  = threadIdx.x;
    const int warp = tid >> 5;
    const int lane = tid & 31;
    const int g    = lane >> 2;
    const int t    = lane & 3;
    const int wm   = (warp & 3) * 32;
    const int wn   = (warp >> 2) * 64;

    const float* Ab = A + (size_t)by * 128 * K;
    const float* Bb = B + (size_t)bx * 128 * K;

    const int lrow = tid >> 3;
    const int lcol = (tid & 7) * 4;

    // ldmatrix per-thread byte offsets within a plane
    const int lane8 = lane & 7;
    const uint32_t smem_u32 = (uint32_t)__cvta_generic_to_shared(smb);
    const uint32_t a_off = ((wm + lane8 + ((lane >> 3) & 1) * 8) * LDB + (lane >> 4) * 8) * 2;
    const uint32_t b_off = ((wn + lane8 + (lane >> 4) * 8) * LDB + ((lane >> 3) & 1) * 8) * 2;

    float4 ra[4], rb[4];
    float acc[2][8][4];
#pragma unroll
    for (int i = 0; i < 2; i++)
#pragma unroll
        for (int j = 0; j < 8; j++)
#pragma unroll
            for (int c = 0; c < 4; c++) acc[i][j][c] = 0.0f;

    const int nk = K / 32;

#define LOADG(KT)                                                              \
    {                                                                          \
        const float* ap_ = Ab + (size_t)lrow * K + (KT) * 32 + lcol;           \
        const float* bp_ = Bb + (size_t)lrow * K + (KT) * 32 + lcol;           \
        ra[0] = *(const float4*)(ap_);                                         \
        ra[1] = *(const float4*)(ap_ + (size_t)32 * K);                        \
        ra[2] = *(const float4*)(ap_ + (size_t)64 * K);                        \
        ra[3] = *(const float4*)(ap_ + (size_t)96 * K);                        \
        rb[0] = *(const float4*)(bp_);                                         \
        rb[1] = *(const float4*)(bp_ + (size_t)32 * K);                        \
        rb[2] = *(const float4*)(bp_ + (size_t)64 * K);                        \
        rb[3] = *(const float4*)(bp_ + (size_t)96 * K);                        \
    }

#define STS(ST)                                                                \
    {                                                                          \
        __nv_bfloat16* sb_ = smb + (ST) * STG4;                                \
        int off_ = lrow * LDB + lcol;                                          \
        split_sts(ra[0], sb_ + off_,            sb_ + BSTG + off_);            \
        split_sts(ra[1], sb_ + off_ + 32 * LDB, sb_ + BSTG + off_ + 32 * LDB); \
        split_sts(ra[2], sb_ + off_ + 64 * LDB, sb_ + BSTG + off_ + 64 * LDB); \
        split_sts(ra[3], sb_ + off_ + 96 * LDB, sb_ + BSTG + off_ + 96 * LDB); \
        __nv_bfloat16* bh_ = sb_ + 2 * BSTG;                                   \
        split_sts(rb[0], bh_ + off_,            bh_ + BSTG + off_);            \
        split_sts(rb[1], bh_ + off_ + 32 * LDB, bh_ + BSTG + off_ + 32 * LDB); \
        split_sts(rb[2], bh_ + off_ + 64 * LDB, bh_ + BSTG + off_ + 64 * LDB); \
        split_sts(rb[3], bh_ + off_ + 96 * LDB, bh_ + BSTG + off_ + 96 * LDB); \
    }

    LOADG(0);
    STS(0);
    if (nk > 1) LOADG(1);
    __syncthreads();

    for (int kt = 0; kt < nk; kt++) {
        const uint32_t sb = smem_u32 + (uint32_t)((kt & 1) * STG4) * 2;

#pragma unroll
        for (int k16 = 0; k16 < 2; k16++) {
            uint32_t ah[2][4], al[2][4];
            ldsm4(ah[0], sb + a_off + k16 * 32);
            ldsm4(ah[1], sb + a_off + 16 * LDB * 2 + k16 * 32);
            ldsm4(al[0], sb + BSTG * 2 + a_off + k16 * 32);
            ldsm4(al[1], sb + BSTG * 2 + a_off + 16 * LDB * 2 + k16 * 32);

#pragma unroll
            for (int jh = 0; jh < 2; jh++) {
                uint32_t bh[2][4], bl[2][4];
#pragma unroll
                for (int jj = 0; jj < 2; jj++) {
                    int j = jh * 2 + jj;                 // B row-pair index (16 rows)
                    ldsm4(bh[jj], sb + 2 * BSTG * 2 + b_off + j * 16 * LDB * 2 + k16 * 32);
                    ldsm4(bl[jj], sb + 3 * BSTG * 2 + b_off + j * 16 * LDB * 2 + k16 * 32);
                }
#pragma unroll
                for (int mt = 0; mt < 2; mt++)
#pragma unroll
                    for (int jj = 0; jj < 2; jj++) {
                        int nt = (jh * 2 + jj) * 2;
                        float (&d0)[4] = acc[mt][nt];
                        float (&d1)[4] = acc[mt][nt + 1];
                        mma_bf16(d0, ah[mt][0], ah[mt][1], ah[mt][2], ah[mt][3],
                                 bl[jj][0], bl[jj][1]);
                        mma_bf16(d0, al[mt][0], al[mt][1], al[mt][2], al[mt][3],
                                 bh[jj][0], bh[jj][1]);
                        mma_bf16(d0, ah[mt][0], ah[mt][1], ah[mt][2], ah[mt][3],
                                 bh[jj][0], bh[jj][1]);
                        mma_bf16(d1, ah[mt][0], ah[mt][1], ah[mt][2], ah[mt][3],
                                 bl[jj][2], bl[jj][3]);
                        mma_bf16(d1, al[mt][0], al[mt][1], al[mt][2], al[mt][3],
                                 bh[jj][2], bh[jj][3]);
                        mma_bf16(d1, ah[mt][0], ah[mt][1], ah[mt][2], ah[mt][3],
                                 bh[jj][2], bh[jj][3]);
                    }
            }
        }

        if (kt + 1 < nk) {
            STS((kt + 1) & 1);
            __syncthreads();
            if (kt + 2 < nk) LOADG(kt + 2);
        }
    }

#pragma unroll
    for (int mt = 0; mt < 2; mt++) {
        int r0 = by * 128 + wm + mt * 16 + g;
#pragma unroll
        for (int nt = 0; nt < 8; nt++) {
            int c0 = bx * 128 + wn + nt * 8 + 2 * t;
            *(float2*)&C[(size_t)r0 * N + c0] =
                make_float2(acc[mt][nt][0], acc[mt][nt][1]);
            *(float2*)&C[(size_t)(r0 + 8) * N + c0] =
                make_float2(acc[mt][nt][2], acc[mt][nt][3]);
        }
    }
#undef LOADG
#undef STS
}

// merged Q/K/V projection launch: 768 CTAs (512 Q + 128 K + 128 V)
__global__ __launch_bounds__(256, 2)
void bgemm_qkv(const float* __restrict__ H, const float* __restrict__ Wq,
               const float* __restrict__ Wk, const float* __restrict__ Wv)
{
    int b = blockIdx.x;
    if (b < 512)      bgemm_body(H, Wq, g_q, 4096, 4096, b & 31, b >> 5);
    else if (b < 640) { int i = b - 512; bgemm_body(H, Wk, g_k, 1024, 4096, i & 7, i >> 3); }
    else              { int i = b - 640; bgemm_body(H, Wv, g_v, 1024, 4096, i & 7, i >> 3); }
}

__global__ __launch_bounds__(256, 2)
void bgemm_o(const float* __restrict__ Wo, float* __restrict__ out)
{
    bgemm_body(g_attn, Wo, out, 4096, 4096, blockIdx.x, blockIdx.y);
}

// ---------------------------------------------------------------------------
// Fused per-head RMSNorm + RoPE (unchanged)
// ---------------------------------------------------------------------------
__global__ __launch_bounds__(256)
void rmsnorm_rope(const float* __restrict__ cosb, const float* __restrict__ sinb,
                  const float* __restrict__ qw, const float* __restrict__ kw)
{
    const int warp = blockIdx.x * 8 + (threadIdx.x >> 5);
    const int lane = threadIdx.x & 31;

    float* base;
    const float* w;
    int s;
    if (warp < S_LEN * NQH) {
        s = warp / NQH;
        int h = warp - s * NQH;
        base = g_q + (size_t)s * D_MODEL + h * HD;
        w = qw;
    } else {
        int wv = warp - S_LEN * NQH;
        s = wv / NKVH;
        int h = wv - s * NKVH;
        base = g_k + (size_t)s * KV_DIM + h * HD;
        w = kw;
    }

    float x0 = base[lane];
    float x1 = base[lane + 32];
    float x2 = base[lane + 64];
    float x3 = base[lane + 96];

    float ss = x0 * x0 + x1 * x1 + x2 * x2 + x3 * x3;
#pragma unroll
    for (int o = 16; o; o >>= 1) ss += __shfl_xor_sync(0xffffffffu, ss, o);
    float inv = rsqrtf(ss * (1.0f / 128.0f) + 1e-6f);

    float n0 = w[lane]      * x0 * inv;
    float n1 = w[lane + 32] * x1 * inv;
    float n2 = w[lane + 64] * x2 * inv;
    float n3 = w[lane + 96] * x3 * inv;

    const float c0 = cosb[s * 64 + lane];
    const float c1 = cosb[s * 64 + lane + 32];
    const float s0 = sinb[s * 64 + lane];
    const float s1 = sinb[s * 64 + lane + 32];

    base[lane]      = n0 * c0 - n2 * s0;
    base[lane + 32] = n1 * c1 - n3 * s1;
    base[lane + 64] = n2 * c0 + n0 * s0;
    base[lane + 96] = n3 * c1 + n1 * s1;
}

// ---------------------------------------------------------------------------
// Tensor-core flash attention v2: no P staging (register-direct fragments),
// double-buffered K/V tiles, packed V transpose.
// smem (bf16 units): Q hi/lo 2x17408; per KV buf: Khi 8704, Klo 8704,
// Vth 9216, Vtl 9216 (35840); two buffers.
// ---------------------------------------------------------------------------
#define OFF_QHI  0
#define OFF_QLO  17408
#define OFF_KV   34816
#define KVBUF    35840
#define FLASH_SMEM_TC ((OFF_KV + 2 * KVBUF) * 2)   // 212992 B

__global__ __launch_bounds__(256, 1)
void flash_attn_tc()
{
    extern __shared__ __nv_bfloat16 smb[];
    __nv_bfloat16* Qhi = smb + OFF_QHI;
    __nv_bfloat16* Qlo = smb + OFF_QLO;

    const int qt  = 15 - blockIdx.x;
    const int h   = blockIdx.y;
    const int q0  = qt * 128;
    const int kvh = h >> 2;
    const int tid  = threadIdx.x;
    const int warp = tid >> 5;
    const int lane = tid & 31;
    const int g = lane >> 2;
    const int t = lane & 3;

    // Q tile load + split
    for (int i = tid; i < 128 * 32; i += 256) {
        int r = i >> 5, c = (i & 31) << 2;
        float4 v = *(const float4*)&g_q[(size_t)(q0 + r) * D_MODEL + h * HD + c];
        __nv_bfloat162 h01, l01, h23, l23;
        split2(v.x, v.y, h01, l01);
        split2(v.z, v.w, h23, l23);
        *(__nv_bfloat162*)(Qhi + r * 136 + c)     = h01;
        *(__nv_bfloat162*)(Qhi + r * 136 + c + 2) = h23;
        *(__nv_bfloat162*)(Qlo + r * 136 + c)     = l01;
        *(__nv_bfloat162*)(Qlo + r * 136 + c + 2) = l23;
    }

    float o[16][4];
#pragma unroll
    for (int nt = 0; nt < 16; nt++)
#pragma unroll
        for (int j = 0; j < 4; j++) o[nt][j] = 0.0f;
    float m0 = -1e30f, m1 = -1e30f, l0 = 0.0f, l1 = 0.0f;

    const int wrow = q0 + warp * 16;
    const int nkt  = 2 * qt + 2;

    // KV tile loader (split K rows; V packed-transposed)
#define LOAD_KV(KT, BUF)                                                       \
    {                                                                          \
        __nv_bfloat16* Khi_ = smb + OFF_KV + (BUF) * KVBUF;                    \
        __nv_bfloat16* Klo_ = Khi_ + 8704;                                     \
        __nv_bfloat16* Vth_ = Khi_ + 17408;                                    \
        __nv_bfloat16* Vtl_ = Khi_ + 26624;                                    \
        const int k0_ = (KT) * 64;                                             \
        for (int i = tid; i < 64 * 32; i += 256) {                             \
            int r = i >> 5, c = (i & 31) << 2;                                 \
            float4 v = *(const float4*)&g_k[(size_t)(k0_ + r) * KV_DIM + kvh * HD + c]; \
            __nv_bfloat162 h01, l01, h23, l23;                                 \
            split2(v.x, v.y, h01, l01);                                        \
            split2(v.z, v.w, h23, l23);                                        \
            *(__nv_bfloat162*)(Khi_ + r * 136 + c)     = h01;                  \
            *(__nv_bfloat162*)(Khi_ + r * 136 + c + 2) = h23;                  \
            *(__nv_bfloat162*)(Klo_ + r * 136 + c)     = l01;                  \
            *(__nv_bfloat162*)(Klo_ + r * 136 + c + 2) = l23;                  \
        }                                                                      \
        for (int u = tid; u < 1024; u += 256) {                                \
            int p = u & 31, c4 = u >> 5;                                       \
            const float* vp_ = &g_v[(size_t)(k0_ + 2 * p) * KV_DIM + kvh * HD + c4 * 4]; \
            float4 va = *(const float4*)vp_;                                   \
            float4 vb = *(const float4*)(vp_ + KV_DIM);                        \
            _Pragma("unroll")                                                  \
            for (int j = 0; j < 4; j++) {                                      \
                __nv_bfloat162 hi_, lo_;                                       \
                split2((&va.x)[j], (&vb.x)[j], hi_, lo_);                      \
                *(__nv_bfloat162*)(Vth_ + (c4 * 4 + j) * 72 + 2 * p) = hi_;    \
                *(__nv_bfloat162*)(Vtl_ + (c4 * 4 + j) * 72 + 2 * p) = lo_;    \
            }                                                                  \
        }                                                                      \
    }

    LOAD_KV(0, 0);

    for (int kt = 0; kt < nkt; kt++) {
        const int k0 = kt * 64;
        __syncthreads();                       // buf(kt) ready; prev reads done
        if (kt + 1 < nkt) LOAD_KV(kt + 1, (kt + 1) & 1);

        if (k0 > wrow + 15) continue;          // warp-level causal tile skip

        const __nv_bfloat16* Khi = smb + OFF_KV + (kt & 1) * KVBUF;
        const __nv_bfloat16* Klo = Khi + 8704;
        const __nv_bfloat16* Vth = Khi + 17408;
        const __nv_bfloat16* Vtl = Khi + 26624;

        // ---- S = Q K^T ----
        float s[8][4];
#pragma unroll
        for (int nt = 0; nt < 8; nt++)
#pragma unroll
            for (int j = 0; j < 4; j++) s[nt][j] = 0.0f;

        const __nv_bfloat16* qrh = Qhi + (warp * 16 + g) * 136 + 2 * t;
        const __nv_bfloat16* qrl = Qlo + (warp * 16 + g) * 136 + 2 * t;
#pragma unroll
        for (int c = 0; c < 8; c++) {
            uint32_t ah0 = *(const uint32_t*)(qrh + c * 16);
            uint32_t ah1 = *(const uint32_t*)(qrh + 8 * 136 + c * 16);
            uint32_t ah2 = *(const uint32_t*)(qrh + c * 16 + 8);
            uint32_t ah3 = *(const uint32_t*)(qrh + 8 * 136 + c * 16 + 8);
            uint32_t al0 = *(const uint32_t*)(qrl + c * 16);
            uint32_t al1 = *(const uint32_t*)(qrl + 8 * 136 + c * 16);
            uint32_t al2 = *(const uint32_t*)(qrl + c * 16 + 8);
            uint32_t al3 = *(const uint32_t*)(qrl + 8 * 136 + c * 16 + 8);
#pragma unroll
            for (int nt = 0; nt < 8; nt++) {
                const __nv_bfloat16* kp  = Khi + (nt * 8 + g) * 136 + c * 16 + 2 * t;
                const __nv_bfloat16* kpl = Klo + (nt * 8 + g) * 136 + c * 16 + 2 * t;
                uint32_t bh0 = *(const uint32_t*)(kp);
                uint32_t bh1 = *(const uint32_t*)(kp + 8);
                uint32_t bl0 = *(const uint32_t*)(kpl);
                uint32_t bl1 = *(const uint32_t*)(kpl + 8);
                mma_bf16(s[nt], ah0, ah1, ah2, ah3, bh0, bh1);
                mma_bf16(s[nt], ah0, ah1, ah2, ah3, bl0, bl1);
                mma_bf16(s[nt], al0, al1, al2, al3, bh0, bh1);
            }
        }

        // ---- scale + causal mask ----
        if (k0 + 63 > wrow) {
            int r0 = wrow + g, r1 = r0 + 8;
#pragma unroll
            for (int nt = 0; nt < 8; nt++) {
                int c0 = k0 + nt * 8 + 2 * t;
                s[nt][0] = (c0     > r0) ? -1e30f : s[nt][0] * SCALE_F;
                s[nt][1] = (c0 + 1 > r0) ? -1e30f : s[nt][1] * SCALE_F;
                s[nt][2] = (c0     > r1) ? -1e30f : s[nt][2] * SCALE_F;
                s[nt][3] = (c0 + 1 > r1) ? -1e30f : s[nt][3] * SCALE_F;
            }
        } else {
#pragma unroll
            for (int nt = 0; nt < 8; nt++)
#pragma unroll
                for (int j = 0; j < 4; j++) s[nt][j] *= SCALE_F;
        }

        // ---- online softmax ----
        float mx0 = -1e30f, mx1 = -1e30f;
#pragma unroll
        for (int nt = 0; nt < 8; nt++) {
            mx0 = fmaxf(mx0, fmaxf(s[nt][0], s[nt][1]));
            mx1 = fmaxf(mx1, fmaxf(s[nt][2], s[nt][3]));
        }
        mx0 = fmaxf(mx0, __shfl_xor_sync(0xffffffffu, mx0, 1));
        mx0 = fmaxf(mx0, __shfl_xor_sync(0xffffffffu, mx0, 2));
        mx1 = fmaxf(mx1, __shfl_xor_sync(0xffffffffu, mx1, 1));
        mx1 = fmaxf(mx1, __shfl_xor_sync(0xffffffffu, mx1, 2));

        float mn0 = fmaxf(m0, mx0), mn1 = fmaxf(m1, mx1);
        float a0 = __expf(m0 - mn0), a1 = __expf(m1 - mn1);
        m0 = mn0; m1 = mn1;

        float sum0 = 0.0f, sum1 = 0.0f;
#pragma unroll
        for (int nt = 0; nt < 8; nt++) {
            s[nt][0] = __expf(s[nt][0] - m0);
            s[nt][1] = __expf(s[nt][1] - m0);
            s[nt][2] = __expf(s[nt][2] - m1);
            s[nt][3] = __expf(s[nt][3] - m1);
            sum0 += s[nt][0] + s[nt][1];
            sum1 += s[nt][2] + s[nt][3];
        }
        sum0 += __shfl_xor_sync(0xffffffffu, sum0, 1);
        sum0 += __shfl_xor_sync(0xffffffffu, sum0, 2);
        sum1 += __shfl_xor_sync(0xffffffffu, sum1, 1);
        sum1 += __shfl_xor_sync(0xffffffffu, sum1, 2);
        l0 = l0 * a0 + sum0;
        l1 = l1 * a1 + sum1;

#pragma unroll
        for (int nt = 0; nt < 16; nt++) {
            o[nt][0] *= a0; o[nt][1] *= a0;
            o[nt][2] *= a1; o[nt][3] *= a1;
        }

        // ---- O += P V : P fragments straight from S registers ----
#pragma unroll
        for (int c = 0; c < 4; c++) {
            __nv_bfloat162 h0, lo0, h1, lo1, h2, lo2, h3, lo3;
            split2(s[2 * c][0],     s[2 * c][1],     h0, lo0);   // (g,   k=2t)
            split2(s[2 * c][2],     s[2 * c][3],     h1, lo1);   // (g+8, k=2t)
            split2(s[2 * c + 1][0], s[2 * c + 1][1], h2, lo2);   // (g,   k=2t+8)
            split2(s[2 * c + 1][2], s[2 * c + 1][3], h3, lo3);   // (g+8, k=2t+8)
            uint32_t ph0 = b2u(h0), ph1 = b2u(h1), ph2 = b2u(h2), ph3 = b2u(h3);
            uint32_t pl0 = b2u(lo0), pl1 = b2u(lo1), pl2 = b2u(lo2), pl3 = b2u(lo3);
#pragma unroll
            for (int nt = 0; nt < 16; nt++) {
                const __nv_bfloat16* vp  = Vth + (nt * 8 + g) * 72 + c * 16 + 2 * t;
                const __nv_bfloat16* vpl = Vtl + (nt * 8 + g) * 72 + c * 16 + 2 * t;
                uint32_t bh0 = *(const uint32_t*)(vp);
                uint32_t bh1 = *(const uint32_t*)(vp + 8);
                uint32_t bl0 = *(const uint32_t*)(vpl);
                uint32_t bl1 = *(const uint32_t*)(vpl + 8);
                mma_bf16(o[nt], ph0, ph1, ph2, ph3, bh0, bh1);
                mma_bf16(o[nt], ph0, ph1, ph2, ph3, bl0, bl1);
                mma_bf16(o[nt], pl0, pl1, pl2, pl3, bh0, bh1);
            }
        }
    }

    float inv0 = 1.0f / l0, inv1 = 1.0f / l1;
    int row0 = q0 + warp * 16 + g;
#pragma unroll
    for (int nt = 0; nt < 16; nt++) {
        int col = h * HD + nt * 8 + 2 * t;
        *(float2*)&g_attn[(size_t)row0 * D_MODEL + col] =
            make_float2(o[nt][0] * inv0, o[nt][1] * inv0);
        *(float2*)&g_attn[(size_t)(row0 + 8) * D_MODEL + col] =
            make_float2(o[nt][2] * inv1, o[nt][3] * inv1);
    }
#undef LOAD_KV
}

// ---------------------------------------------------------------------------
extern "C" void kernel_launch(void* const* d_in, const int* in_sizes, int n_in,
                              void* d_out, int out_size)
{
    const float* hidden = (const float*)d_in[0];
    const float* cosb   = (const float*)d_in[1];
    const float* sinb   = (const float*)d_in[2];
    const float* Wq = (const float*)d_in[4];
    const float* Wk = (const float*)d_in[5];
    const float* Wv = (const float*)d_in[6];
    const float* Wo = (const float*)d_in[7];
    const float* qw = (const float*)d_in[8];
    const float* kw = (const float*)d_in[9];
    float* out = (float*)d_out;

    cudaFuncSetAttribute(bgemm_qkv, cudaFuncAttributeMaxDynamicSharedMemorySize, BGEMM_SMEM);
    cudaFuncSetAttribute(bgemm_o,   cudaFuncAttributeMaxDynamicSharedMemorySize, BGEMM_SMEM);
    cudaFuncSetAttribute(flash_attn_tc, cudaFuncAttributeMaxDynamicSharedMemorySize, FLASH_SMEM_TC);

    bgemm_qkv<<<768, 256, BGEMM_SMEM>>>(hidden, Wq, Wk, Wv);

    rmsnorm_rope<<<10240, 256>>>(cosb, sinb, qw, kw);

    flash_attn_tc<<<dim3(16, 32), 256, FLASH_SMEM_TC>>>();

    bgemm_o<<<dim3(32, 16), 256, BGEMM_SMEM>>>(Wo, out);
}

// round 7
// speedup vs baseline: 3.9388x; 1.2589x over previous
#include <cuda_runtime.h>
#include <cuda_bf16.h>
#include <cuda_fp16.h>
#include <math.h>
#include <stdint.h>

#define S_LEN   2048
#define D_MODEL 4096
#define NQH     32
#define NKVH    8
#define HD      128
#define KV_DIM  1024
#define SCALE_F 0.08838834764831845f   // 128^-0.5

__device__ float g_q[S_LEN * D_MODEL];
__device__ float g_k[S_LEN * KV_DIM];
__device__ float g_v[S_LEN * KV_DIM];
__device__ float g_attn[S_LEN * D_MODEL];

// ---------------------------------------------------------------------------
// helpers
// ---------------------------------------------------------------------------
__device__ __forceinline__ void mma_bf16(float (&d)[4],
    uint32_t a0, uint32_t a1, uint32_t a2, uint32_t a3,
    uint32_t b0, uint32_t b1) {
    asm volatile(
        "mma.sync.aligned.m16n8k16.row.col.f32.bf16.bf16.f32 "
        "{%0,%1,%2,%3}, {%4,%5,%6,%7}, {%8,%9}, {%0,%1,%2,%3};\n"
        : "+f"(d[0]), "+f"(d[1]), "+f"(d[2]), "+f"(d[3])
        : "r"(a0), "r"(a1), "r"(a2), "r"(a3), "r"(b0), "r"(b1));
}

__device__ __forceinline__ void mma_f16(float (&d)[4],
    uint32_t a0, uint32_t a1, uint32_t a2, uint32_t a3,
    uint32_t b0, uint32_t b1) {
    asm volatile(
        "mma.sync.aligned.m16n8k16.row.col.f32.f16.f16.f32 "
        "{%0,%1,%2,%3}, {%4,%5,%6,%7}, {%8,%9}, {%0,%1,%2,%3};\n"
        : "+f"(d[0]), "+f"(d[1]), "+f"(d[2]), "+f"(d[3])
        : "r"(a0), "r"(a1), "r"(a2), "r"(a3), "r"(b0), "r"(b1));
}

__device__ __forceinline__ void ldsm4(uint32_t (&r)[4], uint32_t addr) {
    asm volatile("ldmatrix.sync.aligned.m8n8.x4.shared.b16 {%0,%1,%2,%3}, [%4];"
        : "=r"(r[0]), "=r"(r[1]), "=r"(r[2]), "=r"(r[3]) : "r"(addr));
}

__device__ __forceinline__ void split2(float x0, float x1,
                                       __nv_bfloat162& hi, __nv_bfloat162& lo) {
    hi = __floats2bfloat162_rn(x0, x1);
    float2 hf = __bfloat1622float2(hi);
    lo = __floats2bfloat162_rn(x0 - hf.x, x1 - hf.y);
}

__device__ __forceinline__ uint32_t b2u(__nv_bfloat162 v) {
    return *reinterpret_cast<uint32_t*>(&v);
}

__device__ __forceinline__ uint32_t h2u(__half2 v) {
    return *reinterpret_cast<uint32_t*>(&v);
}

// ---------------------------------------------------------------------------
// fp16 2-term split GEMM NT: C = A @ B^T, fp32 I/O.
// A = ah + al (two fp16 planes, ~22-bit exact); B = bh (fp16 rounded).
// Error ~ a * (b - bh) ~ 2^-12 relative.
// Block 128x128, BK=32, 256 threads (8 warps, 4m x 2n), warp tile 32x64.
// smem row stride 40 halves; 3 planes per stage (Ah, Al, Bh), 2 stages.
// ---------------------------------------------------------------------------
#define LDB      40
#define PLANE_H  (128 * LDB)            // halves per plane (5120)
#define PLANE_B  (PLANE_H * 2)          // bytes per plane (10240)
#define STAGE_H  (3 * PLANE_H)          // halves per stage
#define STAGE_B  (3 * PLANE_B)          // bytes per stage (30720)
#define HGEMM_SMEM (2 * STAGE_B)        // 61440 B

__device__ __forceinline__ uint2 f4_to_h4(float4 v) {
    return make_uint2(h2u(__floats2half2_rn(v.x, v.y)),
                      h2u(__floats2half2_rn(v.z, v.w)));
}

__device__ __forceinline__ void splitA_sts(float4 v, __half* hi, __half* lo) {
    __half2 h01 = __floats2half2_rn(v.x, v.y);
    __half2 h23 = __floats2half2_rn(v.z, v.w);
    float2 f01 = __half22float2(h01);
    float2 f23 = __half22float2(h23);
    __half2 l01 = __floats2half2_rn(v.x - f01.x, v.y - f01.y);
    __half2 l23 = __floats2half2_rn(v.z - f23.x, v.w - f23.y);
    *(uint2*)hi = make_uint2(h2u(h01), h2u(h23));
    *(uint2*)lo = make_uint2(h2u(l01), h2u(l23));
}

__device__ __forceinline__ void hgemm_body(const float* __restrict__ A,
                                           const float* __restrict__ B,
                                           float* __restrict__ C,
                                           int N, int K, int bx, int by)
{
    extern __shared__ __half smh[];

    const int tid  = threadIdx.x;
    const int warp = tid >> 5;
    const int lane = tid & 31;
    const int g    = lane >> 2;
    const int t    = lane & 3;
    const int wm   = (warp & 3) * 32;
    const int wn   = (warp >> 2) * 64;

    const float* Ab = A + (size_t)by * 128 * K;
    const float* Bb = B + (size_t)bx * 128 * K;

    const int lrow = tid >> 3;
    const int lcol = (tid & 7) * 4;

    const int lane8 = lane & 7;
    const uint32_t smem_u32 = (uint32_t)__cvta_generic_to_shared(smh);
    const uint32_t a_off = ((wm + lane8 + ((lane >> 3) & 1) * 8) * LDB + (lane >> 4) * 8) * 2;
    const uint32_t b_off = ((wn + lane8 + (lane >> 4) * 8) * LDB + ((lane >> 3) & 1) * 8) * 2;

    float4 ra[4], rb[4];
    float acc[2][8][4];
#pragma unroll
    for (int i = 0; i < 2; i++)
#pragma unroll
        for (int j = 0; j < 8; j++)
#pragma unroll
            for (int c = 0; c < 4; c++) acc[i][j][c] = 0.0f;

    const int nk = K / 32;

#define LOADG(KT)                                                              \
    {                                                                          \
        const float* ap_ = Ab + (size_t)lrow * K + (KT) * 32 + lcol;           \
        const float* bp_ = Bb + (size_t)lrow * K + (KT) * 32 + lcol;           \
        ra[0] = *(const float4*)(ap_);                                         \
        ra[1] = *(const float4*)(ap_ + (size_t)32 * K);                        \
        ra[2] = *(const float4*)(ap_ + (size_t)64 * K);                        \
        ra[3] = *(const float4*)(ap_ + (size_t)96 * K);                        \
        rb[0] = *(const float4*)(bp_);                                         \
        rb[1] = *(const float4*)(bp_ + (size_t)32 * K);                        \
        rb[2] = *(const float4*)(bp_ + (size_t)64 * K);                        \
        rb[3] = *(const float4*)(bp_ + (size_t)96 * K);                        \
    }

#define STS(ST)                                                                \
    {                                                                          \
        __half* ah_ = smh + (ST) * STAGE_H;                                    \
        __half* al_ = ah_ + PLANE_H;                                           \
        __half* bh_ = ah_ + 2 * PLANE_H;                                       \
        int off_ = lrow * LDB + lcol;                                          \
        splitA_sts(ra[0], ah_ + off_,            al_ + off_);                  \
        splitA_sts(ra[1], ah_ + off_ + 32 * LDB, al_ + off_ + 32 * LDB);       \
        splitA_sts(ra[2], ah_ + off_ + 64 * LDB, al_ + off_ + 64 * LDB);       \
        splitA_sts(ra[3], ah_ + off_ + 96 * LDB, al_ + off_ + 96 * LDB);       \
        *(uint2*)(bh_ + off_)            = f4_to_h4(rb[0]);                    \
        *(uint2*)(bh_ + off_ + 32 * LDB) = f4_to_h4(rb[1]);                    \
        *(uint2*)(bh_ + off_ + 64 * LDB) = f4_to_h4(rb[2]);                    \
        *(uint2*)(bh_ + off_ + 96 * LDB) = f4_to_h4(rb[3]);                    \
    }

    LOADG(0);
    STS(0);
    if (nk > 1) LOADG(1);
    __syncthreads();

    for (int kt = 0; kt < nk; kt++) {
        const uint32_t sb = smem_u32 + (uint32_t)((kt & 1) * STAGE_B);

#pragma unroll
        for (int k16 = 0; k16 < 2; k16++) {
            uint32_t ah[2][4], al[2][4];
            ldsm4(ah[0], sb + a_off + k16 * 32);
            ldsm4(ah[1], sb + a_off + 16 * LDB * 2 + k16 * 32);
            ldsm4(al[0], sb + PLANE_B + a_off + k16 * 32);
            ldsm4(al[1], sb + PLANE_B + a_off + 16 * LDB * 2 + k16 * 32);

#pragma unroll
            for (int jh = 0; jh < 2; jh++) {
                uint32_t bh[2][4];
#pragma unroll
                for (int jj = 0; jj < 2; jj++) {
                    int j = jh * 2 + jj;
                    ldsm4(bh[jj], sb + 2 * PLANE_B + b_off + j * 16 * LDB * 2 + k16 * 32);
                }
#pragma unroll
                for (int mt = 0; mt < 2; mt++)
#pragma unroll
                    for (int jj = 0; jj < 2; jj++) {
                        int nt = (jh * 2 + jj) * 2;
                        float (&d0)[4] = acc[mt][nt];
                        float (&d1)[4] = acc[mt][nt + 1];
                        mma_f16(d0, al[mt][0], al[mt][1], al[mt][2], al[mt][3],
                                bh[jj][0], bh[jj][1]);
                        mma_f16(d0, ah[mt][0], ah[mt][1], ah[mt][2], ah[mt][3],
                                bh[jj][0], bh[jj][1]);
                        mma_f16(d1, al[mt][0], al[mt][1], al[mt][2], al[mt][3],
                                bh[jj][2], bh[jj][3]);
                        mma_f16(d1, ah[mt][0], ah[mt][1], ah[mt][2], ah[mt][3],
                                bh[jj][2], bh[jj][3]);
                    }
            }
        }

        if (kt + 1 < nk) {
            STS((kt + 1) & 1);
            __syncthreads();
            if (kt + 2 < nk) LOADG(kt + 2);
        }
    }

#pragma unroll
    for (int mt = 0; mt < 2; mt++) {
        int r0 = by * 128 + wm + mt * 16 + g;
#pragma unroll
        for (int nt = 0; nt < 8; nt++) {
            int c0 = bx * 128 + wn + nt * 8 + 2 * t;
            *(float2*)&C[(size_t)r0 * N + c0] =
                make_float2(acc[mt][nt][0], acc[mt][nt][1]);
            *(float2*)&C[(size_t)(r0 + 8) * N + c0] =
                make_float2(acc[mt][nt][2], acc[mt][nt][3]);
        }
    }
#undef LOADG
#undef STS
}

// merged Q/K/V projection launch: 768 CTAs (512 Q + 128 K + 128 V)
__global__ __launch_bounds__(256, 2)
void hgemm_qkv(const float* __restrict__ H, const float* __restrict__ Wq,
               const float* __restrict__ Wk, const float* __restrict__ Wv)
{
    int b = blockIdx.x;
    if (b < 512)      hgemm_body(H, Wq, g_q, 4096, 4096, b & 31, b >> 5);
    else if (b < 640) { int i = b - 512; hgemm_body(H, Wk, g_k, 1024, 4096, i & 7, i >> 3); }
    else              { int i = b - 640; hgemm_body(H, Wv, g_v, 1024, 4096, i & 7, i >> 3); }
}

__global__ __launch_bounds__(256, 2)
void hgemm_o(const float* __restrict__ Wo, float* __restrict__ out)
{
    hgemm_body(g_attn, Wo, out, 4096, 4096, blockIdx.x, blockIdx.y);
}

// ---------------------------------------------------------------------------
// Fused per-head RMSNorm + RoPE (unchanged)
// ---------------------------------------------------------------------------
__global__ __launch_bounds__(256)
void rmsnorm_rope(const float* __restrict__ cosb, const float* __restrict__ sinb,
                  const float* __restrict__ qw, const float* __restrict__ kw)
{
    const int warp = blockIdx.x * 8 + (threadIdx.x >> 5);
    const int lane = threadIdx.x & 31;

    float* base;
    const float* w;
    int s;
    if (warp < S_LEN * NQH) {
        s = warp / NQH;
        int h = warp - s * NQH;
        base = g_q + (size_t)s * D_MODEL + h * HD;
        w = qw;
    } else {
        int wv = warp - S_LEN * NQH;
        s = wv / NKVH;
        int h = wv - s * NKVH;
        base = g_k + (size_t)s * KV_DIM + h * HD;
        w = kw;
    }

    float x0 = base[lane];
    float x1 = base[lane + 32];
    float x2 = base[lane + 64];
    float x3 = base[lane + 96];

    float ss = x0 * x0 + x1 * x1 + x2 * x2 + x3 * x3;
#pragma unroll
    for (int o = 16; o; o >>= 1) ss += __shfl_xor_sync(0xffffffffu, ss, o);
    float inv = rsqrtf(ss * (1.0f / 128.0f) + 1e-6f);

    float n0 = w[lane]      * x0 * inv;
    float n1 = w[lane + 32] * x1 * inv;
    float n2 = w[lane + 64] * x2 * inv;
    float n3 = w[lane + 96] * x3 * inv;

    const float c0 = cosb[s * 64 + lane];
    const float c1 = cosb[s * 64 + lane + 32];
    const float s0 = sinb[s * 64 + lane];
    const float s1 = sinb[s * 64 + lane + 32];

    base[lane]      = n0 * c0 - n2 * s0;
    base[lane + 32] = n1 * c1 - n3 * s1;
    base[lane + 64] = n2 * c0 + n0 * s0;
    base[lane + 96] = n3 * c1 + n1 * s1;
}

// ---------------------------------------------------------------------------
// Tensor-core flash attention (unchanged from R5: bf16 3-term, double-buffered
// K/V, register-direct P fragments)
// ---------------------------------------------------------------------------
#define OFF_QHI  0
#define OFF_QLO  17408
#define OFF_KV   34816
#define KVBUF    35840
#define FLASH_SMEM_TC ((OFF_KV + 2 * KVBUF) * 2)   // 212992 B

__global__ __launch_bounds__(256, 1)
void flash_attn_tc()
{
    extern __shared__ __nv_bfloat16 smb[];
    __nv_bfloat16* Qhi = smb + OFF_QHI;
    __nv_bfloat16* Qlo = smb + OFF_QLO;

    const int qt  = 15 - blockIdx.x;
    const int h   = blockIdx.y;
    const int q0  = qt * 128;
    const int kvh = h >> 2;
    const int tid  = threadIdx.x;
    const int warp = tid >> 5;
    const int lane = tid & 31;
    const int g = lane >> 2;
    const int t = lane & 3;

    for (int i = tid; i < 128 * 32; i += 256) {
        int r = i >> 5, c = (i & 31) << 2;
        float4 v = *(const float4*)&g_q[(size_t)(q0 + r) * D_MODEL + h * HD + c];
        __nv_bfloat162 h01, l01, h23, l23;
        split2(v.x, v.y, h01, l01);
        split2(v.z, v.w, h23, l23);
        *(__nv_bfloat162*)(Qhi + r * 136 + c)     = h01;
        *(__nv_bfloat162*)(Qhi + r * 136 + c + 2) = h23;
        *(__nv_bfloat162*)(Qlo + r * 136 + c)     = l01;
        *(__nv_bfloat162*)(Qlo + r * 136 + c + 2) = l23;
    }

    float o[16][4];
#pragma unroll
    for (int nt = 0; nt < 16; nt++)
#pragma unroll
        for (int j = 0; j < 4; j++) o[nt][j] = 0.0f;
    float m0 = -1e30f, m1 = -1e30f, l0 = 0.0f, l1 = 0.0f;

    const int wrow = q0 + warp * 16;
    const int nkt  = 2 * qt + 2;

#define LOAD_KV(KT, BUF)                                                       \
    {                                                                          \
        __nv_bfloat16* Khi_ = smb + OFF_KV + (BUF) * KVBUF;                    \
        __nv_bfloat16* Klo_ = Khi_ + 8704;                                     \
        __nv_bfloat16* Vth_ = Khi_ + 17408;                                    \
        __nv_bfloat16* Vtl_ = Khi_ + 26624;                                    \
        const int k0_ = (KT) * 64;                                             \
        for (int i = tid; i < 64 * 32; i += 256) {                             \
            int r = i >> 5, c = (i & 31) << 2;                                 \
            float4 v = *(const float4*)&g_k[(size_t)(k0_ + r) * KV_DIM + kvh * HD + c]; \
            __nv_bfloat162 h01, l01, h23, l23;                                 \
            split2(v.x, v.y, h01, l01);                                        \
            split2(v.z, v.w, h23, l23);                                        \
            *(__nv_bfloat162*)(Khi_ + r * 136 + c)     = h01;                  \
            *(__nv_bfloat162*)(Khi_ + r * 136 + c + 2) = h23;                  \
            *(__nv_bfloat162*)(Klo_ + r * 136 + c)     = l01;                  \
            *(__nv_bfloat162*)(Klo_ + r * 136 + c + 2) = l23;                  \
        }                                                                      \
        for (int u = tid; u < 1024; u += 256) {                                \
            int p = u & 31, c4 = u >> 5;                                       \
            const float* vp_ = &g_v[(size_t)(k0_ + 2 * p) * KV_DIM + kvh * HD + c4 * 4]; \
            float4 va = *(const float4*)vp_;                                   \
            float4 vb = *(const float4*)(vp_ + KV_DIM);                        \
            _Pragma("unroll")                                                  \
            for (int j = 0; j < 4; j++) {                                      \
                __nv_bfloat162 hi_, lo_;                                       \
                split2((&va.x)[j], (&vb.x)[j], hi_, lo_);                      \
                *(__nv_bfloat162*)(Vth_ + (c4 * 4 + j) * 72 + 2 * p) = hi_;    \
                *(__nv_bfloat162*)(Vtl_ + (c4 * 4 + j) * 72 + 2 * p) = lo_;    \
            }                                                                  \
        }                                                                      \
    }

    LOAD_KV(0, 0);

    for (int kt = 0; kt < nkt; kt++) {
        const int k0 = kt * 64;
        __syncthreads();
        if (kt + 1 < nkt) LOAD_KV(kt + 1, (kt + 1) & 1);

        if (k0 > wrow + 15) continue;

        const __nv_bfloat16* Khi = smb + OFF_KV + (kt & 1) * KVBUF;
        const __nv_bfloat16* Klo = Khi + 8704;
        const __nv_bfloat16* Vth = Khi + 17408;
        const __nv_bfloat16* Vtl = Khi + 26624;

        float s[8][4];
#pragma unroll
        for (int nt = 0; nt < 8; nt++)
#pragma unroll
            for (int j = 0; j < 4; j++) s[nt][j] = 0.0f;

        const __nv_bfloat16* qrh = Qhi + (warp * 16 + g) * 136 + 2 * t;
        const __nv_bfloat16* qrl = Qlo + (warp * 16 + g) * 136 + 2 * t;
#pragma unroll
        for (int c = 0; c < 8; c++) {
            uint32_t ah0 = *(const uint32_t*)(qrh + c * 16);
            uint32_t ah1 = *(const uint32_t*)(qrh + 8 * 136 + c * 16);
            uint32_t ah2 = *(const uint32_t*)(qrh + c * 16 + 8);
            uint32_t ah3 = *(const uint32_t*)(qrh + 8 * 136 + c * 16 + 8);
            uint32_t al0 = *(const uint32_t*)(qrl + c * 16);
            uint32_t al1 = *(const uint32_t*)(qrl + 8 * 136 + c * 16);
            uint32_t al2 = *(const uint32_t*)(qrl + c * 16 + 8);
            uint32_t al3 = *(const uint32_t*)(qrl + 8 * 136 + c * 16 + 8);
#pragma unroll
            for (int nt = 0; nt < 8; nt++) {
                const __nv_bfloat16* kp  = Khi + (nt * 8 + g) * 136 + c * 16 + 2 * t;
                const __nv_bfloat16* kpl = Klo + (nt * 8 + g) * 136 + c * 16 + 2 * t;
                uint32_t bh0 = *(const uint32_t*)(kp);
                uint32_t bh1 = *(const uint32_t*)(kp + 8);
                uint32_t bl0 = *(const uint32_t*)(kpl);
                uint32_t bl1 = *(const uint32_t*)(kpl + 8);
                mma_bf16(s[nt], ah0, ah1, ah2, ah3, bh0, bh1);
                mma_bf16(s[nt], ah0, ah1, ah2, ah3, bl0, bl1);
                mma_bf16(s[nt], al0, al1, al2, al3, bh0, bh1);
            }
        }

        if (k0 + 63 > wrow) {
            int r0 = wrow + g, r1 = r0 + 8;
#pragma unroll
            for (int nt = 0; nt < 8; nt++) {
                int c0 = k0 + nt * 8 + 2 * t;
                s[nt][0] = (c0     > r0) ? -1e30f : s[nt][0] * SCALE_F;
                s[nt][1] = (c0 + 1 > r0) ? -1e30f : s[nt][1] * SCALE_F;
                s[nt][2] = (c0     > r1) ? -1e30f : s[nt][2] * SCALE_F;
                s[nt][3] = (c0 + 1 > r1) ? -1e30f : s[nt][3] * SCALE_F;
            }
        } else {
#pragma unroll
            for (int nt = 0; nt < 8; nt++)
#pragma unroll
                for (int j = 0; j < 4; j++) s[nt][j] *= SCALE_F;
        }

        float mx0 = -1e30f, mx1 = -1e30f;
#pragma unroll
        for (int nt = 0; nt < 8; nt++) {
            mx0 = fmaxf(mx0, fmaxf(s[nt][0], s[nt][1]));
            mx1 = fmaxf(mx1, fmaxf(s[nt][2], s[nt][3]));
        }
        mx0 = fmaxf(mx0, __shfl_xor_sync(0xffffffffu, mx0, 1));
        mx0 = fmaxf(mx0, __shfl_xor_sync(0xffffffffu, mx0, 2));
        mx1 = fmaxf(mx1, __shfl_xor_sync(0xffffffffu, mx1, 1));
        mx1 = fmaxf(mx1, __shfl_xor_sync(0xffffffffu, mx1, 2));

        float mn0 = fmaxf(m0, mx0), mn1 = fmaxf(m1, mx1);
        float a0 = __expf(m0 - mn0), a1 = __expf(m1 - mn1);
        m0 = mn0; m1 = mn1;

        float sum0 = 0.0f, sum1 = 0.0f;
#pragma unroll
        for (int nt = 0; nt < 8; nt++) {
            s[nt][0] = __expf(s[nt][0] - m0);
            s[nt][1] = __expf(s[nt][1] - m0);
            s[nt][2] = __expf(s[nt][2] - m1);
            s[nt][3] = __expf(s[nt][3] - m1);
            sum0 += s[nt][0] + s[nt][1];
            sum1 += s[nt][2] + s[nt][3];
        }
        sum0 += __shfl_xor_sync(0xffffffffu, sum0, 1);
        sum0 += __shfl_xor_sync(0xffffffffu, sum0, 2);
        sum1 += __shfl_xor_sync(0xffffffffu, sum1, 1);
        sum1 += __shfl_xor_sync(0xffffffffu, sum1, 2);
        l0 = l0 * a0 + sum0;
        l1 = l1 * a1 + sum1;

#pragma unroll
        for (int nt = 0; nt < 16; nt++) {
            o[nt][0] *= a0; o[nt][1] *= a0;
            o[nt][2] *= a1; o[nt][3] *= a1;
        }

#pragma unroll
        for (int c = 0; c < 4; c++) {
            __nv_bfloat162 h0, lo0, h1, lo1, h2, lo2, h3, lo3;
            split2(s[2 * c][0],     s[2 * c][1],     h0, lo0);
            split2(s[2 * c][2],     s[2 * c][3],     h1, lo1);
            split2(s[2 * c + 1][0], s[2 * c + 1][1], h2, lo2);
            split2(s[2 * c + 1][2], s[2 * c + 1][3], h3, lo3);
            uint32_t ph0 = b2u(h0), ph1 = b2u(h1), ph2 = b2u(h2), ph3 = b2u(h3);
            uint32_t pl0 = b2u(lo0), pl1 = b2u(lo1), pl2 = b2u(lo2), pl3 = b2u(lo3);
#pragma unroll
            for (int nt = 0; nt < 16; nt++) {
                const __nv_bfloat16* vp  = Vth + (nt * 8 + g) * 72 + c * 16 + 2 * t;
                const __nv_bfloat16* vpl = Vtl + (nt * 8 + g) * 72 + c * 16 + 2 * t;
                uint32_t bh0 = *(const uint32_t*)(vp);
                uint32_t bh1 = *(const uint32_t*)(vp + 8);
                uint32_t bl0 = *(const uint32_t*)(vpl);
                uint32_t bl1 = *(const uint32_t*)(vpl + 8);
                mma_bf16(o[nt], ph0, ph1, ph2, ph3, bh0, bh1);
                mma_bf16(o[nt], ph0, ph1, ph2, ph3, bl0, bl1);
                mma_bf16(o[nt], pl0, pl1, pl2, pl3, bh0, bh1);
            }
        }
    }

    float inv0 = 1.0f / l0, inv1 = 1.0f / l1;
    int row0 = q0 + warp * 16 + g;
#pragma unroll
    for (int nt = 0; nt < 16; nt++) {
        int col = h * HD + nt * 8 + 2 * t;
        *(float2*)&g_attn[(size_t)row0 * D_MODEL + col] =
            make_float2(o[nt][0] * inv0, o[nt][1] * inv0);
        *(float2*)&g_attn[(size_t)(row0 + 8) * D_MODEL + col] =
            make_float2(o[nt][2] * inv1, o[nt][3] * inv1);
    }
#undef LOAD_KV
}

// ---------------------------------------------------------------------------
extern "C" void kernel_launch(void* const* d_in, const int* in_sizes, int n_in,
                              void* d_out, int out_size)
{
    const float* hidden = (const float*)d_in[0];
    const float* cosb   = (const float*)d_in[1];
    const float* sinb   = (const float*)d_in[2];
    const float* Wq = (const float*)d_in[4];
    const float* Wk = (const float*)d_in[5];
    const float* Wv = (const float*)d_in[6];
    const float* Wo = (const float*)d_in[7];
    const float* qw = (const float*)d_in[8];
    const float* kw = (const float*)d_in[9];
    float* out = (float*)d_out;

    cudaFuncSetAttribute(hgemm_qkv, cudaFuncAttributeMaxDynamicSharedMemorySize, HGEMM_SMEM);
    cudaFuncSetAttribute(hgemm_o,   cudaFuncAttributeMaxDynamicSharedMemorySize, HGEMM_SMEM);
    cudaFuncSetAttribute(flash_attn_tc, cudaFuncAttributeMaxDynamicSharedMemorySize, FLASH_SMEM_TC);

    hgemm_qkv<<<768, 256, HGEMM_SMEM>>>(hidden, Wq, Wk, Wv);

    rmsnorm_rope<<<10240, 256>>>(cosb, sinb, qw, kw);

    flash_attn_tc<<<dim3(16, 32), 256, FLASH_SMEM_TC>>>();

    hgemm_o<<<dim3(32, 16), 256, HGEMM_SMEM>>>(Wo, out);
}

// round 8
// speedup vs baseline: 3.9919x; 1.0135x over previous
#include <cuda_runtime.h>
#include <cuda_bf16.h>
#include <cuda_fp16.h>
#include <math.h>
#include <stdint.h>

#define S_LEN   2048
#define D_MODEL 4096
#define NQH     32
#define NKVH    8
#define HD      128
#define KV_DIM  1024
#define SCALE_F 0.08838834764831845f   // 128^-0.5

// fp32 QKV outputs (flash consumes fp32)
__device__ float g_q[S_LEN * D_MODEL];
__device__ float g_k[S_LEN * KV_DIM];
__device__ float g_v[S_LEN * KV_DIM];
// fp16 split planes
__device__ __half g_hh[S_LEN * D_MODEL];   // hidden hi
__device__ __half g_hl[S_LEN * D_MODEL];   // hidden lo
__device__ __half g_wqh[D_MODEL * D_MODEL];
__device__ __half g_wkh[KV_DIM * D_MODEL];
__device__ __half g_wvh[KV_DIM * D_MODEL];
__device__ __half g_woh[D_MODEL * D_MODEL];
__device__ __half g_ah[S_LEN * D_MODEL];   // attn out hi
__device__ __half g_al[S_LEN * D_MODEL];   // attn out lo

// ---------------------------------------------------------------------------
// helpers
// ---------------------------------------------------------------------------
__device__ __forceinline__ void mma_bf16(float (&d)[4],
    uint32_t a0, uint32_t a1, uint32_t a2, uint32_t a3,
    uint32_t b0, uint32_t b1) {
    asm volatile(
        "mma.sync.aligned.m16n8k16.row.col.f32.bf16.bf16.f32 "
        "{%0,%1,%2,%3}, {%4,%5,%6,%7}, {%8,%9}, {%0,%1,%2,%3};\n"
        : "+f"(d[0]), "+f"(d[1]), "+f"(d[2]), "+f"(d[3])
        : "r"(a0), "r"(a1), "r"(a2), "r"(a3), "r"(b0), "r"(b1));
}

__device__ __forceinline__ void mma_f16(float (&d)[4],
    uint32_t a0, uint32_t a1, uint32_t a2, uint32_t a3,
    uint32_t b0, uint32_t b1) {
    asm volatile(
        "mma.sync.aligned.m16n8k16.row.col.f32.f16.f16.f32 "
        "{%0,%1,%2,%3}, {%4,%5,%6,%7}, {%8,%9}, {%0,%1,%2,%3};\n"
        : "+f"(d[0]), "+f"(d[1]), "+f"(d[2]), "+f"(d[3])
        : "r"(a0), "r"(a1), "r"(a2), "r"(a3), "r"(b0), "r"(b1));
}

__device__ __forceinline__ void ldsm4(uint32_t (&r)[4], uint32_t addr) {
    asm volatile("ldmatrix.sync.aligned.m8n8.x4.shared.b16 {%0,%1,%2,%3}, [%4];"
        : "=r"(r[0]), "=r"(r[1]), "=r"(r[2]), "=r"(r[3]) : "r"(addr));
}

__device__ __forceinline__ void split2(float x0, float x1,
                                       __nv_bfloat162& hi, __nv_bfloat162& lo) {
    hi = __floats2bfloat162_rn(x0, x1);
    float2 hf = __bfloat1622float2(hi);
    lo = __floats2bfloat162_rn(x0 - hf.x, x1 - hf.y);
}

__device__ __forceinline__ uint32_t b2u(__nv_bfloat162 v) {
    return *reinterpret_cast<uint32_t*>(&v);
}
__device__ __forceinline__ uint32_t h2u(__half2 v) {
    return *reinterpret_cast<uint32_t*>(&v);
}

// ---------------------------------------------------------------------------
// pre-pass: fp32 -> fp16 hi (+ optional lo residual) planes, vectorized
// ---------------------------------------------------------------------------
__global__ __launch_bounds__(256)
void split_conv(const float4* __restrict__ src, uint2* __restrict__ hi,
                uint2* __restrict__ lo, int n4)
{
    int stride = gridDim.x * blockDim.x;
    for (int i = blockIdx.x * blockDim.x + threadIdx.x; i < n4; i += stride) {
        float4 v = src[i];
        __half2 h01 = __floats2half2_rn(v.x, v.y);
        __half2 h23 = __floats2half2_rn(v.z, v.w);
        hi[i] = make_uint2(h2u(h01), h2u(h23));
        if (lo) {
            float2 f01 = __half22float2(h01);
            float2 f23 = __half22float2(h23);
            lo[i] = make_uint2(
                h2u(__floats2half2_rn(v.x - f01.x, v.y - f01.y)),
                h2u(__floats2half2_rn(v.z - f23.x, v.w - f23.y)));
        }
    }
}

// ---------------------------------------------------------------------------
// fp16 2-term GEMM NT with cp.async: C = (Ah+Al) @ Bh^T, fp32 out.
// CTA tile 256x128, BK=32, 256 threads, 8 warps (4m x 2n), warp tile 64x64.
// 3-stage cp.async pipeline; smem stride 40 halves (LDSM-conflict-free).
// ---------------------------------------------------------------------------
#define LDBH   40
#define AP_H   (256 * LDBH)              // halves per A plane (10240)
#define BP_H   (128 * LDBH)              // halves per B plane (5120)
#define STG_B  ((2 * AP_H + BP_H) * 2)   // bytes per stage (51200)
#define HGEMM_SMEM (3 * STG_B)           // 153600

__device__ __forceinline__ void hgemm_body(const __half* __restrict__ Ah,
                                           const __half* __restrict__ Al,
                                           const __half* __restrict__ Bh,
                                           float* __restrict__ C,
                                           int N, int K, int bx, int by)
{
    extern __shared__ char smc[];
    const uint32_t smem_u32 = (uint32_t)__cvta_generic_to_shared(smc);

    const int tid  = threadIdx.x;
    const int warp = tid >> 5;
    const int lane = tid & 31;
    const int g    = lane >> 2;
    const int t    = lane & 3;
    const int wm   = (warp & 3) * 64;
    const int wn   = (warp >> 2) * 64;

    // ---- loader chunk descriptors (10 x 16B per thread per stage) ----
    uint32_t dst_off[10];
    const __half* src[10];
#pragma unroll
    for (int j = 0; j < 10; j++) {
        int cid = tid + j * 256;
        if (cid < 2048) {
            int plane = cid >> 10;
            int r = (cid & 1023) >> 2;
            int c = cid & 3;
            dst_off[j] = (uint32_t)(plane * AP_H + r * LDBH + c * 8) * 2;
            src[j] = (plane ? Al : Ah) + (size_t)(by * 256 + r) * K + c * 8;
        } else {
            int b = cid - 2048;
            int r = b >> 2, c = b & 3;
            dst_off[j] = (uint32_t)(2 * AP_H + r * LDBH + c * 8) * 2;
            src[j] = Bh + (size_t)(bx * 128 + r) * K + c * 8;
        }
    }

    // ---- ldmatrix offsets (bytes within stage) ----
    const int lane8 = lane & 7;
    const uint32_t a_off = (uint32_t)(((wm + lane8 + ((lane >> 3) & 1) * 8) * LDBH
                                      + (lane >> 4) * 8) * 2);
    const uint32_t b_off = (uint32_t)((2 * AP_H + (wn + lane8 + (lane >> 4) * 8) * LDBH
                                      + ((lane >> 3) & 1) * 8) * 2);

    float acc[4][8][4];
#pragma unroll
    for (int mt = 0; mt < 4; mt++)
#pragma unroll
        for (int nt = 0; nt < 8; nt++)
#pragma unroll
            for (int c = 0; c < 4; c++) acc[mt][nt][c] = 0.0f;

    const int nk = K / 32;

#define CP_ISSUE(KT)                                                           \
    {                                                                          \
        uint32_t sb_ = smem_u32 + (uint32_t)(((KT) % 3) * STG_B);              \
        _Pragma("unroll")                                                      \
        for (int j = 0; j < 10; j++) {                                         \
            asm volatile("cp.async.cg.shared.global [%0], [%1], 16;"           \
                :: "r"(sb_ + dst_off[j]), "l"(src[j] + (KT) * 32) : "memory"); \
        }                                                                      \
    }
#define CP_COMMIT() asm volatile("cp.async.commit_group;" ::: "memory")

    CP_ISSUE(0); CP_COMMIT();
    CP_ISSUE(1); CP_COMMIT();

    for (int kt = 0; kt < nk; kt++) {
        asm volatile("cp.async.wait_group 1;" ::: "memory");
        __syncthreads();

        const uint32_t sb = smem_u32 + (uint32_t)((kt % 3) * STG_B);

#pragma unroll
        for (int k16 = 0; k16 < 2; k16++) {
            uint32_t bh[4][4];
#pragma unroll
            for (int j = 0; j < 4; j++)
                ldsm4(bh[j], sb + b_off + j * 16 * LDBH * 2 + k16 * 32);

#pragma unroll
            for (int mt = 0; mt < 4; mt++) {
                uint32_t ah[4], al[4];
                ldsm4(ah, sb + a_off + mt * 16 * LDBH * 2 + k16 * 32);
                ldsm4(al, sb + AP_H * 2 + a_off + mt * 16 * LDBH * 2 + k16 * 32);
#pragma unroll
                for (int j = 0; j < 4; j++) {
                    float (&d0)[4] = acc[mt][2 * j];
                    float (&d1)[4] = acc[mt][2 * j + 1];
                    mma_f16(d0, al[0], al[1], al[2], al[3], bh[j][0], bh[j][1]);
                    mma_f16(d0, ah[0], ah[1], ah[2], ah[3], bh[j][0], bh[j][1]);
                    mma_f16(d1, al[0], al[1], al[2], al[3], bh[j][2], bh[j][3]);
                    mma_f16(d1, ah[0], ah[1], ah[2], ah[3], bh[j][2], bh[j][3]);
                }
            }
        }

        if (kt + 2 < nk) { CP_ISSUE(kt + 2); }
        CP_COMMIT();   // always commit (keeps wait_group accounting aligned)
    }

    // ---- epilogue ----
#pragma unroll
    for (int mt = 0; mt < 4; mt++) {
        int r0 = by * 256 + wm + mt * 16 + g;
#pragma unroll
        for (int nt = 0; nt < 8; nt++) {
            int c0 = bx * 128 + wn + nt * 8 + 2 * t;
            *(float2*)&C[(size_t)r0 * N + c0] =
                make_float2(acc[mt][nt][0], acc[mt][nt][1]);
            *(float2*)&C[(size_t)(r0 + 8) * N + c0] =
                make_float2(acc[mt][nt][2], acc[mt][nt][3]);
        }
    }
#undef CP_ISSUE
#undef CP_COMMIT
}

// merged Q/K/V projection: 384 CTAs (256 Q + 64 K + 64 V)
__global__ __launch_bounds__(256, 1)
void hgemm_qkv()
{
    int b = blockIdx.x;
    if (b < 256)      hgemm_body(g_hh, g_hl, g_wqh, g_q, 4096, 4096, b & 31, b >> 5);
    else if (b < 320) { int i = b - 256; hgemm_body(g_hh, g_hl, g_wkh, g_k, 1024, 4096, i & 7, i >> 3); }
    else              { int i = b - 320; hgemm_body(g_hh, g_hl, g_wvh, g_v, 1024, 4096, i & 7, i >> 3); }
}

__global__ __launch_bounds__(256, 1)
void hgemm_o(float* __restrict__ out)
{
    hgemm_body(g_ah, g_al, g_woh, out, 4096, 4096, blockIdx.x, blockIdx.y);
}

// ---------------------------------------------------------------------------
// Fused per-head RMSNorm + RoPE (unchanged)
// ---------------------------------------------------------------------------
__global__ __launch_bounds__(256)
void rmsnorm_rope(const float* __restrict__ cosb, const float* __restrict__ sinb,
                  const float* __restrict__ qw, const float* __restrict__ kw)
{
    const int warp = blockIdx.x * 8 + (threadIdx.x >> 5);
    const int lane = threadIdx.x & 31;

    float* base;
    const float* w;
    int s;
    if (warp < S_LEN * NQH) {
        s = warp / NQH;
        int h = warp - s * NQH;
        base = g_q + (size_t)s * D_MODEL + h * HD;
        w = qw;
    } else {
        int wv = warp - S_LEN * NQH;
        s = wv / NKVH;
        int h = wv - s * NKVH;
        base = g_k + (size_t)s * KV_DIM + h * HD;
        w = kw;
    }

    float x0 = base[lane];
    float x1 = base[lane + 32];
    float x2 = base[lane + 64];
    float x3 = base[lane + 96];

    float ss = x0 * x0 + x1 * x1 + x2 * x2 + x3 * x3;
#pragma unroll
    for (int o = 16; o; o >>= 1) ss += __shfl_xor_sync(0xffffffffu, ss, o);
    float inv = rsqrtf(ss * (1.0f / 128.0f) + 1e-6f);

    float n0 = w[lane]      * x0 * inv;
    float n1 = w[lane + 32] * x1 * inv;
    float n2 = w[lane + 64] * x2 * inv;
    float n3 = w[lane + 96] * x3 * inv;

    const float c0 = cosb[s * 64 + lane];
    const float c1 = cosb[s * 64 + lane + 32];
    const float s0 = sinb[s * 64 + lane];
    const float s1 = sinb[s * 64 + lane + 32];

    base[lane]      = n0 * c0 - n2 * s0;
    base[lane + 32] = n1 * c1 - n3 * s1;
    base[lane + 64] = n2 * c0 + n0 * s0;
    base[lane + 96] = n3 * c1 + n1 * s1;
}

// ---------------------------------------------------------------------------
// Tensor-core flash attention (R5 core; epilogue writes fp16 hi/lo planes)
// ---------------------------------------------------------------------------
#define OFF_QHI  0
#define OFF_QLO  17408
#define OFF_KV   34816
#define KVBUF    35840
#define FLASH_SMEM_TC ((OFF_KV + 2 * KVBUF) * 2)   // 212992 B

__global__ __launch_bounds__(256, 1)
void flash_attn_tc()
{
    extern __shared__ __nv_bfloat16 smb[];
    __nv_bfloat16* Qhi = smb + OFF_QHI;
    __nv_bfloat16* Qlo = smb + OFF_QLO;

    const int qt  = 15 - blockIdx.x;
    const int h   = blockIdx.y;
    const int q0  = qt * 128;
    const int kvh = h >> 2;
    const int tid  = threadIdx.x;
    const int warp = tid >> 5;
    const int lane = tid & 31;
    const int g = lane >> 2;
    const int t = lane & 3;

    for (int i = tid; i < 128 * 32; i += 256) {
        int r = i >> 5, c = (i & 31) << 2;
        float4 v = *(const float4*)&g_q[(size_t)(q0 + r) * D_MODEL + h * HD + c];
        __nv_bfloat162 h01, l01, h23, l23;
        split2(v.x, v.y, h01, l01);
        split2(v.z, v.w, h23, l23);
        *(__nv_bfloat162*)(Qhi + r * 136 + c)     = h01;
        *(__nv_bfloat162*)(Qhi + r * 136 + c + 2) = h23;
        *(__nv_bfloat162*)(Qlo + r * 136 + c)     = l01;
        *(__nv_bfloat162*)(Qlo + r * 136 + c + 2) = l23;
    }

    float o[16][4];
#pragma unroll
    for (int nt = 0; nt < 16; nt++)
#pragma unroll
        for (int j = 0; j < 4; j++) o[nt][j] = 0.0f;
    float m0 = -1e30f, m1 = -1e30f, l0 = 0.0f, l1 = 0.0f;

    const int wrow = q0 + warp * 16;
    const int nkt  = 2 * qt + 2;

#define LOAD_KV(KT, BUF)                                                       \
    {                                                                          \
        __nv_bfloat16* Khi_ = smb + OFF_KV + (BUF) * KVBUF;                    \
        __nv_bfloat16* Klo_ = Khi_ + 8704;                                     \
        __nv_bfloat16* Vth_ = Khi_ + 17408;                                    \
        __nv_bfloat16* Vtl_ = Khi_ + 26624;                                    \
        const int k0_ = (KT) * 64;                                             \
        for (int i = tid; i < 64 * 32; i += 256) {                             \
            int r = i >> 5, c = (i & 31) << 2;                                 \
            float4 v = *(const float4*)&g_k[(size_t)(k0_ + r) * KV_DIM + kvh * HD + c]; \
            __nv_bfloat162 h01, l01, h23, l23;                                 \
            split2(v.x, v.y, h01, l01);                                        \
            split2(v.z, v.w, h23, l23);                                        \
            *(__nv_bfloat162*)(Khi_ + r * 136 + c)     = h01;                  \
            *(__nv_bfloat162*)(Khi_ + r * 136 + c + 2) = h23;                  \
            *(__nv_bfloat162*)(Klo_ + r * 136 + c)     = l01;                  \
            *(__nv_bfloat162*)(Klo_ + r * 136 + c + 2) = l23;                  \
        }                                                                      \
        for (int u = tid; u < 1024; u += 256) {                                \
            int p = u & 31, c4 = u >> 5;                                       \
            const float* vp_ = &g_v[(size_t)(k0_ + 2 * p) * KV_DIM + kvh * HD + c4 * 4]; \
            float4 va = *(const float4*)vp_;                                   \
            float4 vb = *(const float4*)(vp_ + KV_DIM);                        \
            _Pragma("unroll")                                                  \
            for (int j = 0; j < 4; j++) {                                      \
                __nv_bfloat162 hi_, lo_;                                       \
                split2((&va.x)[j], (&vb.x)[j], hi_, lo_);                      \
                *(__nv_bfloat162*)(Vth_ + (c4 * 4 + j) * 72 + 2 * p) = hi_;    \
                *(__nv_bfloat162*)(Vtl_ + (c4 * 4 + j) * 72 + 2 * p) = lo_;    \
            }                                                                  \
        }                                                                      \
    }

    LOAD_KV(0, 0);

    for (int kt = 0; kt < nkt; kt++) {
        const int k0 = kt * 64;
        __syncthreads();
        if (kt + 1 < nkt) LOAD_KV(kt + 1, (kt + 1) & 1);

        if (k0 > wrow + 15) continue;

        const __nv_bfloat16* Khi = smb + OFF_KV + (kt & 1) * KVBUF;
        const __nv_bfloat16* Klo = Khi + 8704;
        const __nv_bfloat16* Vth = Khi + 17408;
        const __nv_bfloat16* Vtl = Khi + 26624;

        float s[8][4];
#pragma unroll
        for (int nt = 0; nt < 8; nt++)
#pragma unroll
            for (int j = 0; j < 4; j++) s[nt][j] = 0.0f;

        const __nv_bfloat16* qrh = Qhi + (warp * 16 + g) * 136 + 2 * t;
        const __nv_bfloat16* qrl = Qlo + (warp * 16 + g) * 136 + 2 * t;
#pragma unroll
        for (int c = 0; c < 8; c++) {
            uint32_t ah0 = *(const uint32_t*)(qrh + c * 16);
            uint32_t ah1 = *(const uint32_t*)(qrh + 8 * 136 + c * 16);
            uint32_t ah2 = *(const uint32_t*)(qrh + c * 16 + 8);
            uint32_t ah3 = *(const uint32_t*)(qrh + 8 * 136 + c * 16 + 8);
            uint32_t al0 = *(const uint32_t*)(qrl + c * 16);
            uint32_t al1 = *(const uint32_t*)(qrl + 8 * 136 + c * 16);
            uint32_t al2 = *(const uint32_t*)(qrl + c * 16 + 8);
            uint32_t al3 = *(const uint32_t*)(qrl + 8 * 136 + c * 16 + 8);
#pragma unroll
            for (int nt = 0; nt < 8; nt++) {
                const __nv_bfloat16* kp  = Khi + (nt * 8 + g) * 136 + c * 16 + 2 * t;
                const __nv_bfloat16* kpl = Klo + (nt * 8 + g) * 136 + c * 16 + 2 * t;
                uint32_t bh0 = *(const uint32_t*)(kp);
                uint32_t bh1 = *(const uint32_t*)(kp + 8);
                uint32_t bl0 = *(const uint32_t*)(kpl);
                uint32_t bl1 = *(const uint32_t*)(kpl + 8);
                mma_bf16(s[nt], ah0, ah1, ah2, ah3, bh0, bh1);
                mma_bf16(s[nt], ah0, ah1, ah2, ah3, bl0, bl1);
                mma_bf16(s[nt], al0, al1, al2, al3, bh0, bh1);
            }
        }

        if (k0 + 63 > wrow) {
            int r0 = wrow + g, r1 = r0 + 8;
#pragma unroll
            for (int nt = 0; nt < 8; nt++) {
                int c0 = k0 + nt * 8 + 2 * t;
                s[nt][0] = (c0     > r0) ? -1e30f : s[nt][0] * SCALE_F;
                s[nt][1] = (c0 + 1 > r0) ? -1e30f : s[nt][1] * SCALE_F;
                s[nt][2] = (c0     > r1) ? -1e30f : s[nt][2] * SCALE_F;
                s[nt][3] = (c0 + 1 > r1) ? -1e30f : s[nt][3] * SCALE_F;
            }
        } else {
#pragma unroll
            for (int nt = 0; nt < 8; nt++)
#pragma unroll
                for (int j = 0; j < 4; j++) s[nt][j] *= SCALE_F;
        }

        float mx0 = -1e30f, mx1 = -1e30f;
#pragma unroll
        for (int nt = 0; nt < 8; nt++) {
            mx0 = fmaxf(mx0, fmaxf(s[nt][0], s[nt][1]));
            mx1 = fmaxf(mx1, fmaxf(s[nt][2], s[nt][3]));
        }
        mx0 = fmaxf(mx0, __shfl_xor_sync(0xffffffffu, mx0, 1));
        mx0 = fmaxf(mx0, __shfl_xor_sync(0xffffffffu, mx0, 2));
        mx1 = fmaxf(mx1, __shfl_xor_sync(0xffffffffu, mx1, 1));
        mx1 = fmaxf(mx1, __shfl_xor_sync(0xffffffffu, mx1, 2));

        float mn0 = fmaxf(m0, mx0), mn1 = fmaxf(m1, mx1);
        float a0 = __expf(m0 - mn0), a1 = __expf(m1 - mn1);
        m0 = mn0; m1 = mn1;

        float sum0 = 0.0f, sum1 = 0.0f;
#pragma unroll
        for (int nt = 0; nt < 8; nt++) {
            s[nt][0] = __expf(s[nt][0] - m0);
            s[nt][1] = __expf(s[nt][1] - m0);
            s[nt][2] = __expf(s[nt][2] - m1);
            s[nt][3] = __expf(s[nt][3] - m1);
            sum0 += s[nt][0] + s[nt][1];
            sum1 += s[nt][2] + s[nt][3];
        }
        sum0 += __shfl_xor_sync(0xffffffffu, sum0, 1);
        sum0 += __shfl_xor_sync(0xffffffffu, sum0, 2);
        sum1 += __shfl_xor_sync(0xffffffffu, sum1, 1);
        sum1 += __shfl_xor_sync(0xffffffffu, sum1, 2);
        l0 = l0 * a0 + sum0;
        l1 = l1 * a1 + sum1;

#pragma unroll
        for (int nt = 0; nt < 16; nt++) {
            o[nt][0] *= a0; o[nt][1] *= a0;
            o[nt][2] *= a1; o[nt][3] *= a1;
        }

#pragma unroll
        for (int c = 0; c < 4; c++) {
            __nv_bfloat162 h0, lo0, h1, lo1, h2, lo2, h3, lo3;
            split2(s[2 * c][0],     s[2 * c][1],     h0, lo0);
            split2(s[2 * c][2],     s[2 * c][3],     h1, lo1);
            split2(s[2 * c + 1][0], s[2 * c + 1][1], h2, lo2);
            split2(s[2 * c + 1][2], s[2 * c + 1][3], h3, lo3);
            uint32_t ph0 = b2u(h0), ph1 = b2u(h1), ph2 = b2u(h2), ph3 = b2u(h3);
            uint32_t pl0 = b2u(lo0), pl1 = b2u(lo1), pl2 = b2u(lo2), pl3 = b2u(lo3);
#pragma unroll
            for (int nt = 0; nt < 16; nt++) {
                const __nv_bfloat16* vp  = Vth + (nt * 8 + g) * 72 + c * 16 + 2 * t;
                const __nv_bfloat16* vpl = Vtl + (nt * 8 + g) * 72 + c * 16 + 2 * t;
                uint32_t bh0 = *(const uint32_t*)(vp);
                uint32_t bh1 = *(const uint32_t*)(vp + 8);
                uint32_t bl0 = *(const uint32_t*)(vpl);
                uint32_t bl1 = *(const uint32_t*)(vpl + 8);
                mma_bf16(o[nt], ph0, ph1, ph2, ph3, bh0, bh1);
                mma_bf16(o[nt], ph0, ph1, ph2, ph3, bl0, bl1);
                mma_bf16(o[nt], pl0, pl1, pl2, pl3, bh0, bh1);
            }
        }
    }

    // ---- normalize + write attn output as fp16 hi/lo planes ----
    float inv0 = 1.0f / l0, inv1 = 1.0f / l1;
    int row0 = q0 + warp * 16 + g;
#pragma unroll
    for (int nt = 0; nt < 16; nt++) {
        int col = h * HD + nt * 8 + 2 * t;
        float f0 = o[nt][0] * inv0, f1 = o[nt][1] * inv0;
        float f2 = o[nt][2] * inv1, f3 = o[nt][3] * inv1;
        __half2 hA = __floats2half2_rn(f0, f1);
        float2 fA = __half22float2(hA);
        __half2 lA = __floats2half2_rn(f0 - fA.x, f1 - fA.y);
        __half2 hB = __floats2half2_rn(f2, f3);
        float2 fB = __half22float2(hB);
        __half2 lB = __floats2half2_rn(f2 - fB.x, f3 - fB.y);
        *(uint32_t*)&g_ah[(size_t)row0 * D_MODEL + col]       = h2u(hA);
        *(uint32_t*)&g_al[(size_t)row0 * D_MODEL + col]       = h2u(lA);
        *(uint32_t*)&g_ah[(size_t)(row0 + 8) * D_MODEL + col] = h2u(hB);
        *(uint32_t*)&g_al[(size_t)(row0 + 8) * D_MODEL + col] = h2u(lB);
    }
#undef LOAD_KV
}

// ---------------------------------------------------------------------------
extern "C" void kernel_launch(void* const* d_in, const int* in_sizes, int n_in,
                              void* d_out, int out_size)
{
    const float* hidden = (const float*)d_in[0];
    const float* cosb   = (const float*)d_in[1];
    const float* sinb   = (const float*)d_in[2];
    const float* Wq = (const float*)d_in[4];
    const float* Wk = (const float*)d_in[5];
    const float* Wv = (const float*)d_in[6];
    const float* Wo = (const float*)d_in[7];
    const float* qw = (const float*)d_in[8];
    const float* kw = (const float*)d_in[9];
    float* out = (float*)d_out;

    __half *hh, *hl, *wqh, *wkh, *wvh, *woh;
    cudaGetSymbolAddress((void**)&hh,  g_hh);
    cudaGetSymbolAddress((void**)&hl,  g_hl);
    cudaGetSymbolAddress((void**)&wqh, g_wqh);
    cudaGetSymbolAddress((void**)&wkh, g_wkh);
    cudaGetSymbolAddress((void**)&wvh, g_wvh);
    cudaGetSymbolAddress((void**)&woh, g_woh);

    cudaFuncSetAttribute(hgemm_qkv, cudaFuncAttributeMaxDynamicSharedMemorySize, HGEMM_SMEM);
    cudaFuncSetAttribute(hgemm_o,   cudaFuncAttributeMaxDynamicSharedMemorySize, HGEMM_SMEM);
    cudaFuncSetAttribute(flash_attn_tc, cudaFuncAttributeMaxDynamicSharedMemorySize, FLASH_SMEM_TC);

    // pre-pass: split hidden to hi/lo fp16; convert weights to hi fp16
    split_conv<<<2048, 256>>>((const float4*)hidden, (uint2*)hh, (uint2*)hl,
                              S_LEN * D_MODEL / 4);
    split_conv<<<2048, 256>>>((const float4*)Wq, (uint2*)wqh, nullptr,
                              D_MODEL * D_MODEL / 4);
    split_conv<<<2048, 256>>>((const float4*)Wk, (uint2*)wkh, nullptr,
                              KV_DIM * D_MODEL / 4);
    split_conv<<<2048, 256>>>((const float4*)Wv, (uint2*)wvh, nullptr,
                              KV_DIM * D_MODEL / 4);
    split_conv<<<2048, 256>>>((const float4*)Wo, (uint2*)woh, nullptr,
                              D_MODEL * D_MODEL / 4);

    // projections
    hgemm_qkv<<<384, 256, HGEMM_SMEM>>>();

    rmsnorm_rope<<<10240, 256>>>(cosb, sinb, qw, kw);

    flash_attn_tc<<<dim3(16, 32), 256, FLASH_SMEM_TC>>>();

    hgemm_o<<<dim3(32, 8), 256, HGEMM_SMEM>>>(out);
}

// round 9
// speedup vs baseline: 4.4988x; 1.1270x over previous
#include <cuda_runtime.h>
#include <cuda_bf16.h>
#include <cuda_fp16.h>
#include <math.h>
#include <stdint.h>

#define S_LEN   2048
#define D_MODEL 4096
#define NQH     32
#define NKVH    8
#define HD      128
#define KV_DIM  1024
#define SCALE_F 0.08838834764831845f   // 128^-0.5

// fp32 QKV outputs (flash consumes fp32)
__device__ float g_q[S_LEN * D_MODEL];
__device__ float g_k[S_LEN * KV_DIM];
__device__ float g_v[S_LEN * KV_DIM];
// fp16 split planes
__device__ __half g_hh[S_LEN * D_MODEL];   // hidden hi
__device__ __half g_hl[S_LEN * D_MODEL];   // hidden lo
__device__ __half g_wqh[D_MODEL * D_MODEL];
__device__ __half g_wkh[KV_DIM * D_MODEL];
__device__ __half g_wvh[KV_DIM * D_MODEL];
__device__ __half g_woh[D_MODEL * D_MODEL];
__device__ __half g_ah[S_LEN * D_MODEL];   // attn out hi
__device__ __half g_al[S_LEN * D_MODEL];   // attn out lo

// ---------------------------------------------------------------------------
// helpers
// ---------------------------------------------------------------------------
__device__ __forceinline__ void mma_bf16(float (&d)[4],
    uint32_t a0, uint32_t a1, uint32_t a2, uint32_t a3,
    uint32_t b0, uint32_t b1) {
    asm volatile(
        "mma.sync.aligned.m16n8k16.row.col.f32.bf16.bf16.f32 "
        "{%0,%1,%2,%3}, {%4,%5,%6,%7}, {%8,%9}, {%0,%1,%2,%3};\n"
        : "+f"(d[0]), "+f"(d[1]), "+f"(d[2]), "+f"(d[3])
        : "r"(a0), "r"(a1), "r"(a2), "r"(a3), "r"(b0), "r"(b1));
}

__device__ __forceinline__ void mma_f16(float (&d)[4],
    uint32_t a0, uint32_t a1, uint32_t a2, uint32_t a3,
    uint32_t b0, uint32_t b1) {
    asm volatile(
        "mma.sync.aligned.m16n8k16.row.col.f32.f16.f16.f32 "
        "{%0,%1,%2,%3}, {%4,%5,%6,%7}, {%8,%9}, {%0,%1,%2,%3};\n"
        : "+f"(d[0]), "+f"(d[1]), "+f"(d[2]), "+f"(d[3])
        : "r"(a0), "r"(a1), "r"(a2), "r"(a3), "r"(b0), "r"(b1));
}

__device__ __forceinline__ void ldsm4(uint32_t (&r)[4], uint32_t addr) {
    asm volatile("ldmatrix.sync.aligned.m8n8.x4.shared.b16 {%0,%1,%2,%3}, [%4];"
        : "=r"(r[0]), "=r"(r[1]), "=r"(r[2]), "=r"(r[3]) : "r"(addr));
}

__device__ __forceinline__ void split2(float x0, float x1,
                                       __nv_bfloat162& hi, __nv_bfloat162& lo) {
    hi = __floats2bfloat162_rn(x0, x1);
    float2 hf = __bfloat1622float2(hi);
    lo = __floats2bfloat162_rn(x0 - hf.x, x1 - hf.y);
}

__device__ __forceinline__ uint32_t b2u(__nv_bfloat162 v) {
    return *reinterpret_cast<uint32_t*>(&v);
}
__device__ __forceinline__ uint32_t h2u(__half2 v) {
    return *reinterpret_cast<uint32_t*>(&v);
}

// ---------------------------------------------------------------------------
// pre-pass: fp32 -> fp16 hi (+ optional lo residual) planes, vectorized
// ---------------------------------------------------------------------------
__global__ __launch_bounds__(256)
void split_conv(const float4* __restrict__ src, uint2* __restrict__ hi,
                uint2* __restrict__ lo, int n4)
{
    int stride = gridDim.x * blockDim.x;
    for (int i = blockIdx.x * blockDim.x + threadIdx.x; i < n4; i += stride) {
        float4 v = src[i];
        __half2 h01 = __floats2half2_rn(v.x, v.y);
        __half2 h23 = __floats2half2_rn(v.z, v.w);
        hi[i] = make_uint2(h2u(h01), h2u(h23));
        if (lo) {
            float2 f01 = __half22float2(h01);
            float2 f23 = __half22float2(h23);
            lo[i] = make_uint2(
                h2u(__floats2half2_rn(v.x - f01.x, v.y - f01.y)),
                h2u(__floats2half2_rn(v.z - f23.x, v.w - f23.y)));
        }
    }
}

// ---------------------------------------------------------------------------
// fp16 2-term GEMM NT with cp.async: C = (Ah+Al) @ Bh^T, fp32 out.
// CTA tile 128x128, BK=32, 256 threads, 8 warps (4m x 2n), warp tile 32x64.
// 3-stage cp.async pipeline; 2 CTAs/SM; smem stride 40 halves.
// ---------------------------------------------------------------------------
#define LDBH   40
#define AP_H   (128 * LDBH)              // halves per plane (5120)
#define STG_B  (3 * AP_H * 2)            // bytes per stage (30720)
#define HGEMM_SMEM (3 * STG_B)           // 92160 B

__device__ __forceinline__ void hgemm_body(const __half* __restrict__ Ah,
                                           const __half* __restrict__ Al,
                                           const __half* __restrict__ Bh,
                                           float* __restrict__ C,
                                           int N, int K, int bx, int by)
{
    extern __shared__ char smc[];
    const uint32_t smem_u32 = (uint32_t)__cvta_generic_to_shared(smc);

    const int tid  = threadIdx.x;
    const int warp = tid >> 5;
    const int lane = tid & 31;
    const int g    = lane >> 2;
    const int t    = lane & 3;
    const int wm   = (warp & 3) * 32;
    const int wn   = (warp >> 2) * 64;

    // ---- loader chunk descriptors (6 x 16B per thread per stage) ----
    // chunks: [0,1024) A planes (hi: cid<512, lo: cid>=512), [1024,1536) B hi
    uint32_t dst_off[6];
    const __half* src[6];
#pragma unroll
    for (int j = 0; j < 6; j++) {
        int cid = tid + j * 256;
        if (cid < 1024) {
            int plane = cid >> 9;
            int r = (cid & 511) >> 2;
            int c = cid & 3;
            dst_off[j] = (uint32_t)(plane * AP_H + r * LDBH + c * 8) * 2;
            src[j] = (plane ? Al : Ah) + (size_t)(by * 128 + r) * K + c * 8;
        } else {
            int b = cid - 1024;
            int r = b >> 2, c = b & 3;
            dst_off[j] = (uint32_t)(2 * AP_H + r * LDBH + c * 8) * 2;
            src[j] = Bh + (size_t)(bx * 128 + r) * K + c * 8;
        }
    }

    // ---- ldmatrix offsets (bytes within stage) ----
    const int lane8 = lane & 7;
    const uint32_t a_off = (uint32_t)(((wm + lane8 + ((lane >> 3) & 1) * 8) * LDBH
                                      + (lane >> 4) * 8) * 2);
    const uint32_t b_off = (uint32_t)((2 * AP_H + (wn + lane8 + (lane >> 4) * 8) * LDBH
                                      + ((lane >> 3) & 1) * 8) * 2);

    float acc[2][8][4];
#pragma unroll
    for (int mt = 0; mt < 2; mt++)
#pragma unroll
        for (int nt = 0; nt < 8; nt++)
#pragma unroll
            for (int c = 0; c < 4; c++) acc[mt][nt][c] = 0.0f;

    const int nk = K / 32;

#define CP_ISSUE(KT)                                                           \
    {                                                                          \
        uint32_t sb_ = smem_u32 + (uint32_t)(((KT) % 3) * STG_B);              \
        _Pragma("unroll")                                                      \
        for (int j = 0; j < 6; j++) {                                          \
            asm volatile("cp.async.cg.shared.global [%0], [%1], 16;"           \
                :: "r"(sb_ + dst_off[j]), "l"(src[j] + (KT) * 32) : "memory"); \
        }                                                                      \
    }
#define CP_COMMIT() asm volatile("cp.async.commit_group;" ::: "memory")

    CP_ISSUE(0); CP_COMMIT();
    CP_ISSUE(1); CP_COMMIT();

    for (int kt = 0; kt < nk; kt++) {
        asm volatile("cp.async.wait_group 1;" ::: "memory");
        __syncthreads();

        const uint32_t sb = smem_u32 + (uint32_t)((kt % 3) * STG_B);

#pragma unroll
        for (int k16 = 0; k16 < 2; k16++) {
            uint32_t ah[2][4], al[2][4];
            ldsm4(ah[0], sb + a_off + k16 * 32);
            ldsm4(ah[1], sb + a_off + 16 * LDBH * 2 + k16 * 32);
            ldsm4(al[0], sb + AP_H * 2 + a_off + k16 * 32);
            ldsm4(al[1], sb + AP_H * 2 + a_off + 16 * LDBH * 2 + k16 * 32);

#pragma unroll
            for (int jh = 0; jh < 2; jh++) {
                uint32_t bh[2][4];
#pragma unroll
                for (int jj = 0; jj < 2; jj++) {
                    int j = jh * 2 + jj;
                    ldsm4(bh[jj], sb + b_off + j * 16 * LDBH * 2 + k16 * 32);
                }
#pragma unroll
                for (int mt = 0; mt < 2; mt++)
#pragma unroll
                    for (int jj = 0; jj < 2; jj++) {
                        int nt = (jh * 2 + jj) * 2;
                        float (&d0)[4] = acc[mt][nt];
                        float (&d1)[4] = acc[mt][nt + 1];
                        mma_f16(d0, al[mt][0], al[mt][1], al[mt][2], al[mt][3],
                                bh[jj][0], bh[jj][1]);
                        mma_f16(d0, ah[mt][0], ah[mt][1], ah[mt][2], ah[mt][3],
                                bh[jj][0], bh[jj][1]);
                        mma_f16(d1, al[mt][0], al[mt][1], al[mt][2], al[mt][3],
                                bh[jj][2], bh[jj][3]);
                        mma_f16(d1, ah[mt][0], ah[mt][1], ah[mt][2], ah[mt][3],
                                bh[jj][2], bh[jj][3]);
                    }
            }
        }

        if (kt + 2 < nk) { CP_ISSUE(kt + 2); }
        CP_COMMIT();
    }

    // ---- epilogue ----
#pragma unroll
    for (int mt = 0; mt < 2; mt++) {
        int r0 = by * 128 + wm + mt * 16 + g;
#pragma unroll
        for (int nt = 0; nt < 8; nt++) {
            int c0 = bx * 128 + wn + nt * 8 + 2 * t;
            *(float2*)&C[(size_t)r0 * N + c0] =
                make_float2(acc[mt][nt][0], acc[mt][nt][1]);
            *(float2*)&C[(size_t)(r0 + 8) * N + c0] =
                make_float2(acc[mt][nt][2], acc[mt][nt][3]);
        }
    }
#undef CP_ISSUE
#undef CP_COMMIT
}

// merged Q/K/V projection: 768 CTAs (512 Q + 128 K + 128 V)
__global__ __launch_bounds__(256, 2)
void hgemm_qkv()
{
    int b = blockIdx.x;
    if (b < 512)      hgemm_body(g_hh, g_hl, g_wqh, g_q, 4096, 4096, b & 31, b >> 5);
    else if (b < 640) { int i = b - 512; hgemm_body(g_hh, g_hl, g_wkh, g_k, 1024, 4096, i & 7, i >> 3); }
    else              { int i = b - 640; hgemm_body(g_hh, g_hl, g_wvh, g_v, 1024, 4096, i & 7, i >> 3); }
}

__global__ __launch_bounds__(256, 2)
void hgemm_o(float* __restrict__ out)
{
    hgemm_body(g_ah, g_al, g_woh, out, 4096, 4096, blockIdx.x, blockIdx.y);
}

// ---------------------------------------------------------------------------
// Fused per-head RMSNorm + RoPE (unchanged)
// ---------------------------------------------------------------------------
__global__ __launch_bounds__(256)
void rmsnorm_rope(const float* __restrict__ cosb, const float* __restrict__ sinb,
                  const float* __restrict__ qw, const float* __restrict__ kw)
{
    const int warp = blockIdx.x * 8 + (threadIdx.x >> 5);
    const int lane = threadIdx.x & 31;

    float* base;
    const float* w;
    int s;
    if (warp < S_LEN * NQH) {
        s = warp / NQH;
        int h = warp - s * NQH;
        base = g_q + (size_t)s * D_MODEL + h * HD;
        w = qw;
    } else {
        int wv = warp - S_LEN * NQH;
        s = wv / NKVH;
        int h = wv - s * NKVH;
        base = g_k + (size_t)s * KV_DIM + h * HD;
        w = kw;
    }

    float x0 = base[lane];
    float x1 = base[lane + 32];
    float x2 = base[lane + 64];
    float x3 = base[lane + 96];

    float ss = x0 * x0 + x1 * x1 + x2 * x2 + x3 * x3;
#pragma unroll
    for (int o = 16; o; o >>= 1) ss += __shfl_xor_sync(0xffffffffu, ss, o);
    float inv = rsqrtf(ss * (1.0f / 128.0f) + 1e-6f);

    float n0 = w[lane]      * x0 * inv;
    float n1 = w[lane + 32] * x1 * inv;
    float n2 = w[lane + 64] * x2 * inv;
    float n3 = w[lane + 96] * x3 * inv;

    const float c0 = cosb[s * 64 + lane];
    const float c1 = cosb[s * 64 + lane + 32];
    const float s0 = sinb[s * 64 + lane];
    const float s1 = sinb[s * 64 + lane + 32];

    base[lane]      = n0 * c0 - n2 * s0;
    base[lane + 32] = n1 * c1 - n3 * s1;
    base[lane + 64] = n2 * c0 + n0 * s0;
    base[lane + 96] = n3 * c1 + n1 * s1;
}

// ---------------------------------------------------------------------------
// Tensor-core flash attention (R8: bf16 3-term, double-buffered K/V,
// register-direct P fragments, fp16 hi/lo epilogue)
// ---------------------------------------------------------------------------
#define OFF_QHI  0
#define OFF_QLO  17408
#define OFF_KV   34816
#define KVBUF    35840
#define FLASH_SMEM_TC ((OFF_KV + 2 * KVBUF) * 2)   // 212992 B

__global__ __launch_bounds__(256, 1)
void flash_attn_tc()
{
    extern __shared__ __nv_bfloat16 smb[];
    __nv_bfloat16* Qhi = smb + OFF_QHI;
    __nv_bfloat16* Qlo = smb + OFF_QLO;

    const int qt  = 15 - blockIdx.x;
    const int h   = blockIdx.y;
    const int q0  = qt * 128;
    const int kvh = h >> 2;
    const int tid  = threadIdx.x;
    const int warp = tid >> 5;
    const int lane = tid & 31;
    const int g = lane >> 2;
    const int t = lane & 3;

    for (int i = tid; i < 128 * 32; i += 256) {
        int r = i >> 5, c = (i & 31) << 2;
        float4 v = *(const float4*)&g_q[(size_t)(q0 + r) * D_MODEL + h * HD + c];
        __nv_bfloat162 h01, l01, h23, l23;
        split2(v.x, v.y, h01, l01);
        split2(v.z, v.w, h23, l23);
        *(__nv_bfloat162*)(Qhi + r * 136 + c)     = h01;
        *(__nv_bfloat162*)(Qhi + r * 136 + c + 2) = h23;
        *(__nv_bfloat162*)(Qlo + r * 136 + c)     = l01;
        *(__nv_bfloat162*)(Qlo + r * 136 + c + 2) = l23;
    }

    float o[16][4];
#pragma unroll
    for (int nt = 0; nt < 16; nt++)
#pragma unroll
        for (int j = 0; j < 4; j++) o[nt][j] = 0.0f;
    float m0 = -1e30f, m1 = -1e30f, l0 = 0.0f, l1 = 0.0f;

    const int wrow = q0 + warp * 16;
    const int nkt  = 2 * qt + 2;

#define LOAD_KV(KT, BUF)                                                       \
    {                                                                          \
        __nv_bfloat16* Khi_ = smb + OFF_KV + (BUF) * KVBUF;                    \
        __nv_bfloat16* Klo_ = Khi_ + 8704;                                     \
        __nv_bfloat16* Vth_ = Khi_ + 17408;                                    \
        __nv_bfloat16* Vtl_ = Khi_ + 26624;                                    \
        const int k0_ = (KT) * 64;                                             \
        for (int i = tid; i < 64 * 32; i += 256) {                             \
            int r = i >> 5, c = (i & 31) << 2;                                 \
            float4 v = *(const float4*)&g_k[(size_t)(k0_ + r) * KV_DIM + kvh * HD + c]; \
            __nv_bfloat162 h01, l01, h23, l23;                                 \
            split2(v.x, v.y, h01, l01);                                        \
            split2(v.z, v.w, h23, l23);                                        \
            *(__nv_bfloat162*)(Khi_ + r * 136 + c)     = h01;                  \
            *(__nv_bfloat162*)(Khi_ + r * 136 + c + 2) = h23;                  \
            *(__nv_bfloat162*)(Klo_ + r * 136 + c)     = l01;                  \
            *(__nv_bfloat162*)(Klo_ + r * 136 + c + 2) = l23;                  \
        }                                                                      \
        for (int u = tid; u < 1024; u += 256) {                                \
            int p = u & 31, c4 = u >> 5;                                       \
            const float* vp_ = &g_v[(size_t)(k0_ + 2 * p) * KV_DIM + kvh * HD + c4 * 4]; \
            float4 va = *(const float4*)vp_;                                   \
            float4 vb = *(const float4*)(vp_ + KV_DIM);                        \
            _Pragma("unroll")                                                  \
            for (int j = 0; j < 4; j++) {                                      \
                __nv_bfloat162 hi_, lo_;                                       \
                split2((&va.x)[j], (&vb.x)[j], hi_, lo_);                      \
                *(__nv_bfloat162*)(Vth_ + (c4 * 4 + j) * 72 + 2 * p) = hi_;    \
                *(__nv_bfloat162*)(Vtl_ + (c4 * 4 + j) * 72 + 2 * p) = lo_;    \
            }                                                                  \
        }                                                                      \
    }

    LOAD_KV(0, 0);

    for (int kt = 0; kt < nkt; kt++) {
        const int k0 = kt * 64;
        __syncthreads();
        if (kt + 1 < nkt) LOAD_KV(kt + 1, (kt + 1) & 1);

        if (k0 > wrow + 15) continue;

        const __nv_bfloat16* Khi = smb + OFF_KV + (kt & 1) * KVBUF;
        const __nv_bfloat16* Klo = Khi + 8704;
        const __nv_bfloat16* Vth = Khi + 17408;
        const __nv_bfloat16* Vtl = Khi + 26624;

        float s[8][4];
#pragma unroll
        for (int nt = 0; nt < 8; nt++)
#pragma unroll
            for (int j = 0; j < 4; j++) s[nt][j] = 0.0f;

        const __nv_bfloat16* qrh = Qhi + (warp * 16 + g) * 136 + 2 * t;
        const __nv_bfloat16* qrl = Qlo + (warp * 16 + g) * 136 + 2 * t;
#pragma unroll
        for (int c = 0; c < 8; c++) {
            uint32_t ah0 = *(const uint32_t*)(qrh + c * 16);
            uint32_t ah1 = *(const uint32_t*)(qrh + 8 * 136 + c * 16);
            uint32_t ah2 = *(const uint32_t*)(qrh + c * 16 + 8);
            uint32_t ah3 = *(const uint32_t*)(qrh + 8 * 136 + c * 16 + 8);
            uint32_t al0 = *(const uint32_t*)(qrl + c * 16);
            uint32_t al1 = *(const uint32_t*)(qrl + 8 * 136 + c * 16);
            uint32_t al2 = *(const uint32_t*)(qrl + c * 16 + 8);
            uint32_t al3 = *(const uint32_t*)(qrl + 8 * 136 + c * 16 + 8);
#pragma unroll
            for (int nt = 0; nt < 8; nt++) {
                const __nv_bfloat16* kp  = Khi + (nt * 8 + g) * 136 + c * 16 + 2 * t;
                const __nv_bfloat16* kpl = Klo + (nt * 8 + g) * 136 + c * 16 + 2 * t;
                uint32_t bh0 = *(const uint32_t*)(kp);
                uint32_t bh1 = *(const uint32_t*)(kp + 8);
                uint32_t bl0 = *(const uint32_t*)(kpl);
                uint32_t bl1 = *(const uint32_t*)(kpl + 8);
                mma_bf16(s[nt], ah0, ah1, ah2, ah3, bh0, bh1);
                mma_bf16(s[nt], ah0, ah1, ah2, ah3, bl0, bl1);
                mma_bf16(s[nt], al0, al1, al2, al3, bh0, bh1);
            }
        }

        if (k0 + 63 > wrow) {
            int r0 = wrow + g, r1 = r0 + 8;
#pragma unroll
            for (int nt = 0; nt < 8; nt++) {
                int c0 = k0 + nt * 8 + 2 * t;
                s[nt][0] = (c0     > r0) ? -1e30f : s[nt][0] * SCALE_F;
                s[nt][1] = (c0 + 1 > r0) ? -1e30f : s[nt][1] * SCALE_F;
                s[nt][2] = (c0     > r1) ? -1e30f : s[nt][2] * SCALE_F;
                s[nt][3] = (c0 + 1 > r1) ? -1e30f : s[nt][3] * SCALE_F;
            }
        } else {
#pragma unroll
            for (int nt = 0; nt < 8; nt++)
#pragma unroll
                for (int j = 0; j < 4; j++) s[nt][j] *= SCALE_F;
        }

        float mx0 = -1e30f, mx1 = -1e30f;
#pragma unroll
        for (int nt = 0; nt < 8; nt++) {
            mx0 = fmaxf(mx0, fmaxf(s[nt][0], s[nt][1]));
            mx1 = fmaxf(mx1, fmaxf(s[nt][2], s[nt][3]));
        }
        mx0 = fmaxf(mx0, __shfl_xor_sync(0xffffffffu, mx0, 1));
        mx0 = fmaxf(mx0, __shfl_xor_sync(0xffffffffu, mx0, 2));
        mx1 = fmaxf(mx1, __shfl_xor_sync(0xffffffffu, mx1, 1));
        mx1 = fmaxf(mx1, __shfl_xor_sync(0xffffffffu, mx1, 2));

        float mn0 = fmaxf(m0, mx0), mn1 = fmaxf(m1, mx1);
        float a0 = __expf(m0 - mn0), a1 = __expf(m1 - mn1);
        m0 = mn0; m1 = mn1;

        float sum0 = 0.0f, sum1 = 0.0f;
#pragma unroll
        for (int nt = 0; nt < 8; nt++) {
            s[nt][0] = __expf(s[nt][0] - m0);
            s[nt][1] = __expf(s[nt][1] - m0);
            s[nt][2] = __expf(s[nt][2] - m1);
            s[nt][3] = __expf(s[nt][3] - m1);
            sum0 += s[nt][0] + s[nt][1];
            sum1 += s[nt][2] + s[nt][3];
        }
        sum0 += __shfl_xor_sync(0xffffffffu, sum0, 1);
        sum0 += __shfl_xor_sync(0xffffffffu, sum0, 2);
        sum1 += __shfl_xor_sync(0xffffffffu, sum1, 1);
        sum1 += __shfl_xor_sync(0xffffffffu, sum1, 2);
        l0 = l0 * a0 + sum0;
        l1 = l1 * a1 + sum1;

#pragma unroll
        for (int nt = 0; nt < 16; nt++) {
            o[nt][0] *= a0; o[nt][1] *= a0;
            o[nt][2] *= a1; o[nt][3] *= a1;
        }

#pragma unroll
        for (int c = 0; c < 4; c++) {
            __nv_bfloat162 h0, lo0, h1, lo1, h2, lo2, h3, lo3;
            split2(s[2 * c][0],     s[2 * c][1],     h0, lo0);
            split2(s[2 * c][2],     s[2 * c][3],     h1, lo1);
            split2(s[2 * c + 1][0], s[2 * c + 1][1], h2, lo2);
            split2(s[2 * c + 1][2], s[2 * c + 1][3], h3, lo3);
            uint32_t ph0 = b2u(h0), ph1 = b2u(h1), ph2 = b2u(h2), ph3 = b2u(h3);
            uint32_t pl0 = b2u(lo0), pl1 = b2u(lo1), pl2 = b2u(lo2), pl3 = b2u(lo3);
#pragma unroll
            for (int nt = 0; nt < 16; nt++) {
                const __nv_bfloat16* vp  = Vth + (nt * 8 + g) * 72 + c * 16 + 2 * t;
                const __nv_bfloat16* vpl = Vtl + (nt * 8 + g) * 72 + c * 16 + 2 * t;
                uint32_t bh0 = *(const uint32_t*)(vp);
                uint32_t bh1 = *(const uint32_t*)(vp + 8);
                uint32_t bl0 = *(const uint32_t*)(vpl);
                uint32_t bl1 = *(const uint32_t*)(vpl + 8);
                mma_bf16(o[nt], ph0, ph1, ph2, ph3, bh0, bh1);
                mma_bf16(o[nt], ph0, ph1, ph2, ph3, bl0, bl1);
                mma_bf16(o[nt], pl0, pl1, pl2, pl3, bh0, bh1);
            }
        }
    }

    float inv0 = 1.0f / l0, inv1 = 1.0f / l1;
    int row0 = q0 + warp * 16 + g;
#pragma unroll
    for (int nt = 0; nt < 16; nt++) {
        int col = h * HD + nt * 8 + 2 * t;
        float f0 = o[nt][0] * inv0, f1 = o[nt][1] * inv0;
        float f2 = o[nt][2] * inv1, f3 = o[nt][3] * inv1;
        __half2 hA = __floats2half2_rn(f0, f1);
        float2 fA = __half22float2(hA);
        __half2 lA = __floats2half2_rn(f0 - fA.x, f1 - fA.y);
        __half2 hB = __floats2half2_rn(f2, f3);
        float2 fB = __half22float2(hB);
        __half2 lB = __floats2half2_rn(f2 - fB.x, f3 - fB.y);
        *(uint32_t*)&g_ah[(size_t)row0 * D_MODEL + col]       = h2u(hA);
        *(uint32_t*)&g_al[(size_t)row0 * D_MODEL + col]       = h2u(lA);
        *(uint32_t*)&g_ah[(size_t)(row0 + 8) * D_MODEL + col] = h2u(hB);
        *(uint32_t*)&g_al[(size_t)(row0 + 8) * D_MODEL + col] = h2u(lB);
    }
#undef LOAD_KV
}

// ---------------------------------------------------------------------------
extern "C" void kernel_launch(void* const* d_in, const int* in_sizes, int n_in,
                              void* d_out, int out_size)
{
    const float* hidden = (const float*)d_in[0];
    const float* cosb   = (const float*)d_in[1];
    const float* sinb   = (const float*)d_in[2];
    const float* Wq = (const float*)d_in[4];
    const float* Wk = (const float*)d_in[5];
    const float* Wv = (const float*)d_in[6];
    const float* Wo = (const float*)d_in[7];
    const float* qw = (const float*)d_in[8];
    const float* kw = (const float*)d_in[9];
    float* out = (float*)d_out;

    __half *hh, *hl, *wqh, *wkh, *wvh, *woh;
    cudaGetSymbolAddress((void**)&hh,  g_hh);
    cudaGetSymbolAddress((void**)&hl,  g_hl);
    cudaGetSymbolAddress((void**)&wqh, g_wqh);
    cudaGetSymbolAddress((void**)&wkh, g_wkh);
    cudaGetSymbolAddress((void**)&wvh, g_wvh);
    cudaGetSymbolAddress((void**)&woh, g_woh);

    cudaFuncSetAttribute(hgemm_qkv, cudaFuncAttributeMaxDynamicSharedMemorySize, HGEMM_SMEM);
    cudaFuncSetAttribute(hgemm_o,   cudaFuncAttributeMaxDynamicSharedMemorySize, HGEMM_SMEM);
    cudaFuncSetAttribute(flash_attn_tc, cudaFuncAttributeMaxDynamicSharedMemorySize, FLASH_SMEM_TC);

    // pre-pass: split hidden to hi/lo fp16; convert weights to hi fp16
    split_conv<<<2048, 256>>>((const float4*)hidden, (uint2*)hh, (uint2*)hl,
                              S_LEN * D_MODEL / 4);
    split_conv<<<2048, 256>>>((const float4*)Wq, (uint2*)wqh, nullptr,
                              D_MODEL * D_MODEL / 4);
    split_conv<<<2048, 256>>>((const float4*)Wk, (uint2*)wkh, nullptr,
                              KV_DIM * D_MODEL / 4);
    split_conv<<<2048, 256>>>((const float4*)Wv, (uint2*)wvh, nullptr,
                              KV_DIM * D_MODEL / 4);
    split_conv<<<2048, 256>>>((const float4*)Wo, (uint2*)woh, nullptr,
                              D_MODEL * D_MODEL / 4);

    // projections
    hgemm_qkv<<<768, 256, HGEMM_SMEM>>>();

    rmsnorm_rope<<<10240, 256>>>(cosb, sinb, qw, kw);

    flash_attn_tc<<<dim3(16, 32), 256, FLASH_SMEM_TC>>>();

    hgemm_o<<<dim3(32, 16), 256, HGEMM_SMEM>>>(out);
}

// round 10
// speedup vs baseline: 4.6954x; 1.0437x over previous
#include <cuda_runtime.h>
#include <cuda_bf16.h>
#include <cuda_fp16.h>
#include <math.h>
#include <stdint.h>

#define S_LEN   2048
#define D_MODEL 4096
#define NQH     32
#define NKVH    8
#define HD      128
#define KV_DIM  1024
#define SCALE_F 0.08838834764831845f   // 128^-0.5

// fp32 QKV outputs (flash consumes fp32)
__device__ float g_q[S_LEN * D_MODEL];
__device__ float g_k[S_LEN * KV_DIM];
__device__ float g_v[S_LEN * KV_DIM];
// fp16 split planes
__device__ __half g_hh[S_LEN * D_MODEL];   // hidden hi
__device__ __half g_hl[S_LEN * D_MODEL];   // hidden lo
__device__ __half g_wqh[D_MODEL * D_MODEL];
__device__ __half g_wkh[KV_DIM * D_MODEL];
__device__ __half g_wvh[KV_DIM * D_MODEL];
__device__ __half g_woh[D_MODEL * D_MODEL];
__device__ __half g_ah[S_LEN * D_MODEL];   // attn out hi
__device__ __half g_al[S_LEN * D_MODEL];   // attn out lo

// ---------------------------------------------------------------------------
// helpers
// ---------------------------------------------------------------------------
__device__ __forceinline__ void mma_bf16(float (&d)[4],
    uint32_t a0, uint32_t a1, uint32_t a2, uint32_t a3,
    uint32_t b0, uint32_t b1) {
    asm volatile(
        "mma.sync.aligned.m16n8k16.row.col.f32.bf16.bf16.f32 "
        "{%0,%1,%2,%3}, {%4,%5,%6,%7}, {%8,%9}, {%0,%1,%2,%3};\n"
        : "+f"(d[0]), "+f"(d[1]), "+f"(d[2]), "+f"(d[3])
        : "r"(a0), "r"(a1), "r"(a2), "r"(a3), "r"(b0), "r"(b1));
}

__device__ __forceinline__ void mma_f16(float (&d)[4],
    uint32_t a0, uint32_t a1, uint32_t a2, uint32_t a3,
    uint32_t b0, uint32_t b1) {
    asm volatile(
        "mma.sync.aligned.m16n8k16.row.col.f32.f16.f16.f32 "
        "{%0,%1,%2,%3}, {%4,%5,%6,%7}, {%8,%9}, {%0,%1,%2,%3};\n"
        : "+f"(d[0]), "+f"(d[1]), "+f"(d[2]), "+f"(d[3])
        : "r"(a0), "r"(a1), "r"(a2), "r"(a3), "r"(b0), "r"(b1));
}

__device__ __forceinline__ void ldsm4(uint32_t (&r)[4], uint32_t addr) {
    asm volatile("ldmatrix.sync.aligned.m8n8.x4.shared.b16 {%0,%1,%2,%3}, [%4];"
        : "=r"(r[0]), "=r"(r[1]), "=r"(r[2]), "=r"(r[3]) : "r"(addr));
}

__device__ __forceinline__ void split2(float x0, float x1,
                                       __nv_bfloat162& hi, __nv_bfloat162& lo) {
    hi = __floats2bfloat162_rn(x0, x1);
    float2 hf = __bfloat1622float2(hi);
    lo = __floats2bfloat162_rn(x0 - hf.x, x1 - hf.y);
}

__device__ __forceinline__ void split2h(float x0, float x1,
                                        __half2& hi, __half2& lo) {
    hi = __floats2half2_rn(x0, x1);
    float2 hf = __half22float2(hi);
    lo = __floats2half2_rn(x0 - hf.x, x1 - hf.y);
}

__device__ __forceinline__ uint32_t b2u(__nv_bfloat162 v) {
    return *reinterpret_cast<uint32_t*>(&v);
}
__device__ __forceinline__ uint32_t h2u(__half2 v) {
    return *reinterpret_cast<uint32_t*>(&v);
}

// ---------------------------------------------------------------------------
// pre-pass: all fp32->fp16 conversions in ONE launch (segmented grid-stride)
// segments (float4 units): hidden 2M (hi+lo), Wq 4M, Wk 1M, Wv 1M, Wo 4M
// ---------------------------------------------------------------------------
#define SEG0 (2 * 1024 * 1024)
#define SEG1 (SEG0 + 4 * 1024 * 1024)
#define SEG2 (SEG1 + 1024 * 1024)
#define SEG3 (SEG2 + 1024 * 1024)
#define SEG4 (SEG3 + 4 * 1024 * 1024)

__global__ __launch_bounds__(256)
void split_all(const float4* __restrict__ hidden, const float4* __restrict__ Wq,
               const float4* __restrict__ Wk, const float4* __restrict__ Wv,
               const float4* __restrict__ Wo)
{
    int stride = gridDim.x * blockDim.x;
    for (int i = blockIdx.x * blockDim.x + threadIdx.x; i < SEG4; i += stride) {
        const float4* src;
        uint2 *hi, *lo = nullptr;
        int off;
        if (i < SEG0)      { src = hidden; off = i;        hi = (uint2*)g_hh; lo = (uint2*)g_hl; }
        else if (i < SEG1) { src = Wq;     off = i - SEG0; hi = (uint2*)g_wqh; }
        else if (i < SEG2) { src = Wk;     off = i - SEG1; hi = (uint2*)g_wkh; }
        else if (i < SEG3) { src = Wv;     off = i - SEG2; hi = (uint2*)g_wvh; }
        else               { src = Wo;     off = i - SEG3; hi = (uint2*)g_woh; }
        float4 v = src[off];
        __half2 h01 = __floats2half2_rn(v.x, v.y);
        __half2 h23 = __floats2half2_rn(v.z, v.w);
        hi[off] = make_uint2(h2u(h01), h2u(h23));
        if (lo) {
            float2 f01 = __half22float2(h01);
            float2 f23 = __half22float2(h23);
            lo[off] = make_uint2(
                h2u(__floats2half2_rn(v.x - f01.x, v.y - f01.y)),
                h2u(__floats2half2_rn(v.z - f23.x, v.w - f23.y)));
        }
    }
}

// ---------------------------------------------------------------------------
// fp16 2-term GEMM NT with cp.async (unchanged from R9)
// CTA tile 128x128, BK=32, 256 threads, 8 warps (4m x 2n), warp tile 32x64.
// 3-stage cp.async pipeline; 2 CTAs/SM; smem stride 40 halves.
// ---------------------------------------------------------------------------
#define LDBH   40
#define AP_H   (128 * LDBH)
#define STG_B  (3 * AP_H * 2)
#define HGEMM_SMEM (3 * STG_B)           // 92160 B

__device__ __forceinline__ void hgemm_body(const __half* __restrict__ Ah,
                                           const __half* __restrict__ Al,
                                           const __half* __restrict__ Bh,
                                           float* __restrict__ C,
                                           int N, int K, int bx, int by)
{
    extern __shared__ char smc[];
    const uint32_t smem_u32 = (uint32_t)__cvta_generic_to_shared(smc);

    const int tid  = threadIdx.x;
    const int warp = tid >> 5;
    const int lane = tid & 31;
    const int g    = lane >> 2;
    const int t    = lane & 3;
    const int wm   = (warp & 3) * 32;
    const int wn   = (warp >> 2) * 64;

    uint32_t dst_off[6];
    const __half* src[6];
#pragma unroll
    for (int j = 0; j < 6; j++) {
        int cid = tid + j * 256;
        if (cid < 1024) {
            int plane = cid >> 9;
            int r = (cid & 511) >> 2;
            int c = cid & 3;
            dst_off[j] = (uint32_t)(plane * AP_H + r * LDBH + c * 8) * 2;
            src[j] = (plane ? Al : Ah) + (size_t)(by * 128 + r) * K + c * 8;
        } else {
            int b = cid - 1024;
            int r = b >> 2, c = b & 3;
            dst_off[j] = (uint32_t)(2 * AP_H + r * LDBH + c * 8) * 2;
            src[j] = Bh + (size_t)(bx * 128 + r) * K + c * 8;
        }
    }

    const int lane8 = lane & 7;
    const uint32_t a_off = (uint32_t)(((wm + lane8 + ((lane >> 3) & 1) * 8) * LDBH
                                      + (lane >> 4) * 8) * 2);
    const uint32_t b_off = (uint32_t)((2 * AP_H + (wn + lane8 + (lane >> 4) * 8) * LDBH
                                      + ((lane >> 3) & 1) * 8) * 2);

    float acc[2][8][4];
#pragma unroll
    for (int mt = 0; mt < 2; mt++)
#pragma unroll
        for (int nt = 0; nt < 8; nt++)
#pragma unroll
            for (int c = 0; c < 4; c++) acc[mt][nt][c] = 0.0f;

    const int nk = K / 32;

#define CP_ISSUE(KT)                                                           \
    {                                                                          \
        uint32_t sb_ = smem_u32 + (uint32_t)(((KT) % 3) * STG_B);              \
        _Pragma("unroll")                                                      \
        for (int j = 0; j < 6; j++) {                                          \
            asm volatile("cp.async.cg.shared.global [%0], [%1], 16;"           \
                :: "r"(sb_ + dst_off[j]), "l"(src[j] + (KT) * 32) : "memory"); \
        }                                                                      \
    }
#define CP_COMMIT() asm volatile("cp.async.commit_group;" ::: "memory")

    CP_ISSUE(0); CP_COMMIT();
    CP_ISSUE(1); CP_COMMIT();

    for (int kt = 0; kt < nk; kt++) {
        asm volatile("cp.async.wait_group 1;" ::: "memory");
        __syncthreads();

        const uint32_t sb = smem_u32 + (uint32_t)((kt % 3) * STG_B);

#pragma unroll
        for (int k16 = 0; k16 < 2; k16++) {
            uint32_t ah[2][4], al[2][4];
            ldsm4(ah[0], sb + a_off + k16 * 32);
            ldsm4(ah[1], sb + a_off + 16 * LDBH * 2 + k16 * 32);
            ldsm4(al[0], sb + AP_H * 2 + a_off + k16 * 32);
            ldsm4(al[1], sb + AP_H * 2 + a_off + 16 * LDBH * 2 + k16 * 32);

#pragma unroll
            for (int jh = 0; jh < 2; jh++) {
                uint32_t bh[2][4];
#pragma unroll
                for (int jj = 0; jj < 2; jj++) {
                    int j = jh * 2 + jj;
                    ldsm4(bh[jj], sb + b_off + j * 16 * LDBH * 2 + k16 * 32);
                }
#pragma unroll
                for (int mt = 0; mt < 2; mt++)
#pragma unroll
                    for (int jj = 0; jj < 2; jj++) {
                        int nt = (jh * 2 + jj) * 2;
                        float (&d0)[4] = acc[mt][nt];
                        float (&d1)[4] = acc[mt][nt + 1];
                        mma_f16(d0, al[mt][0], al[mt][1], al[mt][2], al[mt][3],
                                bh[jj][0], bh[jj][1]);
                        mma_f16(d0, ah[mt][0], ah[mt][1], ah[mt][2], ah[mt][3],
                                bh[jj][0], bh[jj][1]);
                        mma_f16(d1, al[mt][0], al[mt][1], al[mt][2], al[mt][3],
                                bh[jj][2], bh[jj][3]);
                        mma_f16(d1, ah[mt][0], ah[mt][1], ah[mt][2], ah[mt][3],
                                bh[jj][2], bh[jj][3]);
                    }
            }
        }

        if (kt + 2 < nk) { CP_ISSUE(kt + 2); }
        CP_COMMIT();
    }

#pragma unroll
    for (int mt = 0; mt < 2; mt++) {
        int r0 = by * 128 + wm + mt * 16 + g;
#pragma unroll
        for (int nt = 0; nt < 8; nt++) {
            int c0 = bx * 128 + wn + nt * 8 + 2 * t;
            *(float2*)&C[(size_t)r0 * N + c0] =
                make_float2(acc[mt][nt][0], acc[mt][nt][1]);
            *(float2*)&C[(size_t)(r0 + 8) * N + c0] =
                make_float2(acc[mt][nt][2], acc[mt][nt][3]);
        }
    }
#undef CP_ISSUE
#undef CP_COMMIT
}

__global__ __launch_bounds__(256, 2)
void hgemm_qkv()
{
    int b = blockIdx.x;
    if (b < 512)      hgemm_body(g_hh, g_hl, g_wqh, g_q, 4096, 4096, b & 31, b >> 5);
    else if (b < 640) { int i = b - 512; hgemm_body(g_hh, g_hl, g_wkh, g_k, 1024, 4096, i & 7, i >> 3); }
    else              { int i = b - 640; hgemm_body(g_hh, g_hl, g_wvh, g_v, 1024, 4096, i & 7, i >> 3); }
}

__global__ __launch_bounds__(256, 2)
void hgemm_o(float* __restrict__ out)
{
    hgemm_body(g_ah, g_al, g_woh, out, 4096, 4096, blockIdx.x, blockIdx.y);
}

// ---------------------------------------------------------------------------
// Fused per-head RMSNorm + RoPE (unchanged)
// ---------------------------------------------------------------------------
__global__ __launch_bounds__(256)
void rmsnorm_rope(const float* __restrict__ cosb, const float* __restrict__ sinb,
                  const float* __restrict__ qw, const float* __restrict__ kw)
{
    const int warp = blockIdx.x * 8 + (threadIdx.x >> 5);
    const int lane = threadIdx.x & 31;

    float* base;
    const float* w;
    int s;
    if (warp < S_LEN * NQH) {
        s = warp / NQH;
        int h = warp - s * NQH;
        base = g_q + (size_t)s * D_MODEL + h * HD;
        w = qw;
    } else {
        int wv = warp - S_LEN * NQH;
        s = wv / NKVH;
        int h = wv - s * NKVH;
        base = g_k + (size_t)s * KV_DIM + h * HD;
        w = kw;
    }

    float x0 = base[lane];
    float x1 = base[lane + 32];
    float x2 = base[lane + 64];
    float x3 = base[lane + 96];

    float ss = x0 * x0 + x1 * x1 + x2 * x2 + x3 * x3;
#pragma unroll
    for (int o = 16; o; o >>= 1) ss += __shfl_xor_sync(0xffffffffu, ss, o);
    float inv = rsqrtf(ss * (1.0f / 128.0f) + 1e-6f);

    float n0 = w[lane]      * x0 * inv;
    float n1 = w[lane + 32] * x1 * inv;
    float n2 = w[lane + 64] * x2 * inv;
    float n3 = w[lane + 96] * x3 * inv;

    const float c0 = cosb[s * 64 + lane];
    const float c1 = cosb[s * 64 + lane + 32];
    const float s0 = sinb[s * 64 + lane];
    const float s1 = sinb[s * 64 + lane + 32];

    base[lane]      = n0 * c0 - n2 * s0;
    base[lane + 32] = n1 * c1 - n3 * s1;
    base[lane + 64] = n2 * c0 + n0 * s0;
    base[lane + 96] = n3 * c1 + n1 * s1;
}

// ---------------------------------------------------------------------------
// Tensor-core flash attention.
// QK^T: bf16 3-term (softmax-amplified path, kept exact to 2^-16).
// P.V : fp16 2-term (P = ph+pl fp16 exact; V single fp16 plane, 2^-12 linear).
// Double-buffered K/V; register-direct P fragments; fp16 hi/lo epilogue.
// smem halves: Qhi 17408, Qlo 17408; per KV buf: Khi 8704, Klo 8704, Vh 9216.
// ---------------------------------------------------------------------------
#define OFF_QHI  0
#define OFF_QLO  17408
#define OFF_KV   34816
#define KVBUF    26624
#define FLASH_SMEM_TC ((OFF_KV + 2 * KVBUF) * 2)   // 176128 B

__global__ __launch_bounds__(256, 1)
void flash_attn_tc()
{
    extern __shared__ __nv_bfloat16 smb[];
    __nv_bfloat16* Qhi = smb + OFF_QHI;
    __nv_bfloat16* Qlo = smb + OFF_QLO;

    const int qt  = 15 - blockIdx.x;
    const int h   = blockIdx.y;
    const int q0  = qt * 128;
    const int kvh = h >> 2;
    const int tid  = threadIdx.x;
    const int warp = tid >> 5;
    const int lane = tid & 31;
    const int g = lane >> 2;
    const int t = lane & 3;

    for (int i = tid; i < 128 * 32; i += 256) {
        int r = i >> 5, c = (i & 31) << 2;
        float4 v = *(const float4*)&g_q[(size_t)(q0 + r) * D_MODEL + h * HD + c];
        __nv_bfloat162 h01, l01, h23, l23;
        split2(v.x, v.y, h01, l01);
        split2(v.z, v.w, h23, l23);
        *(__nv_bfloat162*)(Qhi + r * 136 + c)     = h01;
        *(__nv_bfloat162*)(Qhi + r * 136 + c + 2) = h23;
        *(__nv_bfloat162*)(Qlo + r * 136 + c)     = l01;
        *(__nv_bfloat162*)(Qlo + r * 136 + c + 2) = l23;
    }

    float o[16][4];
#pragma unroll
    for (int nt = 0; nt < 16; nt++)
#pragma unroll
        for (int j = 0; j < 4; j++) o[nt][j] = 0.0f;
    float m0 = -1e30f, m1 = -1e30f, l0 = 0.0f, l1 = 0.0f;

    const int wrow = q0 + warp * 16;
    const int nkt  = 2 * qt + 2;

    // K: bf16 hi/lo split rows; V: single fp16, hd-major transpose
#define LOAD_KV(KT, BUF)                                                       \
    {                                                                          \
        __nv_bfloat16* Khi_ = smb + OFF_KV + (BUF) * KVBUF;                    \
        __nv_bfloat16* Klo_ = Khi_ + 8704;                                     \
        __half*        Vh_  = (__half*)(Khi_ + 17408);                         \
        const int k0_ = (KT) * 64;                                             \
        for (int i = tid; i < 64 * 32; i += 256) {                             \
            int r = i >> 5, c = (i & 31) << 2;                                 \
            float4 v = *(const float4*)&g_k[(size_t)(k0_ + r) * KV_DIM + kvh * HD + c]; \
            __nv_bfloat162 h01, l01, h23, l23;                                 \
            split2(v.x, v.y, h01, l01);                                        \
            split2(v.z, v.w, h23, l23);                                        \
            *(__nv_bfloat162*)(Khi_ + r * 136 + c)     = h01;                  \
            *(__nv_bfloat162*)(Khi_ + r * 136 + c + 2) = h23;                  \
            *(__nv_bfloat162*)(Klo_ + r * 136 + c)     = l01;                  \
            *(__nv_bfloat162*)(Klo_ + r * 136 + c + 2) = l23;                  \
        }                                                                      \
        for (int u = tid; u < 1024; u += 256) {                                \
            int p = u & 31, c4 = u >> 5;                                       \
            const float* vp_ = &g_v[(size_t)(k0_ + 2 * p) * KV_DIM + kvh * HD + c4 * 4]; \
            float4 va = *(const float4*)vp_;                                   \
            float4 vb = *(const float4*)(vp_ + KV_DIM);                        \
            _Pragma("unroll")                                                  \
            for (int j = 0; j < 4; j++) {                                      \
                __half2 hv = __floats2half2_rn((&va.x)[j], (&vb.x)[j]);        \
                *(__half2*)(Vh_ + (c4 * 4 + j) * 72 + 2 * p) = hv;             \
            }                                                                  \
        }                                                                      \
    }

    LOAD_KV(0, 0);

    for (int kt = 0; kt < nkt; kt++) {
        const int k0 = kt * 64;
        __syncthreads();
        if (kt + 1 < nkt) LOAD_KV(kt + 1, (kt + 1) & 1);

        if (k0 > wrow + 15) continue;

        const __nv_bfloat16* Khi = smb + OFF_KV + (kt & 1) * KVBUF;
        const __nv_bfloat16* Klo = Khi + 8704;
        const __half*        Vh  = (const __half*)(Khi + 17408);

        // ---- S = Q K^T (bf16 3-term) ----
        float s[8][4];
#pragma unroll
        for (int nt = 0; nt < 8; nt++)
#pragma unroll
            for (int j = 0; j < 4; j++) s[nt][j] = 0.0f;

        const __nv_bfloat16* qrh = Qhi + (warp * 16 + g) * 136 + 2 * t;
        const __nv_bfloat16* qrl = Qlo + (warp * 16 + g) * 136 + 2 * t;
#pragma unroll
        for (int c = 0; c < 8; c++) {
            uint32_t ah0 = *(const uint32_t*)(qrh + c * 16);
            uint32_t ah1 = *(const uint32_t*)(qrh + 8 * 136 + c * 16);
            uint32_t ah2 = *(const uint32_t*)(qrh + c * 16 + 8);
            uint32_t ah3 = *(const uint32_t*)(qrh + 8 * 136 + c * 16 + 8);
            uint32_t al0 = *(const uint32_t*)(qrl + c * 16);
            uint32_t al1 = *(const uint32_t*)(qrl + 8 * 136 + c * 16);
            uint32_t al2 = *(const uint32_t*)(qrl + c * 16 + 8);
            uint32_t al3 = *(const uint32_t*)(qrl + 8 * 136 + c * 16 + 8);
#pragma unroll
            for (int nt = 0; nt < 8; nt++) {
                const __nv_bfloat16* kp  = Khi + (nt * 8 + g) * 136 + c * 16 + 2 * t;
                const __nv_bfloat16* kpl = Klo + (nt * 8 + g) * 136 + c * 16 + 2 * t;
                uint32_t bh0 = *(const uint32_t*)(kp);
                uint32_t bh1 = *(const uint32_t*)(kp + 8);
                uint32_t bl0 = *(const uint32_t*)(kpl);
                uint32_t bl1 = *(const uint32_t*)(kpl + 8);
                mma_bf16(s[nt], ah0, ah1, ah2, ah3, bh0, bh1);
                mma_bf16(s[nt], ah0, ah1, ah2, ah3, bl0, bl1);
                mma_bf16(s[nt], al0, al1, al2, al3, bh0, bh1);
            }
        }

        if (k0 + 63 > wrow) {
            int r0 = wrow + g, r1 = r0 + 8;
#pragma unroll
            for (int nt = 0; nt < 8; nt++) {
                int c0 = k0 + nt * 8 + 2 * t;
                s[nt][0] = (c0     > r0) ? -1e30f : s[nt][0] * SCALE_F;
                s[nt][1] = (c0 + 1 > r0) ? -1e30f : s[nt][1] * SCALE_F;
                s[nt][2] = (c0     > r1) ? -1e30f : s[nt][2] * SCALE_F;
                s[nt][3] = (c0 + 1 > r1) ? -1e30f : s[nt][3] * SCALE_F;
            }
        } else {
#pragma unroll
            for (int nt = 0; nt < 8; nt++)
#pragma unroll
                for (int j = 0; j < 4; j++) s[nt][j] *= SCALE_F;
        }

        float mx0 = -1e30f, mx1 = -1e30f;
#pragma unroll
        for (int nt = 0; nt < 8; nt++) {
            mx0 = fmaxf(mx0, fmaxf(s[nt][0], s[nt][1]));
            mx1 = fmaxf(mx1, fmaxf(s[nt][2], s[nt][3]));
        }
        mx0 = fmaxf(mx0, __shfl_xor_sync(0xffffffffu, mx0, 1));
        mx0 = fmaxf(mx0, __shfl_xor_sync(0xffffffffu, mx0, 2));
        mx1 = fmaxf(mx1, __shfl_xor_sync(0xffffffffu, mx1, 1));
        mx1 = fmaxf(mx1, __shfl_xor_sync(0xffffffffu, mx1, 2));

        float mn0 = fmaxf(m0, mx0), mn1 = fmaxf(m1, mx1);
        float a0 = __expf(m0 - mn0), a1 = __expf(m1 - mn1);
        m0 = mn0; m1 = mn1;

        float sum0 = 0.0f, sum1 = 0.0f;
#pragma unroll
        for (int nt = 0; nt < 8; nt++) {
            s[nt][0] = __expf(s[nt][0] - m0);
            s[nt][1] = __expf(s[nt][1] - m0);
            s[nt][2] = __expf(s[nt][2] - m1);
            s[nt][3] = __expf(s[nt][3] - m1);
            sum0 += s[nt][0] + s[nt][1];
            sum1 += s[nt][2] + s[nt][3];
        }
        sum0 += __shfl_xor_sync(0xffffffffu, sum0, 1);
        sum0 += __shfl_xor_sync(0xffffffffu, sum0, 2);
        sum1 += __shfl_xor_sync(0xffffffffu, sum1, 1);
        sum1 += __shfl_xor_sync(0xffffffffu, sum1, 2);
        l0 = l0 * a0 + sum0;
        l1 = l1 * a1 + sum1;

#pragma unroll
        for (int nt = 0; nt < 16; nt++) {
            o[nt][0] *= a0; o[nt][1] *= a0;
            o[nt][2] *= a1; o[nt][3] *= a1;
        }

        // ---- O += P V (fp16: P 2-term split, V single) ----
#pragma unroll
        for (int c = 0; c < 4; c++) {
            __half2 h0, lo0, h1, lo1, h2, lo2, h3, lo3;
            split2h(s[2 * c][0],     s[2 * c][1],     h0, lo0);   // (g,   k=2t)
            split2h(s[2 * c][2],     s[2 * c][3],     h1, lo1);   // (g+8, k=2t)
            split2h(s[2 * c + 1][0], s[2 * c + 1][1], h2, lo2);   // (g,   k=2t+8)
            split2h(s[2 * c + 1][2], s[2 * c + 1][3], h3, lo3);   // (g+8, k=2t+8)
            uint32_t ph0 = h2u(h0), ph1 = h2u(h1), ph2 = h2u(h2), ph3 = h2u(h3);
            uint32_t pl0 = h2u(lo0), pl1 = h2u(lo1), pl2 = h2u(lo2), pl3 = h2u(lo3);
#pragma unroll
            for (int nt = 0; nt < 16; nt++) {
                const __half* vp = Vh + (nt * 8 + g) * 72 + c * 16 + 2 * t;
                uint32_t vh0 = *(const uint32_t*)(vp);
                uint32_t vh1 = *(const uint32_t*)(vp + 8);
                mma_f16(o[nt], ph0, ph1, ph2, ph3, vh0, vh1);
                mma_f16(o[nt], pl0, pl1, pl2, pl3, vh0, vh1);
            }
        }
    }

    // ---- normalize + write attn output as fp16 hi/lo planes ----
    float inv0 = 1.0f / l0, inv1 = 1.0f / l1;
    int row0 = q0 + warp * 16 + g;
#pragma unroll
    for (int nt = 0; nt < 16; nt++) {
        int col = h * HD + nt * 8 + 2 * t;
        float f0 = o[nt][0] * inv0, f1 = o[nt][1] * inv0;
        float f2 = o[nt][2] * inv1, f3 = o[nt][3] * inv1;
        __half2 hA, lA, hB, lB;
        split2h(f0, f1, hA, lA);
        split2h(f2, f3, hB, lB);
        *(uint32_t*)&g_ah[(size_t)row0 * D_MODEL + col]       = h2u(hA);
        *(uint32_t*)&g_al[(size_t)row0 * D_MODEL + col]       = h2u(lA);
        *(uint32_t*)&g_ah[(size_t)(row0 + 8) * D_MODEL + col] = h2u(hB);
        *(uint32_t*)&g_al[(size_t)(row0 + 8) * D_MODEL + col] = h2u(lB);
    }
#undef LOAD_KV
}

// ---------------------------------------------------------------------------
extern "C" void kernel_launch(void* const* d_in, const int* in_sizes, int n_in,
                              void* d_out, int out_size)
{
    const float* hidden = (const float*)d_in[0];
    const float* cosb   = (const float*)d_in[1];
    const float* sinb   = (const float*)d_in[2];
    const float* Wq = (const float*)d_in[4];
    const float* Wk = (const float*)d_in[5];
    const float* Wv = (const float*)d_in[6];
    const float* Wo = (const float*)d_in[7];
    const float* qw = (const float*)d_in[8];
    const float* kw = (const float*)d_in[9];
    float* out = (float*)d_out;

    cudaFuncSetAttribute(hgemm_qkv, cudaFuncAttributeMaxDynamicSharedMemorySize, HGEMM_SMEM);
    cudaFuncSetAttribute(hgemm_o,   cudaFuncAttributeMaxDynamicSharedMemorySize, HGEMM_SMEM);
    cudaFuncSetAttribute(flash_attn_tc, cudaFuncAttributeMaxDynamicSharedMemorySize, FLASH_SMEM_TC);

    // pre-pass: one launch for all splits/conversions
    split_all<<<2048, 256>>>((const float4*)hidden, (const float4*)Wq,
                             (const float4*)Wk, (const float4*)Wv,
                             (const float4*)Wo);

    // projections
    hgemm_qkv<<<768, 256, HGEMM_SMEM>>>();

    rmsnorm_rope<<<10240, 256>>>(cosb, sinb, qw, kw);

    flash_attn_tc<<<dim3(16, 32), 256, FLASH_SMEM_TC>>>();

    hgemm_o<<<dim3(32, 16), 256, HGEMM_SMEM>>>(out);
}

// round 11
// speedup vs baseline: 5.4286x; 1.1562x over previous
#include <cuda_runtime.h>
#include <cuda_fp16.h>
#include <math.h>
#include <stdint.h>

#define S_LEN   2048
#define D_MODEL 4096
#define NQH     32
#define NKVH    8
#define HD      128
#define KV_DIM  1024
#define SCALE_F 0.08838834764831845f   // 128^-0.5

// fp32 QKV projection outputs
__device__ float g_q[S_LEN * D_MODEL];
__device__ float g_k[S_LEN * KV_DIM];
__device__ float g_v[S_LEN * KV_DIM];
// fp16 split planes (GEMM inputs)
__device__ __half g_hh[S_LEN * D_MODEL];
__device__ __half g_hl[S_LEN * D_MODEL];
__device__ __half g_wqh[D_MODEL * D_MODEL];
__device__ __half g_wkh[KV_DIM * D_MODEL];
__device__ __half g_wvh[KV_DIM * D_MODEL];
__device__ __half g_woh[D_MODEL * D_MODEL];
__device__ __half g_ah[S_LEN * D_MODEL];   // attn out hi
__device__ __half g_al[S_LEN * D_MODEL];   // attn out lo
// fp16 flash inputs (produced by rmsnorm_rope / vtrans)
__device__ __half g_qh[S_LEN * D_MODEL];   // q hi
__device__ __half g_ql[S_LEN * D_MODEL];   // q lo
__device__ __half g_kh[S_LEN * KV_DIM];    // k single fp16
__device__ __half g_vt[KV_DIM * S_LEN];    // v transposed [kv*128+d][s]

// ---------------------------------------------------------------------------
// helpers
// ---------------------------------------------------------------------------
__device__ __forceinline__ void mma_f16(float (&d)[4],
    uint32_t a0, uint32_t a1, uint32_t a2, uint32_t a3,
    uint32_t b0, uint32_t b1) {
    asm volatile(
        "mma.sync.aligned.m16n8k16.row.col.f32.f16.f16.f32 "
        "{%0,%1,%2,%3}, {%4,%5,%6,%7}, {%8,%9}, {%0,%1,%2,%3};\n"
        : "+f"(d[0]), "+f"(d[1]), "+f"(d[2]), "+f"(d[3])
        : "r"(a0), "r"(a1), "r"(a2), "r"(a3), "r"(b0), "r"(b1));
}

__device__ __forceinline__ void ldsm4(uint32_t (&r)[4], uint32_t addr) {
    asm volatile("ldmatrix.sync.aligned.m8n8.x4.shared.b16 {%0,%1,%2,%3}, [%4];"
        : "=r"(r[0]), "=r"(r[1]), "=r"(r[2]), "=r"(r[3]) : "r"(addr));
}

__device__ __forceinline__ void split2h(float x0, float x1,
                                        __half2& hi, __half2& lo) {
    hi = __floats2half2_rn(x0, x1);
    float2 hf = __half22float2(hi);
    lo = __floats2half2_rn(x0 - hf.x, x1 - hf.y);
}

__device__ __forceinline__ uint32_t h2u(__half2 v) {
    return *reinterpret_cast<uint32_t*>(&v);
}

// ---------------------------------------------------------------------------
// pre-pass: all fp32->fp16 conversions in ONE launch (unchanged from R10)
// ---------------------------------------------------------------------------
#define SEG0 (2 * 1024 * 1024)
#define SEG1 (SEG0 + 4 * 1024 * 1024)
#define SEG2 (SEG1 + 1024 * 1024)
#define SEG3 (SEG2 + 1024 * 1024)
#define SEG4 (SEG3 + 4 * 1024 * 1024)

__global__ __launch_bounds__(256)
void split_all(const float4* __restrict__ hidden, const float4* __restrict__ Wq,
               const float4* __restrict__ Wk, const float4* __restrict__ Wv,
               const float4* __restrict__ Wo)
{
    int stride = gridDim.x * blockDim.x;
    for (int i = blockIdx.x * blockDim.x + threadIdx.x; i < SEG4; i += stride) {
        const float4* src;
        uint2 *hi, *lo = nullptr;
        int off;
        if (i < SEG0)      { src = hidden; off = i;        hi = (uint2*)g_hh; lo = (uint2*)g_hl; }
        else if (i < SEG1) { src = Wq;     off = i - SEG0; hi = (uint2*)g_wqh; }
        else if (i < SEG2) { src = Wk;     off = i - SEG1; hi = (uint2*)g_wkh; }
        else if (i < SEG3) { src = Wv;     off = i - SEG2; hi = (uint2*)g_wvh; }
        else               { src = Wo;     off = i - SEG3; hi = (uint2*)g_woh; }
        float4 v = src[off];
        __half2 h01 = __floats2half2_rn(v.x, v.y);
        __half2 h23 = __floats2half2_rn(v.z, v.w);
        hi[off] = make_uint2(h2u(h01), h2u(h23));
        if (lo) {
            float2 f01 = __half22float2(h01);
            float2 f23 = __half22float2(h23);
            lo[off] = make_uint2(
                h2u(__floats2half2_rn(v.x - f01.x, v.y - f01.y)),
                h2u(__floats2half2_rn(v.z - f23.x, v.w - f23.y)));
        }
    }
}

// ---------------------------------------------------------------------------
// fp16 2-term GEMM NT with cp.async (unchanged from R9/R10)
// ---------------------------------------------------------------------------
#define LDBH   40
#define AP_H   (128 * LDBH)
#define STG_B  (3 * AP_H * 2)
#define HGEMM_SMEM (3 * STG_B)           // 92160 B

__device__ __forceinline__ void hgemm_body(const __half* __restrict__ Ah,
                                           const __half* __restrict__ Al,
                                           const __half* __restrict__ Bh,
                                           float* __restrict__ C,
                                           int N, int K, int bx, int by)
{
    extern __shared__ char smc[];
    const uint32_t smem_u32 = (uint32_t)__cvta_generic_to_shared(smc);

    const int tid  = threadIdx.x;
    const int warp = tid >> 5;
    const int lane = tid & 31;
    const int g    = lane >> 2;
    const int t    = lane & 3;
    const int wm   = (warp & 3) * 32;
    const int wn   = (warp >> 2) * 64;

    uint32_t dst_off[6];
    const __half* src[6];
#pragma unroll
    for (int j = 0; j < 6; j++) {
        int cid = tid + j * 256;
        if (cid < 1024) {
            int plane = cid >> 9;
            int r = (cid & 511) >> 2;
            int c = cid & 3;
            dst_off[j] = (uint32_t)(plane * AP_H + r * LDBH + c * 8) * 2;
            src[j] = (plane ? Al : Ah) + (size_t)(by * 128 + r) * K + c * 8;
        } else {
            int b = cid - 1024;
            int r = b >> 2, c = b & 3;
            dst_off[j] = (uint32_t)(2 * AP_H + r * LDBH + c * 8) * 2;
            src[j] = Bh + (size_t)(bx * 128 + r) * K + c * 8;
        }
    }

    const int lane8 = lane & 7;
    const uint32_t a_off = (uint32_t)(((wm + lane8 + ((lane >> 3) & 1) * 8) * LDBH
                                      + (lane >> 4) * 8) * 2);
    const uint32_t b_off = (uint32_t)((2 * AP_H + (wn + lane8 + (lane >> 4) * 8) * LDBH
                                      + ((lane >> 3) & 1) * 8) * 2);

    float acc[2][8][4];
#pragma unroll
    for (int mt = 0; mt < 2; mt++)
#pragma unroll
        for (int nt = 0; nt < 8; nt++)
#pragma unroll
            for (int c = 0; c < 4; c++) acc[mt][nt][c] = 0.0f;

    const int nk = K / 32;

#define CP_ISSUE(KT)                                                           \
    {                                                                          \
        uint32_t sb_ = smem_u32 + (uint32_t)(((KT) % 3) * STG_B);              \
        _Pragma("unroll")                                                      \
        for (int j = 0; j < 6; j++) {                                          \
            asm volatile("cp.async.cg.shared.global [%0], [%1], 16;"           \
                :: "r"(sb_ + dst_off[j]), "l"(src[j] + (KT) * 32) : "memory"); \
        }                                                                      \
    }
#define CP_COMMIT() asm volatile("cp.async.commit_group;" ::: "memory")

    CP_ISSUE(0); CP_COMMIT();
    CP_ISSUE(1); CP_COMMIT();

    for (int kt = 0; kt < nk; kt++) {
        asm volatile("cp.async.wait_group 1;" ::: "memory");
        __syncthreads();

        const uint32_t sb = smem_u32 + (uint32_t)((kt % 3) * STG_B);

#pragma unroll
        for (int k16 = 0; k16 < 2; k16++) {
            uint32_t ah[2][4], al[2][4];
            ldsm4(ah[0], sb + a_off + k16 * 32);
            ldsm4(ah[1], sb + a_off + 16 * LDBH * 2 + k16 * 32);
            ldsm4(al[0], sb + AP_H * 2 + a_off + k16 * 32);
            ldsm4(al[1], sb + AP_H * 2 + a_off + 16 * LDBH * 2 + k16 * 32);

#pragma unroll
            for (int jh = 0; jh < 2; jh++) {
                uint32_t bh[2][4];
#pragma unroll
                for (int jj = 0; jj < 2; jj++) {
                    int j = jh * 2 + jj;
                    ldsm4(bh[jj], sb + b_off + j * 16 * LDBH * 2 + k16 * 32);
                }
#pragma unroll
                for (int mt = 0; mt < 2; mt++)
#pragma unroll
                    for (int jj = 0; jj < 2; jj++) {
                        int nt = (jh * 2 + jj) * 2;
                        float (&d0)[4] = acc[mt][nt];
                        float (&d1)[4] = acc[mt][nt + 1];
                        mma_f16(d0, al[mt][0], al[mt][1], al[mt][2], al[mt][3],
                                bh[jj][0], bh[jj][1]);
                        mma_f16(d0, ah[mt][0], ah[mt][1], ah[mt][2], ah[mt][3],
                                bh[jj][0], bh[jj][1]);
                        mma_f16(d1, al[mt][0], al[mt][1], al[mt][2], al[mt][3],
                                bh[jj][2], bh[jj][3]);
                        mma_f16(d1, ah[mt][0], ah[mt][1], ah[mt][2], ah[mt][3],
                                bh[jj][2], bh[jj][3]);
                    }
            }
        }

        if (kt + 2 < nk) { CP_ISSUE(kt + 2); }
        CP_COMMIT();
    }

#pragma unroll
    for (int mt = 0; mt < 2; mt++) {
        int r0 = by * 128 + wm + mt * 16 + g;
#pragma unroll
        for (int nt = 0; nt < 8; nt++) {
            int c0 = bx * 128 + wn + nt * 8 + 2 * t;
            *(float2*)&C[(size_t)r0 * N + c0] =
                make_float2(acc[mt][nt][0], acc[mt][nt][1]);
            *(float2*)&C[(size_t)(r0 + 8) * N + c0] =
                make_float2(acc[mt][nt][2], acc[mt][nt][3]);
        }
    }
#undef CP_ISSUE
#undef CP_COMMIT
}

__global__ __launch_bounds__(256, 2)
void hgemm_qkv()
{
    int b = blockIdx.x;
    if (b < 512)      hgemm_body(g_hh, g_hl, g_wqh, g_q, 4096, 4096, b & 31, b >> 5);
    else if (b < 640) { int i = b - 512; hgemm_body(g_hh, g_hl, g_wkh, g_k, 1024, 4096, i & 7, i >> 3); }
    else              { int i = b - 640; hgemm_body(g_hh, g_hl, g_wvh, g_v, 1024, 4096, i & 7, i >> 3); }
}

__global__ __launch_bounds__(256, 2)
void hgemm_o(float* __restrict__ out)
{
    hgemm_body(g_ah, g_al, g_woh, out, 4096, 4096, blockIdx.x, blockIdx.y);
}

// ---------------------------------------------------------------------------
// Fused per-head RMSNorm + RoPE; writes fp16 directly:
// Q -> hi/lo planes (g_qh, g_ql);  K -> single fp16 plane (g_kh).
// ---------------------------------------------------------------------------
__global__ __launch_bounds__(256)
void rmsnorm_rope(const float* __restrict__ cosb, const float* __restrict__ sinb,
                  const float* __restrict__ qw, const float* __restrict__ kw)
{
    const int warp = blockIdx.x * 8 + (threadIdx.x >> 5);
    const int lane = threadIdx.x & 31;

    const float* base;
    const float* w;
    int s;
    bool is_q = warp < S_LEN * NQH;
    size_t off;
    if (is_q) {
        s = warp / NQH;
        int h = warp - s * NQH;
        off = (size_t)s * D_MODEL + h * HD;
        base = g_q + off;
        w = qw;
    } else {
        int wv = warp - S_LEN * NQH;
        s = wv / NKVH;
        int h = wv - s * NKVH;
        off = (size_t)s * KV_DIM + h * HD;
        base = g_k + off;
        w = kw;
    }

    float x0 = base[lane];
    float x1 = base[lane + 32];
    float x2 = base[lane + 64];
    float x3 = base[lane + 96];

    float ss = x0 * x0 + x1 * x1 + x2 * x2 + x3 * x3;
#pragma unroll
    for (int o = 16; o; o >>= 1) ss += __shfl_xor_sync(0xffffffffu, ss, o);
    float inv = rsqrtf(ss * (1.0f / 128.0f) + 1e-6f);

    float n0 = w[lane]      * x0 * inv;
    float n1 = w[lane + 32] * x1 * inv;
    float n2 = w[lane + 64] * x2 * inv;
    float n3 = w[lane + 96] * x3 * inv;

    const float c0 = cosb[s * 64 + lane];
    const float c1 = cosb[s * 64 + lane + 32];
    const float s0 = sinb[s * 64 + lane];
    const float s1 = sinb[s * 64 + lane + 32];

    float r0 = n0 * c0 - n2 * s0;
    float r1 = n1 * c1 - n3 * s1;
    float r2 = n2 * c0 + n0 * s0;
    float r3 = n3 * c1 + n1 * s1;

    if (is_q) {
        float rr[4] = {r0, r1, r2, r3};
#pragma unroll
        for (int j = 0; j < 4; j++) {
            __half hv = __float2half_rn(rr[j]);
            g_qh[off + lane + j * 32] = hv;
            g_ql[off + lane + j * 32] = __float2half_rn(rr[j] - __half2float(hv));
        }
    } else {
        g_kh[off + lane]      = __float2half_rn(r0);
        g_kh[off + lane + 32] = __float2half_rn(r1);
        g_kh[off + lane + 64] = __float2half_rn(r2);
        g_kh[off + lane + 96] = __float2half_rn(r3);
    }
}

// ---------------------------------------------------------------------------
// V transpose: g_v fp32 [s][kv*128+d] -> g_vt fp16 [kv*128+d][s]
// ---------------------------------------------------------------------------
__global__ __launch_bounds__(256)
void vtrans()
{
    __shared__ float tile[32][33];
    const int kvh = blockIdx.z;
    const int s0 = blockIdx.x * 32;
    const int d0 = blockIdx.y * 32;
    const int tx = threadIdx.x;        // 0..31
    const int ty = threadIdx.y;        // 0..7

#pragma unroll
    for (int i = 0; i < 4; i++) {
        int sl = ty + i * 8;
        tile[sl][tx] = g_v[(size_t)(s0 + sl) * KV_DIM + kvh * HD + d0 + tx];
    }
    __syncthreads();
#pragma unroll
    for (int i = 0; i < 4; i++) {
        int dl = ty + i * 8;
        g_vt[(size_t)(kvh * HD + d0 + dl) * S_LEN + s0 + tx] =
            __float2half_rn(tile[tx][dl]);
    }
}

// ---------------------------------------------------------------------------
// Tensor-core flash attention v3: pure cp.async loaders, 3-stage KV pipeline.
// QK^T: fp16 2-term (Q hi/lo, K single).  P.V: fp16 2-term (P hi/lo, V single).
// smem halves: Qh 17408, Ql 17408; per KV buf: K 8704 + Vt 9216 = 17920; x3.
// ---------------------------------------------------------------------------
#define OFF_QH   0
#define OFF_QL   17408
#define OFF_FKV  34816
#define FKVBUF   17920
#define FLASH_SMEM_TC ((OFF_FKV + 3 * FKVBUF) * 2)   // 177152 B

__global__ __launch_bounds__(256, 1)
void flash_attn_tc()
{
    extern __shared__ __half smh[];

    const int qt  = 15 - blockIdx.x;
    const int h   = blockIdx.y;
    const int q0  = qt * 128;
    const int kvh = h >> 2;
    const int tid  = threadIdx.x;
    const int warp = tid >> 5;
    const int lane = tid & 31;
    const int g = lane >> 2;
    const int t = lane & 3;

    const uint32_t sbase = (uint32_t)__cvta_generic_to_shared(smh);

#define CP16(DST, SRC)                                                         \
    asm volatile("cp.async.cg.shared.global [%0], [%1], 16;"                   \
                 :: "r"(DST), "l"(SRC) : "memory")
#define CP_COMMIT() asm volatile("cp.async.commit_group;" ::: "memory")

    // KV tile loader: K 64x128 (stride 136) + Vt 128x64 (stride 72), all cp.async
#define LOAD_KV(KT, BUF)                                                       \
    {                                                                          \
        const uint32_t kb_ = sbase + (uint32_t)(OFF_FKV + (BUF) * FKVBUF) * 2; \
        const int k0_ = (KT) * 64;                                             \
        _Pragma("unroll")                                                      \
        for (int j = 0; j < 8; j++) {                                          \
            int cid = tid + j * 256;                                           \
            if (cid < 1024) {                                                  \
                int r = cid >> 4, c = cid & 15;                                \
                CP16(kb_ + (uint32_t)(r * 136 + c * 8) * 2,                    \
                     g_kh + (size_t)(k0_ + r) * KV_DIM + kvh * HD + c * 8);    \
            } else {                                                           \
                int b = cid - 1024;                                            \
                int r = b >> 3, c = b & 7;                                     \
                CP16(kb_ + (uint32_t)(8704 + r * 72 + c * 8) * 2,              \
                     g_vt + (size_t)(kvh * HD + r) * S_LEN + k0_ + c * 8);     \
            }                                                                  \
        }                                                                      \
    }

    // prologue: Q (hi+lo) + KV tile 0 in group 0; KV tile 1 in group 1
#pragma unroll
    for (int j = 0; j < 16; j++) {
        int cid = tid + j * 256;
        int plane = cid >> 11;
        int rem = cid & 2047;
        int r = rem >> 4, c = rem & 15;
        CP16(sbase + (uint32_t)((plane ? OFF_QL : OFF_QH) + r * 136 + c * 8) * 2,
             (plane ? g_ql : g_qh) + (size_t)(q0 + r) * D_MODEL + h * HD + c * 8);
    }
    LOAD_KV(0, 0);
    CP_COMMIT();
    LOAD_KV(1, 1);
    CP_COMMIT();

    float o[16][4];
#pragma unroll
    for (int nt = 0; nt < 16; nt++)
#pragma unroll
        for (int j = 0; j < 4; j++) o[nt][j] = 0.0f;
    float m0 = -1e30f, m1 = -1e30f, l0 = 0.0f, l1 = 0.0f;

    const int wrow = q0 + warp * 16;
    const int nkt  = 2 * qt + 2;

    const __half* qrh = smh + OFF_QH + (warp * 16 + g) * 136 + 2 * t;
    const __half* qrl = smh + OFF_QL + (warp * 16 + g) * 136 + 2 * t;

    for (int kt = 0; kt < nkt; kt++) {
        const int k0 = kt * 64;
        asm volatile("cp.async.wait_group 1;" ::: "memory");
        __syncthreads();
        if (kt + 2 < nkt) LOAD_KV(kt + 2, (kt + 2) % 3);
        CP_COMMIT();

        if (k0 > wrow + 15) continue;

        const __half* Kh = smh + OFF_FKV + (kt % 3) * FKVBUF;
        const __half* Vh = Kh + 8704;

        // ---- S = Q K^T (fp16 2-term: Qhi*K + Qlo*K) ----
        float s[8][4];
#pragma unroll
        for (int nt = 0; nt < 8; nt++)
#pragma unroll
            for (int j = 0; j < 4; j++) s[nt][j] = 0.0f;

#pragma unroll
        for (int c = 0; c < 8; c++) {
            uint32_t ah0 = *(const uint32_t*)(qrh + c * 16);
            uint32_t ah1 = *(const uint32_t*)(qrh + 8 * 136 + c * 16);
            uint32_t ah2 = *(const uint32_t*)(qrh + c * 16 + 8);
            uint32_t ah3 = *(const uint32_t*)(qrh + 8 * 136 + c * 16 + 8);
            uint32_t al0 = *(const uint32_t*)(qrl + c * 16);
            uint32_t al1 = *(const uint32_t*)(qrl + 8 * 136 + c * 16);
            uint32_t al2 = *(const uint32_t*)(qrl + c * 16 + 8);
            uint32_t al3 = *(const uint32_t*)(qrl + 8 * 136 + c * 16 + 8);
#pragma unroll
            for (int nt = 0; nt < 8; nt++) {
                const __half* kp = Kh + (nt * 8 + g) * 136 + c * 16 + 2 * t;
                uint32_t b0 = *(const uint32_t*)(kp);
                uint32_t b1 = *(const uint32_t*)(kp + 8);
                mma_f16(s[nt], al0, al1, al2, al3, b0, b1);
                mma_f16(s[nt], ah0, ah1, ah2, ah3, b0, b1);
            }
        }

        // ---- scale + causal mask ----
        if (k0 + 63 > wrow) {
            int r0 = wrow + g, r1 = r0 + 8;
#pragma unroll
            for (int nt = 0; nt < 8; nt++) {
                int c0 = k0 + nt * 8 + 2 * t;
                s[nt][0] = (c0     > r0) ? -1e30f : s[nt][0] * SCALE_F;
                s[nt][1] = (c0 + 1 > r0) ? -1e30f : s[nt][1] * SCALE_F;
                s[nt][2] = (c0     > r1) ? -1e30f : s[nt][2] * SCALE_F;
                s[nt][3] = (c0 + 1 > r1) ? -1e30f : s[nt][3] * SCALE_F;
            }
        } else {
#pragma unroll
            for (int nt = 0; nt < 8; nt++)
#pragma unroll
                for (int j = 0; j < 4; j++) s[nt][j] *= SCALE_F;
        }

        // ---- online softmax ----
        float mx0 = -1e30f, mx1 = -1e30f;
#pragma unroll
        for (int nt = 0; nt < 8; nt++) {
            mx0 = fmaxf(mx0, fmaxf(s[nt][0], s[nt][1]));
            mx1 = fmaxf(mx1, fmaxf(s[nt][2], s[nt][3]));
        }
        mx0 = fmaxf(mx0, __shfl_xor_sync(0xffffffffu, mx0, 1));
        mx0 = fmaxf(mx0, __shfl_xor_sync(0xffffffffu, mx0, 2));
        mx1 = fmaxf(mx1, __shfl_xor_sync(0xffffffffu, mx1, 1));
        mx1 = fmaxf(mx1, __shfl_xor_sync(0xffffffffu, mx1, 2));

        float mn0 = fmaxf(m0, mx0), mn1 = fmaxf(m1, mx1);
        float a0 = __expf(m0 - mn0), a1 = __expf(m1 - mn1);
        m0 = mn0; m1 = mn1;

        float sum0 = 0.0f, sum1 = 0.0f;
#pragma unroll
        for (int nt = 0; nt < 8; nt++) {
            s[nt][0] = __expf(s[nt][0] - m0);
            s[nt][1] = __expf(s[nt][1] - m0);
            s[nt][2] = __expf(s[nt][2] - m1);
            s[nt][3] = __expf(s[nt][3] - m1);
            sum0 += s[nt][0] + s[nt][1];
            sum1 += s[nt][2] + s[nt][3];
        }
        sum0 += __shfl_xor_sync(0xffffffffu, sum0, 1);
        sum0 += __shfl_xor_sync(0xffffffffu, sum0, 2);
        sum1 += __shfl_xor_sync(0xffffffffu, sum1, 1);
        sum1 += __shfl_xor_sync(0xffffffffu, sum1, 2);
        l0 = l0 * a0 + sum0;
        l1 = l1 * a1 + sum1;

#pragma unroll
        for (int nt = 0; nt < 16; nt++) {
            o[nt][0] *= a0; o[nt][1] *= a0;
            o[nt][2] *= a1; o[nt][3] *= a1;
        }

        // ---- O += P V (fp16: P 2-term split, V single) ----
#pragma unroll
        for (int c = 0; c < 4; c++) {
            __half2 h0, lo0, h1, lo1, h2, lo2, h3, lo3;
            split2h(s[2 * c][0],     s[2 * c][1],     h0, lo0);
            split2h(s[2 * c][2],     s[2 * c][3],     h1, lo1);
            split2h(s[2 * c + 1][0], s[2 * c + 1][1], h2, lo2);
            split2h(s[2 * c + 1][2], s[2 * c + 1][3], h3, lo3);
            uint32_t ph0 = h2u(h0), ph1 = h2u(h1), ph2 = h2u(h2), ph3 = h2u(h3);
            uint32_t pl0 = h2u(lo0), pl1 = h2u(lo1), pl2 = h2u(lo2), pl3 = h2u(lo3);
#pragma unroll
            for (int nt = 0; nt < 16; nt++) {
                const __half* vp = Vh + (nt * 8 + g) * 72 + c * 16 + 2 * t;
                uint32_t vh0 = *(const uint32_t*)(vp);
                uint32_t vh1 = *(const uint32_t*)(vp + 8);
                mma_f16(o[nt], ph0, ph1, ph2, ph3, vh0, vh1);
                mma_f16(o[nt], pl0, pl1, pl2, pl3, vh0, vh1);
            }
        }
    }

    // ---- normalize + write attn output as fp16 hi/lo planes ----
    float inv0 = 1.0f / l0, inv1 = 1.0f / l1;
    int row0 = q0 + warp * 16 + g;
#pragma unroll
    for (int nt = 0; nt < 16; nt++) {
        int col = h * HD + nt * 8 + 2 * t;
        float f0 = o[nt][0] * inv0, f1 = o[nt][1] * inv0;
        float f2 = o[nt][2] * inv1, f3 = o[nt][3] * inv1;
        __half2 hA, lA, hB, lB;
        split2h(f0, f1, hA, lA);
        split2h(f2, f3, hB, lB);
        *(uint32_t*)&g_ah[(size_t)row0 * D_MODEL + col]       = h2u(hA);
        *(uint32_t*)&g_al[(size_t)row0 * D_MODEL + col]       = h2u(lA);
        *(uint32_t*)&g_ah[(size_t)(row0 + 8) * D_MODEL + col] = h2u(hB);
        *(uint32_t*)&g_al[(size_t)(row0 + 8) * D_MODEL + col] = h2u(lB);
    }
#undef LOAD_KV
#undef CP16
#undef CP_COMMIT
}

// ---------------------------------------------------------------------------
extern "C" void kernel_launch(void* const* d_in, const int* in_sizes, int n_in,
                              void* d_out, int out_size)
{
    const float* hidden = (const float*)d_in[0];
    const float* cosb   = (const float*)d_in[1];
    const float* sinb   = (const float*)d_in[2];
    const float* Wq = (const float*)d_in[4];
    const float* Wk = (const float*)d_in[5];
    const float* Wv = (const float*)d_in[6];
    const float* Wo = (const float*)d_in[7];
    const float* qw = (const float*)d_in[8];
    const float* kw = (const float*)d_in[9];
    float* out = (float*)d_out;

    cudaFuncSetAttribute(hgemm_qkv, cudaFuncAttributeMaxDynamicSharedMemorySize, HGEMM_SMEM);
    cudaFuncSetAttribute(hgemm_o,   cudaFuncAttributeMaxDynamicSharedMemorySize, HGEMM_SMEM);
    cudaFuncSetAttribute(flash_attn_tc, cudaFuncAttributeMaxDynamicSharedMemorySize, FLASH_SMEM_TC);

    split_all<<<2048, 256>>>((const float4*)hidden, (const float4*)Wq,
                             (const float4*)Wk, (const float4*)Wv,
                             (const float4*)Wo);

    hgemm_qkv<<<768, 256, HGEMM_SMEM>>>();

    rmsnorm_rope<<<10240, 256>>>(cosb, sinb, qw, kw);
    vtrans<<<dim3(64, 4, 8), dim3(32, 8)>>>();

    flash_attn_tc<<<dim3(16, 32), 256, FLASH_SMEM_TC>>>();

    hgemm_o<<<dim3(32, 16), 256, HGEMM_SMEM>>>(out);
}

// round 12
// speedup vs baseline: 6.2340x; 1.1484x over previous
#include <cuda_runtime.h>
#include <cuda_fp16.h>
#include <math.h>
#include <stdint.h>

#define S_LEN   2048
#define D_MODEL 4096
#define NQH     32
#define NKVH    8
#define HD      128
#define KV_DIM  1024
#define SCALE_F 0.08838834764831845f   // 128^-0.5

// fp32 QKV projection outputs
__device__ float g_q[S_LEN * D_MODEL];
__device__ float g_k[S_LEN * KV_DIM];
__device__ float g_v[S_LEN * KV_DIM];
// fp16 split planes (GEMM inputs)
__device__ __half g_hh[S_LEN * D_MODEL];
__device__ __half g_hl[S_LEN * D_MODEL];
__device__ __half g_wqh[D_MODEL * D_MODEL];
__device__ __half g_wkh[KV_DIM * D_MODEL];
__device__ __half g_wvh[KV_DIM * D_MODEL];
__device__ __half g_woh[D_MODEL * D_MODEL];
__device__ __half g_ah[S_LEN * D_MODEL];   // attn out hi
__device__ __half g_al[S_LEN * D_MODEL];   // attn out lo
// fp16 flash inputs
__device__ __half g_qh[S_LEN * D_MODEL];   // q single fp16
__device__ __half g_kh[S_LEN * KV_DIM];    // k single fp16
__device__ __half g_vt[KV_DIM * S_LEN];    // v transposed [kv*128+d][s]

// ---------------------------------------------------------------------------
// helpers
// ---------------------------------------------------------------------------
__device__ __forceinline__ void mma_f16(float (&d)[4],
    uint32_t a0, uint32_t a1, uint32_t a2, uint32_t a3,
    uint32_t b0, uint32_t b1) {
    asm volatile(
        "mma.sync.aligned.m16n8k16.row.col.f32.f16.f16.f32 "
        "{%0,%1,%2,%3}, {%4,%5,%6,%7}, {%8,%9}, {%0,%1,%2,%3};\n"
        : "+f"(d[0]), "+f"(d[1]), "+f"(d[2]), "+f"(d[3])
        : "r"(a0), "r"(a1), "r"(a2), "r"(a3), "r"(b0), "r"(b1));
}

__device__ __forceinline__ void ldsm4(uint32_t (&r)[4], uint32_t addr) {
    asm volatile("ldmatrix.sync.aligned.m8n8.x4.shared.b16 {%0,%1,%2,%3}, [%4];"
        : "=r"(r[0]), "=r"(r[1]), "=r"(r[2]), "=r"(r[3]) : "r"(addr));
}

__device__ __forceinline__ void split2h(float x0, float x1,
                                        __half2& hi, __half2& lo) {
    hi = __floats2half2_rn(x0, x1);
    float2 hf = __half22float2(hi);
    lo = __floats2half2_rn(x0 - hf.x, x1 - hf.y);
}

__device__ __forceinline__ uint32_t h2u(__half2 v) {
    return *reinterpret_cast<uint32_t*>(&v);
}

// ---------------------------------------------------------------------------
// pre-pass: all fp32->fp16 conversions in ONE launch
// ---------------------------------------------------------------------------
#define SEG0 (2 * 1024 * 1024)
#define SEG1 (SEG0 + 4 * 1024 * 1024)
#define SEG2 (SEG1 + 1024 * 1024)
#define SEG3 (SEG2 + 1024 * 1024)
#define SEG4 (SEG3 + 4 * 1024 * 1024)

__global__ __launch_bounds__(256)
void split_all(const float4* __restrict__ hidden, const float4* __restrict__ Wq,
               const float4* __restrict__ Wk, const float4* __restrict__ Wv,
               const float4* __restrict__ Wo)
{
    int stride = gridDim.x * blockDim.x;
    for (int i = blockIdx.x * blockDim.x + threadIdx.x; i < SEG4; i += stride) {
        const float4* src;
        uint2 *hi, *lo = nullptr;
        int off;
        if (i < SEG0)      { src = hidden; off = i;        hi = (uint2*)g_hh; lo = (uint2*)g_hl; }
        else if (i < SEG1) { src = Wq;     off = i - SEG0; hi = (uint2*)g_wqh; }
        else if (i < SEG2) { src = Wk;     off = i - SEG1; hi = (uint2*)g_wkh; }
        else if (i < SEG3) { src = Wv;     off = i - SEG2; hi = (uint2*)g_wvh; }
        else               { src = Wo;     off = i - SEG3; hi = (uint2*)g_woh; }
        float4 v = src[off];
        __half2 h01 = __floats2half2_rn(v.x, v.y);
        __half2 h23 = __floats2half2_rn(v.z, v.w);
        hi[off] = make_uint2(h2u(h01), h2u(h23));
        if (lo) {
            float2 f01 = __half22float2(h01);
            float2 f23 = __half22float2(h23);
            lo[off] = make_uint2(
                h2u(__floats2half2_rn(v.x - f01.x, v.y - f01.y)),
                h2u(__floats2half2_rn(v.z - f23.x, v.w - f23.y)));
        }
    }
}

// ---------------------------------------------------------------------------
// fp16 GEMM NT with cp.async. twoA=true: C = (Ah+Al) @ Bh^T (2-term);
// twoA=false: C = Ah @ Bh^T (1-term, Al plane skipped entirely).
// CTA tile 128x128, BK=32, 256 threads, 8 warps (4m x 2n), warp tile 32x64.
// 3-stage pipeline; 2 CTAs/SM; smem stride 40 halves.
// ---------------------------------------------------------------------------
#define LDBH   40
#define AP_H   (128 * LDBH)
#define STG_B  (3 * AP_H * 2)
#define HGEMM_SMEM (3 * STG_B)           // 92160 B

__device__ __forceinline__ void hgemm_body(const __half* __restrict__ Ah,
                                           const __half* __restrict__ Al,
                                           const __half* __restrict__ Bh,
                                           float* __restrict__ C,
                                           int N, int K, int bx, int by,
                                           bool twoA)
{
    extern __shared__ char smc[];
    const uint32_t smem_u32 = (uint32_t)__cvta_generic_to_shared(smc);

    const int tid  = threadIdx.x;
    const int warp = tid >> 5;
    const int lane = tid & 31;
    const int g    = lane >> 2;
    const int t    = lane & 3;
    const int wm   = (warp & 3) * 32;
    const int wn   = (warp >> 2) * 64;

    uint32_t dst_off[6];
    const __half* src[6];
    bool skip[6];
#pragma unroll
    for (int j = 0; j < 6; j++) {
        int cid = tid + j * 256;
        skip[j] = false;
        if (cid < 1024) {
            int plane = cid >> 9;
            int r = (cid & 511) >> 2;
            int c = cid & 3;
            dst_off[j] = (uint32_t)(plane * AP_H + r * LDBH + c * 8) * 2;
            src[j] = (plane ? Al : Ah) + (size_t)(by * 128 + r) * K + c * 8;
            if (plane && !twoA) skip[j] = true;
        } else {
            int b = cid - 1024;
            int r = b >> 2, c = b & 3;
            dst_off[j] = (uint32_t)(2 * AP_H + r * LDBH + c * 8) * 2;
            src[j] = Bh + (size_t)(bx * 128 + r) * K + c * 8;
        }
    }

    const int lane8 = lane & 7;
    const uint32_t a_off = (uint32_t)(((wm + lane8 + ((lane >> 3) & 1) * 8) * LDBH
                                      + (lane >> 4) * 8) * 2);
    const uint32_t b_off = (uint32_t)((2 * AP_H + (wn + lane8 + (lane >> 4) * 8) * LDBH
                                      + ((lane >> 3) & 1) * 8) * 2);

    float acc[2][8][4];
#pragma unroll
    for (int mt = 0; mt < 2; mt++)
#pragma unroll
        for (int nt = 0; nt < 8; nt++)
#pragma unroll
            for (int c = 0; c < 4; c++) acc[mt][nt][c] = 0.0f;

    const int nk = K / 32;

#define CP_ISSUE(KT)                                                           \
    {                                                                          \
        uint32_t sb_ = smem_u32 + (uint32_t)(((KT) % 3) * STG_B);              \
        _Pragma("unroll")                                                      \
        for (int j = 0; j < 6; j++) {                                          \
            if (!skip[j])                                                      \
                asm volatile("cp.async.cg.shared.global [%0], [%1], 16;"       \
                    :: "r"(sb_ + dst_off[j]), "l"(src[j] + (KT) * 32) : "memory"); \
        }                                                                      \
    }
#define CP_COMMIT() asm volatile("cp.async.commit_group;" ::: "memory")

    CP_ISSUE(0); CP_COMMIT();
    CP_ISSUE(1); CP_COMMIT();

    for (int kt = 0; kt < nk; kt++) {
        asm volatile("cp.async.wait_group 1;" ::: "memory");
        __syncthreads();

        const uint32_t sb = smem_u32 + (uint32_t)((kt % 3) * STG_B);

#pragma unroll
        for (int k16 = 0; k16 < 2; k16++) {
            uint32_t ah[2][4], al[2][4];
            ldsm4(ah[0], sb + a_off + k16 * 32);
            ldsm4(ah[1], sb + a_off + 16 * LDBH * 2 + k16 * 32);
            if (twoA) {
                ldsm4(al[0], sb + AP_H * 2 + a_off + k16 * 32);
                ldsm4(al[1], sb + AP_H * 2 + a_off + 16 * LDBH * 2 + k16 * 32);
            }

#pragma unroll
            for (int jh = 0; jh < 2; jh++) {
                uint32_t bh[2][4];
#pragma unroll
                for (int jj = 0; jj < 2; jj++) {
                    int j = jh * 2 + jj;
                    ldsm4(bh[jj], sb + b_off + j * 16 * LDBH * 2 + k16 * 32);
                }
#pragma unroll
                for (int mt = 0; mt < 2; mt++)
#pragma unroll
                    for (int jj = 0; jj < 2; jj++) {
                        int nt = (jh * 2 + jj) * 2;
                        float (&d0)[4] = acc[mt][nt];
                        float (&d1)[4] = acc[mt][nt + 1];
                        if (twoA) {
                            mma_f16(d0, al[mt][0], al[mt][1], al[mt][2], al[mt][3],
                                    bh[jj][0], bh[jj][1]);
                            mma_f16(d1, al[mt][0], al[mt][1], al[mt][2], al[mt][3],
                                    bh[jj][2], bh[jj][3]);
                        }
                        mma_f16(d0, ah[mt][0], ah[mt][1], ah[mt][2], ah[mt][3],
                                bh[jj][0], bh[jj][1]);
                        mma_f16(d1, ah[mt][0], ah[mt][1], ah[mt][2], ah[mt][3],
                                bh[jj][2], bh[jj][3]);
                    }
            }
        }

        if (kt + 2 < nk) { CP_ISSUE(kt + 2); }
        CP_COMMIT();
    }

#pragma unroll
    for (int mt = 0; mt < 2; mt++) {
        int r0 = by * 128 + wm + mt * 16 + g;
#pragma unroll
        for (int nt = 0; nt < 8; nt++) {
            int c0 = bx * 128 + wn + nt * 8 + 2 * t;
            *(float2*)&C[(size_t)r0 * N + c0] =
                make_float2(acc[mt][nt][0], acc[mt][nt][1]);
            *(float2*)&C[(size_t)(r0 + 8) * N + c0] =
                make_float2(acc[mt][nt][2], acc[mt][nt][3]);
        }
    }
#undef CP_ISSUE
#undef CP_COMMIT
}

__global__ __launch_bounds__(256, 2)
void hgemm_qkv()
{
    int b = blockIdx.x;
    if (b < 512)      hgemm_body(g_hh, g_hl, g_wqh, g_q, 4096, 4096, b & 31, b >> 5, true);
    else if (b < 640) { int i = b - 512; hgemm_body(g_hh, g_hl, g_wkh, g_k, 1024, 4096, i & 7, i >> 3, false); }
    else              { int i = b - 640; hgemm_body(g_hh, g_hl, g_wvh, g_v, 1024, 4096, i & 7, i >> 3, false); }
}

__global__ __launch_bounds__(256, 2)
void hgemm_o(float* __restrict__ out)
{
    hgemm_body(g_ah, g_al, g_woh, out, 4096, 4096, blockIdx.x, blockIdx.y, true);
}

// ---------------------------------------------------------------------------
// Fused per-head RMSNorm + RoPE; Q and K both written as single fp16 planes.
// ---------------------------------------------------------------------------
__global__ __launch_bounds__(256)
void rmsnorm_rope(const float* __restrict__ cosb, const float* __restrict__ sinb,
                  const float* __restrict__ qw, const float* __restrict__ kw)
{
    const int warp = blockIdx.x * 8 + (threadIdx.x >> 5);
    const int lane = threadIdx.x & 31;

    const float* base;
    const float* w;
    int s;
    bool is_q = warp < S_LEN * NQH;
    size_t off;
    if (is_q) {
        s = warp / NQH;
        int h = warp - s * NQH;
        off = (size_t)s * D_MODEL + h * HD;
        base = g_q + off;
        w = qw;
    } else {
        int wv = warp - S_LEN * NQH;
        s = wv / NKVH;
        int h = wv - s * NKVH;
        off = (size_t)s * KV_DIM + h * HD;
        base = g_k + off;
        w = kw;
    }

    float x0 = base[lane];
    float x1 = base[lane + 32];
    float x2 = base[lane + 64];
    float x3 = base[lane + 96];

    float ss = x0 * x0 + x1 * x1 + x2 * x2 + x3 * x3;
#pragma unroll
    for (int o = 16; o; o >>= 1) ss += __shfl_xor_sync(0xffffffffu, ss, o);
    float inv = rsqrtf(ss * (1.0f / 128.0f) + 1e-6f);

    float n0 = w[lane]      * x0 * inv;
    float n1 = w[lane + 32] * x1 * inv;
    float n2 = w[lane + 64] * x2 * inv;
    float n3 = w[lane + 96] * x3 * inv;

    const float c0 = cosb[s * 64 + lane];
    const float c1 = cosb[s * 64 + lane + 32];
    const float s0 = sinb[s * 64 + lane];
    const float s1 = sinb[s * 64 + lane + 32];

    float r0 = n0 * c0 - n2 * s0;
    float r1 = n1 * c1 - n3 * s1;
    float r2 = n2 * c0 + n0 * s0;
    float r3 = n3 * c1 + n1 * s1;

    __half* dst = is_q ? g_qh : g_kh;
    dst[off + lane]      = __float2half_rn(r0);
    dst[off + lane + 32] = __float2half_rn(r1);
    dst[off + lane + 64] = __float2half_rn(r2);
    dst[off + lane + 96] = __float2half_rn(r3);
}

// ---------------------------------------------------------------------------
// V transpose: g_v fp32 [s][kv*128+d] -> g_vt fp16 [kv*128+d][s]
// ---------------------------------------------------------------------------
__global__ __launch_bounds__(256)
void vtrans()
{
    __shared__ float tile[32][33];
    const int kvh = blockIdx.z;
    const int s0 = blockIdx.x * 32;
    const int d0 = blockIdx.y * 32;
    const int tx = threadIdx.x;
    const int ty = threadIdx.y;

#pragma unroll
    for (int i = 0; i < 4; i++) {
        int sl = ty + i * 8;
        tile[sl][tx] = g_v[(size_t)(s0 + sl) * KV_DIM + kvh * HD + d0 + tx];
    }
    __syncthreads();
#pragma unroll
    for (int i = 0; i < 4; i++) {
        int dl = ty + i * 8;
        g_vt[(size_t)(kvh * HD + d0 + dl) * S_LEN + s0 + tx] =
            __float2half_rn(tile[tx][dl]);
    }
}

// ---------------------------------------------------------------------------
// Tensor-core flash attention v4: Q single fp16, 4-stage cp.async KV pipeline.
// QK^T: fp16 1-term.  P.V: fp16 2-term (P hi/lo, V single).
// smem halves: Qh 17408; per KV buf: K 8704 + Vt 9216 = 17920; x4 buffers.
// ---------------------------------------------------------------------------
#define OFF_QH   0
#define OFF_FKV  17408
#define FKVBUF   17920
#define FLASH_SMEM_TC ((OFF_FKV + 4 * FKVBUF) * 2)   // 178176 B

__global__ __launch_bounds__(256, 1)
void flash_attn_tc()
{
    extern __shared__ __half smh[];

    const int qt  = 15 - blockIdx.x;
    const int h   = blockIdx.y;
    const int q0  = qt * 128;
    const int kvh = h >> 2;
    const int tid  = threadIdx.x;
    const int warp = tid >> 5;
    const int lane = tid & 31;
    const int g = lane >> 2;
    const int t = lane & 3;

    const uint32_t sbase = (uint32_t)__cvta_generic_to_shared(smh);

#define CP16(DST, SRC)                                                         \
    asm volatile("cp.async.cg.shared.global [%0], [%1], 16;"                   \
                 :: "r"(DST), "l"(SRC) : "memory")
#define CP_COMMIT() asm volatile("cp.async.commit_group;" ::: "memory")

#define LOAD_KV(KT, BUF)                                                       \
    {                                                                          \
        const uint32_t kb_ = sbase + (uint32_t)(OFF_FKV + (BUF) * FKVBUF) * 2; \
        const int k0_ = (KT) * 64;                                             \
        _Pragma("unroll")                                                      \
        for (int j = 0; j < 8; j++) {                                          \
            int cid = tid + j * 256;                                           \
            if (cid < 1024) {                                                  \
                int r = cid >> 4, c = cid & 15;                                \
                CP16(kb_ + (uint32_t)(r * 136 + c * 8) * 2,                    \
                     g_kh + (size_t)(k0_ + r) * KV_DIM + kvh * HD + c * 8);    \
            } else {                                                           \
                int b = cid - 1024;                                            \
                int r = b >> 3, c = b & 7;                                     \
                CP16(kb_ + (uint32_t)(8704 + r * 72 + c * 8) * 2,              \
                     g_vt + (size_t)(kvh * HD + r) * S_LEN + k0_ + c * 8);     \
            }                                                                  \
        }                                                                      \
    }

    const int wrow = q0 + warp * 16;
    const int nkt  = 2 * qt + 2;

    // prologue: Q + KV0 in group 0; KV1 group 1; KV2 group 2 (guarded, always commit)
#pragma unroll
    for (int j = 0; j < 8; j++) {
        int cid = tid + j * 256;
        int r = cid >> 4, c = cid & 15;
        CP16(sbase + (uint32_t)(OFF_QH + r * 136 + c * 8) * 2,
             g_qh + (size_t)(q0 + r) * D_MODEL + h * HD + c * 8);
    }
    LOAD_KV(0, 0);
    CP_COMMIT();
    if (1 < nkt) LOAD_KV(1, 1);
    CP_COMMIT();
    if (2 < nkt) LOAD_KV(2, 2);
    CP_COMMIT();

    float o[16][4];
#pragma unroll
    for (int nt = 0; nt < 16; nt++)
#pragma unroll
        for (int j = 0; j < 4; j++) o[nt][j] = 0.0f;
    float m0 = -1e30f, m1 = -1e30f, l0 = 0.0f, l1 = 0.0f;

    const __half* qrh = smh + OFF_QH + (warp * 16 + g) * 136 + 2 * t;

    for (int kt = 0; kt < nkt; kt++) {
        const int k0 = kt * 64;
        asm volatile("cp.async.wait_group 2;" ::: "memory");
        __syncthreads();
        if (kt + 3 < nkt) LOAD_KV(kt + 3, (kt + 3) & 3);
        CP_COMMIT();

        if (k0 > wrow + 15) continue;

        const __half* Kh = smh + OFF_FKV + (kt & 3) * FKVBUF;
        const __half* Vh = Kh + 8704;

        // ---- S = Q K^T (fp16 single-term) ----
        float s[8][4];
#pragma unroll
        for (int nt = 0; nt < 8; nt++)
#pragma unroll
            for (int j = 0; j < 4; j++) s[nt][j] = 0.0f;

#pragma unroll
        for (int c = 0; c < 8; c++) {
            uint32_t ah0 = *(const uint32_t*)(qrh + c * 16);
            uint32_t ah1 = *(const uint32_t*)(qrh + 8 * 136 + c * 16);
            uint32_t ah2 = *(const uint32_t*)(qrh + c * 16 + 8);
            uint32_t ah3 = *(const uint32_t*)(qrh + 8 * 136 + c * 16 + 8);
#pragma unroll
            for (int nt = 0; nt < 8; nt++) {
                const __half* kp = Kh + (nt * 8 + g) * 136 + c * 16 + 2 * t;
                uint32_t b0 = *(const uint32_t*)(kp);
                uint32_t b1 = *(const uint32_t*)(kp + 8);
                mma_f16(s[nt], ah0, ah1, ah2, ah3, b0, b1);
            }
        }

        // ---- scale + causal mask ----
        if (k0 + 63 > wrow) {
            int r0 = wrow + g, r1 = r0 + 8;
#pragma unroll
            for (int nt = 0; nt < 8; nt++) {
                int c0 = k0 + nt * 8 + 2 * t;
                s[nt][0] = (c0     > r0) ? -1e30f : s[nt][0] * SCALE_F;
                s[nt][1] = (c0 + 1 > r0) ? -1e30f : s[nt][1] * SCALE_F;
                s[nt][2] = (c0     > r1) ? -1e30f : s[nt][2] * SCALE_F;
                s[nt][3] = (c0 + 1 > r1) ? -1e30f : s[nt][3] * SCALE_F;
            }
        } else {
#pragma unroll
            for (int nt = 0; nt < 8; nt++)
#pragma unroll
                for (int j = 0; j < 4; j++) s[nt][j] *= SCALE_F;
        }

        // ---- online softmax ----
        float mx0 = -1e30f, mx1 = -1e30f;
#pragma unroll
        for (int nt = 0; nt < 8; nt++) {
            mx0 = fmaxf(mx0, fmaxf(s[nt][0], s[nt][1]));
            mx1 = fmaxf(mx1, fmaxf(s[nt][2], s[nt][3]));
        }
        mx0 = fmaxf(mx0, __shfl_xor_sync(0xffffffffu, mx0, 1));
        mx0 = fmaxf(mx0, __shfl_xor_sync(0xffffffffu, mx0, 2));
        mx1 = fmaxf(mx1, __shfl_xor_sync(0xffffffffu, mx1, 1));
        mx1 = fmaxf(mx1, __shfl_xor_sync(0xffffffffu, mx1, 2));

        float mn0 = fmaxf(m0, mx0), mn1 = fmaxf(m1, mx1);
        float a0 = __expf(m0 - mn0), a1 = __expf(m1 - mn1);
        m0 = mn0; m1 = mn1;

        float sum0 = 0.0f, sum1 = 0.0f;
#pragma unroll
        for (int nt = 0; nt < 8; nt++) {
            s[nt][0] = __expf(s[nt][0] - m0);
            s[nt][1] = __expf(s[nt][1] - m0);
            s[nt][2] = __expf(s[nt][2] - m1);
            s[nt][3] = __expf(s[nt][3] - m1);
            sum0 += s[nt][0] + s[nt][1];
            sum1 += s[nt][2] + s[nt][3];
        }
        sum0 += __shfl_xor_sync(0xffffffffu, sum0, 1);
        sum0 += __shfl_xor_sync(0xffffffffu, sum0, 2);
        sum1 += __shfl_xor_sync(0xffffffffu, sum1, 1);
        sum1 += __shfl_xor_sync(0xffffffffu, sum1, 2);
        l0 = l0 * a0 + sum0;
        l1 = l1 * a1 + sum1;

#pragma unroll
        for (int nt = 0; nt < 16; nt++) {
            o[nt][0] *= a0; o[nt][1] *= a0;
            o[nt][2] *= a1; o[nt][3] *= a1;
        }

        // ---- O += P V (fp16: P 2-term split, V single) ----
#pragma unroll
        for (int c = 0; c < 4; c++) {
            __half2 h0, lo0, h1, lo1, h2, lo2, h3, lo3;
            split2h(s[2 * c][0],     s[2 * c][1],     h0, lo0);
            split2h(s[2 * c][2],     s[2 * c][3],     h1, lo1);
            split2h(s[2 * c + 1][0], s[2 * c + 1][1], h2, lo2);
            split2h(s[2 * c + 1][2], s[2 * c + 1][3], h3, lo3);
            uint32_t ph0 = h2u(h0), ph1 = h2u(h1), ph2 = h2u(h2), ph3 = h2u(h3);
            uint32_t pl0 = h2u(lo0), pl1 = h2u(lo1), pl2 = h2u(lo2), pl3 = h2u(lo3);
#pragma unroll
            for (int nt = 0; nt < 16; nt++) {
                const __half* vp = Vh + (nt * 8 + g) * 72 + c * 16 + 2 * t;
                uint32_t vh0 = *(const uint32_t*)(vp);
                uint32_t vh1 = *(const uint32_t*)(vp + 8);
                mma_f16(o[nt], ph0, ph1, ph2, ph3, vh0, vh1);
                mma_f16(o[nt], pl0, pl1, pl2, pl3, vh0, vh1);
            }
        }
    }

    // ---- normalize + write attn output as fp16 hi/lo planes ----
    float inv0 = 1.0f / l0, inv1 = 1.0f / l1;
    int row0 = q0 + warp * 16 + g;
#pragma unroll
    for (int nt = 0; nt < 16; nt++) {
        int col = h * HD + nt * 8 + 2 * t;
        float f0 = o[nt][0] * inv0, f1 = o[nt][1] * inv0;
        float f2 = o[nt][2] * inv1, f3 = o[nt][3] * inv1;
        __half2 hA, lA, hB, lB;
        split2h(f0, f1, hA, lA);
        split2h(f2, f3, hB, lB);
        *(uint32_t*)&g_ah[(size_t)row0 * D_MODEL + col]       = h2u(hA);
        *(uint32_t*)&g_al[(size_t)row0 * D_MODEL + col]       = h2u(lA);
        *(uint32_t*)&g_ah[(size_t)(row0 + 8) * D_MODEL + col] = h2u(hB);
        *(uint32_t*)&g_al[(size_t)(row0 + 8) * D_MODEL + col] = h2u(lB);
    }
#undef LOAD_KV
#undef CP16
#undef CP_COMMIT
}

// ---------------------------------------------------------------------------
extern "C" void kernel_launch(void* const* d_in, const int* in_sizes, int n_in,
                              void* d_out, int out_size)
{
    const float* hidden = (const float*)d_in[0];
    const float* cosb   = (const float*)d_in[1];
    const float* sinb   = (const float*)d_in[2];
    const float* Wq = (const float*)d_in[4];
    const float* Wk = (const float*)d_in[5];
    const float* Wv = (const float*)d_in[6];
    const float* Wo = (const float*)d_in[7];
    const float* qw = (const float*)d_in[8];
    const float* kw = (const float*)d_in[9];
    float* out = (float*)d_out;

    cudaFuncSetAttribute(hgemm_qkv, cudaFuncAttributeMaxDynamicSharedMemorySize, HGEMM_SMEM);
    cudaFuncSetAttribute(hgemm_o,   cudaFuncAttributeMaxDynamicSharedMemorySize, HGEMM_SMEM);
    cudaFuncSetAttribute(flash_attn_tc, cudaFuncAttributeMaxDynamicSharedMemorySize, FLASH_SMEM_TC);

    split_all<<<2048, 256>>>((const float4*)hidden, (const float4*)Wq,
                             (const float4*)Wk, (const float4*)Wv,
                             (const float4*)Wo);

    hgemm_qkv<<<768, 256, HGEMM_SMEM>>>();

    rmsnorm_rope<<<10240, 256>>>(cosb, sinb, qw, kw);
    vtrans<<<dim3(64, 4, 8), dim3(32, 8)>>>();

    flash_attn_tc<<<dim3(16, 32), 256, FLASH_SMEM_TC>>>();

    hgemm_o<<<dim3(32, 16), 256, HGEMM_SMEM>>>(out);
}

// round 13
// speedup vs baseline: 7.9632x; 1.2774x over previous
#include <cuda_runtime.h>
#include <cuda_fp16.h>
#include <math.h>
#include <stdint.h>

#define S_LEN   2048
#define D_MODEL 4096
#define NQH     32
#define NKVH    8
#define HD      128
#define KV_DIM  1024
#define SCALE_F 0.08838834764831845f   // 128^-0.5

// fp32 QKV projection outputs
__device__ float g_q[S_LEN * D_MODEL];
__device__ float g_k[S_LEN * KV_DIM];
__device__ float g_v[S_LEN * KV_DIM];
// fp16 planes (all GEMMs 1-term now)
__device__ __half g_hh[S_LEN * D_MODEL];   // hidden fp16
__device__ __half g_wqh[D_MODEL * D_MODEL];
__device__ __half g_wkh[KV_DIM * D_MODEL];
__device__ __half g_wvh[KV_DIM * D_MODEL];
__device__ __half g_woh[D_MODEL * D_MODEL];
__device__ __half g_ah[S_LEN * D_MODEL];   // attn out fp16
// fp16 flash inputs
__device__ __half g_qh[S_LEN * D_MODEL];   // q fp16
__device__ __half g_kh[S_LEN * KV_DIM];    // k fp16
__device__ __half g_vt[KV_DIM * S_LEN];    // v transposed [kv*128+d][s]

// ---------------------------------------------------------------------------
// helpers
// ---------------------------------------------------------------------------
__device__ __forceinline__ void mma_f16(float (&d)[4],
    uint32_t a0, uint32_t a1, uint32_t a2, uint32_t a3,
    uint32_t b0, uint32_t b1) {
    asm volatile(
        "mma.sync.aligned.m16n8k16.row.col.f32.f16.f16.f32 "
        "{%0,%1,%2,%3}, {%4,%5,%6,%7}, {%8,%9}, {%0,%1,%2,%3};\n"
        : "+f"(d[0]), "+f"(d[1]), "+f"(d[2]), "+f"(d[3])
        : "r"(a0), "r"(a1), "r"(a2), "r"(a3), "r"(b0), "r"(b1));
}

__device__ __forceinline__ void ldsm4(uint32_t (&r)[4], uint32_t addr) {
    asm volatile("ldmatrix.sync.aligned.m8n8.x4.shared.b16 {%0,%1,%2,%3}, [%4];"
        : "=r"(r[0]), "=r"(r[1]), "=r"(r[2]), "=r"(r[3]) : "r"(addr));
}

__device__ __forceinline__ void split2h(float x0, float x1,
                                        __half2& hi, __half2& lo) {
    hi = __floats2half2_rn(x0, x1);
    float2 hf = __half22float2(hi);
    lo = __floats2half2_rn(x0 - hf.x, x1 - hf.y);
}

__device__ __forceinline__ uint32_t h2u(__half2 v) {
    return *reinterpret_cast<uint32_t*>(&v);
}

// ---------------------------------------------------------------------------
// pre-pass: all fp32->fp16 conversions in ONE launch (all 1-term now)
// segments (float4 units): hidden 2M, Wq 4M, Wk 1M, Wv 1M, Wo 4M
// ---------------------------------------------------------------------------
#define SEG0 (2 * 1024 * 1024)
#define SEG1 (SEG0 + 4 * 1024 * 1024)
#define SEG2 (SEG1 + 1024 * 1024)
#define SEG3 (SEG2 + 1024 * 1024)
#define SEG4 (SEG3 + 4 * 1024 * 1024)

__global__ __launch_bounds__(256)
void split_all(const float4* __restrict__ hidden, const float4* __restrict__ Wq,
               const float4* __restrict__ Wk, const float4* __restrict__ Wv,
               const float4* __restrict__ Wo)
{
    int stride = gridDim.x * blockDim.x;
    for (int i = blockIdx.x * blockDim.x + threadIdx.x; i < SEG4; i += stride) {
        const float4* src;
        uint2* hi;
        int off;
        if (i < SEG0)      { src = hidden; off = i;        hi = (uint2*)g_hh; }
        else if (i < SEG1) { src = Wq;     off = i - SEG0; hi = (uint2*)g_wqh; }
        else if (i < SEG2) { src = Wk;     off = i - SEG1; hi = (uint2*)g_wkh; }
        else if (i < SEG3) { src = Wv;     off = i - SEG2; hi = (uint2*)g_wvh; }
        else               { src = Wo;     off = i - SEG3; hi = (uint2*)g_woh; }
        float4 v = src[off];
        hi[off] = make_uint2(h2u(__floats2half2_rn(v.x, v.y)),
                             h2u(__floats2half2_rn(v.z, v.w)));
    }
}

// ---------------------------------------------------------------------------
// fp16 1-term GEMM NT with cp.async: C = Ah @ Bh^T, fp32 out.
// CTA tile 128x128, BK=32, 256 threads, 8 warps (4m x 2n), warp tile 32x64.
// 4-stage cp.async pipeline; 2 CTAs/SM; smem stride 40 halves.
// ---------------------------------------------------------------------------
#define LDBH   40
#define AP_H   (128 * LDBH)              // 5120 halves per plane
#define STG_B  (2 * AP_H * 2)            // 20480 B per stage (A + B)
#define HGEMM_SMEM (4 * STG_B)           // 81920 B

__device__ __forceinline__ void hgemm_body(const __half* __restrict__ Ah,
                                           const __half* __restrict__ Bh,
                                           float* __restrict__ C,
                                           int N, int K, int bx, int by)
{
    extern __shared__ char smc[];
    const uint32_t smem_u32 = (uint32_t)__cvta_generic_to_shared(smc);

    const int tid  = threadIdx.x;
    const int warp = tid >> 5;
    const int lane = tid & 31;
    const int g    = lane >> 2;
    const int t    = lane & 3;
    const int wm   = (warp & 3) * 32;
    const int wn   = (warp >> 2) * 64;

    // loader chunks: 4 x 16B per thread per stage (A 512 + B 512 chunks)
    uint32_t dst_off[4];
    const __half* src[4];
#pragma unroll
    for (int j = 0; j < 4; j++) {
        int cid = tid + j * 256;
        if (cid < 512) {
            int r = cid >> 2, c = cid & 3;
            dst_off[j] = (uint32_t)(r * LDBH + c * 8) * 2;
            src[j] = Ah + (size_t)(by * 128 + r) * K + c * 8;
        } else {
            int b = cid - 512;
            int r = b >> 2, c = b & 3;
            dst_off[j] = (uint32_t)(AP_H + r * LDBH + c * 8) * 2;
            src[j] = Bh + (size_t)(bx * 128 + r) * K + c * 8;
        }
    }

    const int lane8 = lane & 7;
    const uint32_t a_off = (uint32_t)(((wm + lane8 + ((lane >> 3) & 1) * 8) * LDBH
                                      + (lane >> 4) * 8) * 2);
    const uint32_t b_off = (uint32_t)((AP_H + (wn + lane8 + (lane >> 4) * 8) * LDBH
                                      + ((lane >> 3) & 1) * 8) * 2);

    float acc[2][8][4];
#pragma unroll
    for (int mt = 0; mt < 2; mt++)
#pragma unroll
        for (int nt = 0; nt < 8; nt++)
#pragma unroll
            for (int c = 0; c < 4; c++) acc[mt][nt][c] = 0.0f;

    const int nk = K / 32;

#define CP_ISSUE(KT)                                                           \
    {                                                                          \
        uint32_t sb_ = smem_u32 + (uint32_t)(((KT) & 3) * STG_B);              \
        _Pragma("unroll")                                                      \
        for (int j = 0; j < 4; j++) {                                          \
            asm volatile("cp.async.cg.shared.global [%0], [%1], 16;"           \
                :: "r"(sb_ + dst_off[j]), "l"(src[j] + (KT) * 32) : "memory"); \
        }                                                                      \
    }
#define CP_COMMIT() asm volatile("cp.async.commit_group;" ::: "memory")

    CP_ISSUE(0); CP_COMMIT();
    CP_ISSUE(1); CP_COMMIT();
    CP_ISSUE(2); CP_COMMIT();

    for (int kt = 0; kt < nk; kt++) {
        asm volatile("cp.async.wait_group 2;" ::: "memory");
        __syncthreads();
        if (kt + 3 < nk) { CP_ISSUE(kt + 3); }
        CP_COMMIT();

        const uint32_t sb = smem_u32 + (uint32_t)((kt & 3) * STG_B);

#pragma unroll
        for (int k16 = 0; k16 < 2; k16++) {
            uint32_t ah[2][4];
            ldsm4(ah[0], sb + a_off + k16 * 32);
            ldsm4(ah[1], sb + a_off + 16 * LDBH * 2 + k16 * 32);

#pragma unroll
            for (int jh = 0; jh < 2; jh++) {
                uint32_t bh[2][4];
#pragma unroll
                for (int jj = 0; jj < 2; jj++) {
                    int j = jh * 2 + jj;
                    ldsm4(bh[jj], sb + b_off + j * 16 * LDBH * 2 + k16 * 32);
                }
#pragma unroll
                for (int mt = 0; mt < 2; mt++)
#pragma unroll
                    for (int jj = 0; jj < 2; jj++) {
                        int nt = (jh * 2 + jj) * 2;
                        mma_f16(acc[mt][nt], ah[mt][0], ah[mt][1], ah[mt][2],
                                ah[mt][3], bh[jj][0], bh[jj][1]);
                        mma_f16(acc[mt][nt + 1], ah[mt][0], ah[mt][1], ah[mt][2],
                                ah[mt][3], bh[jj][2], bh[jj][3]);
                    }
            }
        }
    }

#pragma unroll
    for (int mt = 0; mt < 2; mt++) {
        int r0 = by * 128 + wm + mt * 16 + g;
#pragma unroll
        for (int nt = 0; nt < 8; nt++) {
            int c0 = bx * 128 + wn + nt * 8 + 2 * t;
            *(float2*)&C[(size_t)r0 * N + c0] =
                make_float2(acc[mt][nt][0], acc[mt][nt][1]);
            *(float2*)&C[(size_t)(r0 + 8) * N + c0] =
                make_float2(acc[mt][nt][2], acc[mt][nt][3]);
        }
    }
#undef CP_ISSUE
#undef CP_COMMIT
}

__global__ __launch_bounds__(256, 2)
void hgemm_qkv()
{
    int b = blockIdx.x;
    if (b < 512)      hgemm_body(g_hh, g_wqh, g_q, 4096, 4096, b & 31, b >> 5);
    else if (b < 640) { int i = b - 512; hgemm_body(g_hh, g_wkh, g_k, 1024, 4096, i & 7, i >> 3); }
    else              { int i = b - 640; hgemm_body(g_hh, g_wvh, g_v, 1024, 4096, i & 7, i >> 3); }
}

__global__ __launch_bounds__(256, 2)
void hgemm_o(float* __restrict__ out)
{
    hgemm_body(g_ah, g_woh, out, 4096, 4096, blockIdx.x, blockIdx.y);
}

// ---------------------------------------------------------------------------
// Fused per-head RMSNorm + RoPE; Q and K written as single fp16 planes.
// ---------------------------------------------------------------------------
__global__ __launch_bounds__(256)
void rmsnorm_rope(const float* __restrict__ cosb, const float* __restrict__ sinb,
                  const float* __restrict__ qw, const float* __restrict__ kw)
{
    const int warp = blockIdx.x * 8 + (threadIdx.x >> 5);
    const int lane = threadIdx.x & 31;

    const float* base;
    const float* w;
    int s;
    bool is_q = warp < S_LEN * NQH;
    size_t off;
    if (is_q) {
        s = warp / NQH;
        int h = warp - s * NQH;
        off = (size_t)s * D_MODEL + h * HD;
        base = g_q + off;
        w = qw;
    } else {
        int wv = warp - S_LEN * NQH;
        s = wv / NKVH;
        int h = wv - s * NKVH;
        off = (size_t)s * KV_DIM + h * HD;
        base = g_k + off;
        w = kw;
    }

    float x0 = base[lane];
    float x1 = base[lane + 32];
    float x2 = base[lane + 64];
    float x3 = base[lane + 96];

    float ss = x0 * x0 + x1 * x1 + x2 * x2 + x3 * x3;
#pragma unroll
    for (int o = 16; o; o >>= 1) ss += __shfl_xor_sync(0xffffffffu, ss, o);
    float inv = rsqrtf(ss * (1.0f / 128.0f) + 1e-6f);

    float n0 = w[lane]      * x0 * inv;
    float n1 = w[lane + 32] * x1 * inv;
    float n2 = w[lane + 64] * x2 * inv;
    float n3 = w[lane + 96] * x3 * inv;

    const float c0 = cosb[s * 64 + lane];
    const float c1 = cosb[s * 64 + lane + 32];
    const float s0 = sinb[s * 64 + lane];
    const float s1 = sinb[s * 64 + lane + 32];

    float r0 = n0 * c0 - n2 * s0;
    float r1 = n1 * c1 - n3 * s1;
    float r2 = n2 * c0 + n0 * s0;
    float r3 = n3 * c1 + n1 * s1;

    __half* dst = is_q ? g_qh : g_kh;
    dst[off + lane]      = __float2half_rn(r0);
    dst[off + lane + 32] = __float2half_rn(r1);
    dst[off + lane + 64] = __float2half_rn(r2);
    dst[off + lane + 96] = __float2half_rn(r3);
}

// ---------------------------------------------------------------------------
// V transpose: g_v fp32 [s][kv*128+d] -> g_vt fp16 [kv*128+d][s]
// ---------------------------------------------------------------------------
__global__ __launch_bounds__(256)
void vtrans()
{
    __shared__ float tile[32][33];
    const int kvh = blockIdx.z;
    const int s0 = blockIdx.x * 32;
    const int d0 = blockIdx.y * 32;
    const int tx = threadIdx.x;
    const int ty = threadIdx.y;

#pragma unroll
    for (int i = 0; i < 4; i++) {
        int sl = ty + i * 8;
        tile[sl][tx] = g_v[(size_t)(s0 + sl) * KV_DIM + kvh * HD + d0 + tx];
    }
    __syncthreads();
#pragma unroll
    for (int i = 0; i < 4; i++) {
        int dl = ty + i * 8;
        g_vt[(size_t)(kvh * HD + d0 + dl) * S_LEN + s0 + tx] =
            __float2half_rn(tile[tx][dl]);
    }
}

// ---------------------------------------------------------------------------
// Tensor-core flash attention (R12 core): Q single fp16, 4-stage cp.async KV
// pipeline. QK^T: fp16 1-term. P.V: fp16 2-term. Epilogue: single fp16 plane.
// ---------------------------------------------------------------------------
#define OFF_QH   0
#define OFF_FKV  17408
#define FKVBUF   17920
#define FLASH_SMEM_TC ((OFF_FKV + 4 * FKVBUF) * 2)   // 178176 B

__global__ __launch_bounds__(256, 1)
void flash_attn_tc()
{
    extern __shared__ __half smh[];

    const int qt  = 15 - blockIdx.x;
    const int h   = blockIdx.y;
    const int q0  = qt * 128;
    const int kvh = h >> 2;
    const int tid  = threadIdx.x;
    const int warp = tid >> 5;
    const int lane = tid & 31;
    const int g = lane >> 2;
    const int t = lane & 3;

    const uint32_t sbase = (uint32_t)__cvta_generic_to_shared(smh);

#define CP16(DST, SRC)                                                         \
    asm volatile("cp.async.cg.shared.global [%0], [%1], 16;"                   \
                 :: "r"(DST), "l"(SRC) : "memory")
#define CP_COMMIT() asm volatile("cp.async.commit_group;" ::: "memory")

#define LOAD_KV(KT, BUF)                                                       \
    {                                                                          \
        const uint32_t kb_ = sbase + (uint32_t)(OFF_FKV + (BUF) * FKVBUF) * 2; \
        const int k0_ = (KT) * 64;                                             \
        _Pragma("unroll")                                                      \
        for (int j = 0; j < 8; j++) {                                          \
            int cid = tid + j * 256;                                           \
            if (cid < 1024) {                                                  \
                int r = cid >> 4, c = cid & 15;                                \
                CP16(kb_ + (uint32_t)(r * 136 + c * 8) * 2,                    \
                     g_kh + (size_t)(k0_ + r) * KV_DIM + kvh * HD + c * 8);    \
            } else {                                                           \
                int b = cid - 1024;                                            \
                int r = b >> 3, c = b & 7;                                     \
                CP16(kb_ + (uint32_t)(8704 + r * 72 + c * 8) * 2,              \
                     g_vt + (size_t)(kvh * HD + r) * S_LEN + k0_ + c * 8);     \
            }                                                                  \
        }                                                                      \
    }

    const int wrow = q0 + warp * 16;
    const int nkt  = 2 * qt + 2;

#pragma unroll
    for (int j = 0; j < 8; j++) {
        int cid = tid + j * 256;
        int r = cid >> 4, c = cid & 15;
        CP16(sbase + (uint32_t)(OFF_QH + r * 136 + c * 8) * 2,
             g_qh + (size_t)(q0 + r) * D_MODEL + h * HD + c * 8);
    }
    LOAD_KV(0, 0);
    CP_COMMIT();
    if (1 < nkt) LOAD_KV(1, 1);
    CP_COMMIT();
    if (2 < nkt) LOAD_KV(2, 2);
    CP_COMMIT();

    float o[16][4];
#pragma unroll
    for (int nt = 0; nt < 16; nt++)
#pragma unroll
        for (int j = 0; j < 4; j++) o[nt][j] = 0.0f;
    float m0 = -1e30f, m1 = -1e30f, l0 = 0.0f, l1 = 0.0f;

    const __half* qrh = smh + OFF_QH + (warp * 16 + g) * 136 + 2 * t;

    for (int kt = 0; kt < nkt; kt++) {
        const int k0 = kt * 64;
        asm volatile("cp.async.wait_group 2;" ::: "memory");
        __syncthreads();
        if (kt + 3 < nkt) LOAD_KV(kt + 3, (kt + 3) & 3);
        CP_COMMIT();

        if (k0 > wrow + 15) continue;

        const __half* Kh = smh + OFF_FKV + (kt & 3) * FKVBUF;
        const __half* Vh = Kh + 8704;

        float s[8][4];
#pragma unroll
        for (int nt = 0; nt < 8; nt++)
#pragma unroll
            for (int j = 0; j < 4; j++) s[nt][j] = 0.0f;

#pragma unroll
        for (int c = 0; c < 8; c++) {
            uint32_t ah0 = *(const uint32_t*)(qrh + c * 16);
            uint32_t ah1 = *(const uint32_t*)(qrh + 8 * 136 + c * 16);
            uint32_t ah2 = *(const uint32_t*)(qrh + c * 16 + 8);
            uint32_t ah3 = *(const uint32_t*)(qrh + 8 * 136 + c * 16 + 8);
#pragma unroll
            for (int nt = 0; nt < 8; nt++) {
                const __half* kp = Kh + (nt * 8 + g) * 136 + c * 16 + 2 * t;
                uint32_t b0 = *(const uint32_t*)(kp);
                uint32_t b1 = *(const uint32_t*)(kp + 8);
                mma_f16(s[nt], ah0, ah1, ah2, ah3, b0, b1);
            }
        }

        if (k0 + 63 > wrow) {
            int r0 = wrow + g, r1 = r0 + 8;
#pragma unroll
            for (int nt = 0; nt < 8; nt++) {
                int c0 = k0 + nt * 8 + 2 * t;
                s[nt][0] = (c0     > r0) ? -1e30f : s[nt][0] * SCALE_F;
                s[nt][1] = (c0 + 1 > r0) ? -1e30f : s[nt][1] * SCALE_F;
                s[nt][2] = (c0     > r1) ? -1e30f : s[nt][2] * SCALE_F;
                s[nt][3] = (c0 + 1 > r1) ? -1e30f : s[nt][3] * SCALE_F;
            }
        } else {
#pragma unroll
            for (int nt = 0; nt < 8; nt++)
#pragma unroll
                for (int j = 0; j < 4; j++) s[nt][j] *= SCALE_F;
        }

        float mx0 = -1e30f, mx1 = -1e30f;
#pragma unroll
        for (int nt = 0; nt < 8; nt++) {
            mx0 = fmaxf(mx0, fmaxf(s[nt][0], s[nt][1]));
            mx1 = fmaxf(mx1, fmaxf(s[nt][2], s[nt][3]));
        }
        mx0 = fmaxf(mx0, __shfl_xor_sync(0xffffffffu, mx0, 1));
        mx0 = fmaxf(mx0, __shfl_xor_sync(0xffffffffu, mx0, 2));
        mx1 = fmaxf(mx1, __shfl_xor_sync(0xffffffffu, mx1, 1));
        mx1 = fmaxf(mx1, __shfl_xor_sync(0xffffffffu, mx1, 2));

        float mn0 = fmaxf(m0, mx0), mn1 = fmaxf(m1, mx1);
        float a0 = __expf(m0 - mn0), a1 = __expf(m1 - mn1);
        m0 = mn0; m1 = mn1;

        float sum0 = 0.0f, sum1 = 0.0f;
#pragma unroll
        for (int nt = 0; nt < 8; nt++) {
            s[nt][0] = __expf(s[nt][0] - m0);
            s[nt][1] = __expf(s[nt][1] - m0);
            s[nt][2] = __expf(s[nt][2] - m1);
            s[nt][3] = __expf(s[nt][3] - m1);
            sum0 += s[nt][0] + s[nt][1];
            sum1 += s[nt][2] + s[nt][3];
        }
        sum0 += __shfl_xor_sync(0xffffffffu, sum0, 1);
        sum0 += __shfl_xor_sync(0xffffffffu, sum0, 2);
        sum1 += __shfl_xor_sync(0xffffffffu, sum1, 1);
        sum1 += __shfl_xor_sync(0xffffffffu, sum1, 2);
        l0 = l0 * a0 + sum0;
        l1 = l1 * a1 + sum1;

#pragma unroll
        for (int nt = 0; nt < 16; nt++) {
            o[nt][0] *= a0; o[nt][1] *= a0;
            o[nt][2] *= a1; o[nt][3] *= a1;
        }

#pragma unroll
        for (int c = 0; c < 4; c++) {
            __half2 h0, lo0, h1, lo1, h2, lo2, h3, lo3;
            split2h(s[2 * c][0],     s[2 * c][1],     h0, lo0);
            split2h(s[2 * c][2],     s[2 * c][3],     h1, lo1);
            split2h(s[2 * c + 1][0], s[2 * c + 1][1], h2, lo2);
            split2h(s[2 * c + 1][2], s[2 * c + 1][3], h3, lo3);
            uint32_t ph0 = h2u(h0), ph1 = h2u(h1), ph2 = h2u(h2), ph3 = h2u(h3);
            uint32_t pl0 = h2u(lo0), pl1 = h2u(lo1), pl2 = h2u(lo2), pl3 = h2u(lo3);
#pragma unroll
            for (int nt = 0; nt < 16; nt++) {
                const __half* vp = Vh + (nt * 8 + g) * 72 + c * 16 + 2 * t;
                uint32_t vh0 = *(const uint32_t*)(vp);
                uint32_t vh1 = *(const uint32_t*)(vp + 8);
                mma_f16(o[nt], ph0, ph1, ph2, ph3, vh0, vh1);
                mma_f16(o[nt], pl0, pl1, pl2, pl3, vh0, vh1);
            }
        }
    }

    // ---- normalize + write attn output as single fp16 plane ----
    float inv0 = 1.0f / l0, inv1 = 1.0f / l1;
    int row0 = q0 + warp * 16 + g;
#pragma unroll
    for (int nt = 0; nt < 16; nt++) {
        int col = h * HD + nt * 8 + 2 * t;
        *(uint32_t*)&g_ah[(size_t)row0 * D_MODEL + col] =
            h2u(__floats2half2_rn(o[nt][0] * inv0, o[nt][1] * inv0));
        *(uint32_t*)&g_ah[(size_t)(row0 + 8) * D_MODEL + col] =
            h2u(__floats2half2_rn(o[nt][2] * inv1, o[nt][3] * inv1));
    }
#undef LOAD_KV
#undef CP16
#undef CP_COMMIT
}

// ---------------------------------------------------------------------------
extern "C" void kernel_launch(void* const* d_in, const int* in_sizes, int n_in,
                              void* d_out, int out_size)
{
    const float* hidden = (const float*)d_in[0];
    const float* cosb   = (const float*)d_in[1];
    const float* sinb   = (const float*)d_in[2];
    const float* Wq = (const float*)d_in[4];
    const float* Wk = (const float*)d_in[5];
    const float* Wv = (const float*)d_in[6];
    const float* Wo = (const float*)d_in[7];
    const float* qw = (const float*)d_in[8];
    const float* kw = (const float*)d_in[9];
    float* out = (float*)d_out;

    cudaFuncSetAttribute(hgemm_qkv, cudaFuncAttributeMaxDynamicSharedMemorySize, HGEMM_SMEM);
    cudaFuncSetAttribute(hgemm_o,   cudaFuncAttributeMaxDynamicSharedMemorySize, HGEMM_SMEM);
    cudaFuncSetAttribute(flash_attn_tc, cudaFuncAttributeMaxDynamicSharedMemorySize, FLASH_SMEM_TC);

    split_all<<<2048, 256>>>((const float4*)hidden, (const float4*)Wq,
                             (const float4*)Wk, (const float4*)Wv,
                             (const float4*)Wo);

    hgemm_qkv<<<768, 256, HGEMM_SMEM>>>();

    rmsnorm_rope<<<10240, 256>>>(cosb, sinb, qw, kw);
    vtrans<<<dim3(64, 4, 8), dim3(32, 8)>>>();

    flash_attn_tc<<<dim3(16, 32), 256, FLASH_SMEM_TC>>>();

    hgemm_o<<<dim3(32, 16), 256, HGEMM_SMEM>>>(out);
}